// round 1
// baseline (speedup 1.0000x reference)
#include <cuda_runtime.h>
#include <math.h>

#define H 512
#define F 1024
#define E 16
#define MAX_T 8192
#define EPS 1e-5f

#define TM 64           // tokens per CTA tile
#define FC 64           // F chunk
#define XS (TM + 4)     // padded smem row stride (68 floats, 16B-aligned stride)

// Scratch for normalized tokens (no allocation allowed -> device global).
__device__ float g_xhat[(size_t)MAX_T * H];

// ---------------------------------------------------------------------------
// LayerNorm: one CTA (256 threads) per token row, two-pass (matches reference)
// ---------------------------------------------------------------------------
__device__ __forceinline__ float block_sum256(float v) {
    __shared__ float red[8];
    #pragma unroll
    for (int o = 16; o > 0; o >>= 1) v += __shfl_xor_sync(0xffffffffu, v, o);
    int wid = threadIdx.x >> 5, lane = threadIdx.x & 31;
    if (lane == 0) red[wid] = v;
    __syncthreads();
    if (threadIdx.x < 32) {
        float r = (threadIdx.x < 8) ? red[threadIdx.x] : 0.0f;
        #pragma unroll
        for (int o = 4; o > 0; o >>= 1) r += __shfl_xor_sync(0xffffffffu, r, o);
        if (threadIdx.x == 0) red[0] = r;
    }
    __syncthreads();
    float out = red[0];
    __syncthreads();   // allow smem reuse on next call
    return out;
}

__global__ void ln_kernel(const float* __restrict__ tokens, int nrows) {
    int row = blockIdx.x;
    const float* x = tokens + (size_t)row * H;
    int tid = threadIdx.x;
    float v0 = x[tid];
    float v1 = x[tid + 256];
    float s = block_sum256(v0 + v1);
    float mu = s * (1.0f / H);
    float d0 = v0 - mu, d1 = v1 - mu;
    float q = block_sum256(d0 * d0 + d1 * d1);
    float rs = rsqrtf(q * (1.0f / H) + EPS);
    g_xhat[(size_t)row * H + tid]       = d0 * rs;
    g_xhat[(size_t)row * H + tid + 256] = d1 * rs;
}

// ---------------------------------------------------------------------------
// Fused per-expert FFN: CTA = (token tile of 64, expert).
//   xsT  [H][XS]  : affine-applied x_hat, transposed (k-major) in SMEM
//   htT  [FC][XS] : GELU(h) chunk, transposed, in SMEM
//   acc  [8][16]  : per-thread fp32 output accumulators (64x512 per CTA)
// ---------------------------------------------------------------------------
__device__ __forceinline__ float gelu_erf(float x) {
    return 0.5f * x * (1.0f + erff(x * 0.70710678118654752f));
}

__global__ void __launch_bounds__(256, 1) ffn_kernel(
    const float* __restrict__ ln_g, const float* __restrict__ ln_b,
    const float* __restrict__ W1,   const float* __restrict__ b1,
    const float* __restrict__ W2,   const float* __restrict__ b2,
    float* __restrict__ out)
{
    extern __shared__ float sm[];
    float* xsT = sm;                 // H * XS floats
    float* htT = sm + H * XS;        // FC * XS floats

    const int e    = blockIdx.y;
    const int tok0 = blockIdx.x * TM;
    const int tid  = threadIdx.x;

    // ---- Load x_hat tile, apply per-expert affine, store transposed ----
    {
        const float* gv = ln_g + e * H;
        const float* bv = ln_b + e * H;
        for (int idx = tid; idx < TM * H; idx += 256) {
            int tok = idx >> 9;          // /H
            int k   = idx & (H - 1);
            float xv = g_xhat[(size_t)(tok0 + tok) * H + k];
            xsT[k * XS + tok] = fmaf(xv, gv[k], bv[k]);
        }
    }
    __syncthreads();

    const int fp   = tid & 31;       // f-pair index within chunk (2 f per thread)
    const int tg   = tid >> 5;       // token group (8 tokens each)
    const int trow = tg * 8;
    const int hb   = (tid & 31) * 16;

    // ---- Output accumulators, initialized with b2 ----
    float acc[8][16];
    {
        const float* b2p = b2 + e * H + hb;
        float bb[16];
        #pragma unroll
        for (int j = 0; j < 16; j++) bb[j] = b2p[j];
        #pragma unroll
        for (int i = 0; i < 8; i++)
            #pragma unroll
            for (int j = 0; j < 16; j++) acc[i][j] = bb[j];
    }

    for (int fc = 0; fc < F; fc += FC) {
        // ================= GEMM1: ht[64][64] = xsT^T @ W1 chunk ============
        float c1[2][8];
        #pragma unroll
        for (int fi = 0; fi < 2; fi++)
            #pragma unroll
            for (int j = 0; j < 8; j++) c1[fi][j] = 0.0f;

        const float* w1p = W1 + ((size_t)e * H) * F + fc + 2 * fp;
        #pragma unroll 4
        for (int k = 0; k < H; k++) {
            float2 w = *reinterpret_cast<const float2*>(w1p);
            w1p += F;
            const float4 a0 = *reinterpret_cast<const float4*>(xsT + k * XS + trow);
            const float4 a1 = *reinterpret_cast<const float4*>(xsT + k * XS + trow + 4);
            c1[0][0] = fmaf(w.x, a0.x, c1[0][0]);
            c1[0][1] = fmaf(w.x, a0.y, c1[0][1]);
            c1[0][2] = fmaf(w.x, a0.z, c1[0][2]);
            c1[0][3] = fmaf(w.x, a0.w, c1[0][3]);
            c1[0][4] = fmaf(w.x, a1.x, c1[0][4]);
            c1[0][5] = fmaf(w.x, a1.y, c1[0][5]);
            c1[0][6] = fmaf(w.x, a1.z, c1[0][6]);
            c1[0][7] = fmaf(w.x, a1.w, c1[0][7]);
            c1[1][0] = fmaf(w.y, a0.x, c1[1][0]);
            c1[1][1] = fmaf(w.y, a0.y, c1[1][1]);
            c1[1][2] = fmaf(w.y, a0.z, c1[1][2]);
            c1[1][3] = fmaf(w.y, a0.w, c1[1][3]);
            c1[1][4] = fmaf(w.y, a1.x, c1[1][4]);
            c1[1][5] = fmaf(w.y, a1.y, c1[1][5]);
            c1[1][6] = fmaf(w.y, a1.z, c1[1][6]);
            c1[1][7] = fmaf(w.y, a1.w, c1[1][7]);
        }

        // bias + erf-GELU, store transposed chunk
        {
            float bb0 = b1[e * F + fc + 2 * fp];
            float bb1 = b1[e * F + fc + 2 * fp + 1];
            #pragma unroll
            for (int j = 0; j < 8; j++) {
                htT[(2 * fp)     * XS + trow + j] = gelu_erf(c1[0][j] + bb0);
                htT[(2 * fp + 1) * XS + trow + j] = gelu_erf(c1[1][j] + bb1);
            }
        }
        __syncthreads();

        // ================= GEMM2: acc += ht @ W2 chunk =====================
        {
            const float* w2p = W2 + ((size_t)e * F + fc) * H + hb;
            // prefetch kk = 0
            float4 nb0 = *reinterpret_cast<const float4*>(w2p + 0);
            float4 nb1 = *reinterpret_cast<const float4*>(w2p + 4);
            float4 nb2 = *reinterpret_cast<const float4*>(w2p + 8);
            float4 nb3 = *reinterpret_cast<const float4*>(w2p + 12);
            float4 na0 = *reinterpret_cast<const float4*>(htT + 0 * XS + trow);
            float4 na1 = *reinterpret_cast<const float4*>(htT + 0 * XS + trow + 4);

            #pragma unroll 2
            for (int kk = 0; kk < FC; kk++) {
                float4 cb0 = nb0, cb1 = nb1, cb2 = nb2, cb3 = nb3;
                float4 ca0 = na0, ca1 = na1;
                if (kk + 1 < FC) {
                    const float* p = w2p + (size_t)(kk + 1) * H;
                    nb0 = *reinterpret_cast<const float4*>(p + 0);
                    nb1 = *reinterpret_cast<const float4*>(p + 4);
                    nb2 = *reinterpret_cast<const float4*>(p + 8);
                    nb3 = *reinterpret_cast<const float4*>(p + 12);
                    na0 = *reinterpret_cast<const float4*>(htT + (kk + 1) * XS + trow);
                    na1 = *reinterpret_cast<const float4*>(htT + (kk + 1) * XS + trow + 4);
                }
                float av[8] = {ca0.x, ca0.y, ca0.z, ca0.w, ca1.x, ca1.y, ca1.z, ca1.w};
                float bv[16] = {cb0.x, cb0.y, cb0.z, cb0.w,
                                cb1.x, cb1.y, cb1.z, cb1.w,
                                cb2.x, cb2.y, cb2.z, cb2.w,
                                cb3.x, cb3.y, cb3.z, cb3.w};
                #pragma unroll
                for (int i = 0; i < 8; i++)
                    #pragma unroll
                    for (int j = 0; j < 16; j++)
                        acc[i][j] = fmaf(av[i], bv[j], acc[i][j]);
            }
        }
        __syncthreads();   // htT reused by next chunk's GEMM1 stores
    }

    // ---- Writeback: out[t][e][h] ----
    #pragma unroll
    for (int i = 0; i < 8; i++) {
        float* op = out + (((size_t)(tok0 + trow + i)) * E + e) * H + hb;
        #pragma unroll
        for (int j = 0; j < 16; j += 4) {
            float4 v = make_float4(acc[i][j], acc[i][j + 1], acc[i][j + 2], acc[i][j + 3]);
            *reinterpret_cast<float4*>(op + j) = v;
        }
    }
}

// ---------------------------------------------------------------------------
extern "C" void kernel_launch(void* const* d_in, const int* in_sizes, int n_in,
                              void* d_out, int out_size)
{
    const float* tokens = (const float*)d_in[0];
    const float* ln_g   = (const float*)d_in[1];
    const float* ln_b   = (const float*)d_in[2];
    const float* W1     = (const float*)d_in[3];
    const float* b1     = (const float*)d_in[4];
    const float* W2     = (const float*)d_in[5];
    const float* b2     = (const float*)d_in[6];
    float* out = (float*)d_out;

    int T = in_sizes[0] / H;   // 8192

    const int smem_bytes = (H * XS + FC * XS) * (int)sizeof(float);  // ~157 KB
    cudaFuncSetAttribute(ffn_kernel, cudaFuncAttributeMaxDynamicSharedMemorySize, smem_bytes);

    ln_kernel<<<T, 256>>>(tokens, T);

    dim3 grid(T / TM, E);
    ffn_kernel<<<grid, 256, smem_bytes>>>(ln_g, ln_b, W1, b1, W2, b2, out);
}

// round 3
// speedup vs baseline: 10.9490x; 10.9490x over previous
#include <cuda_runtime.h>
#include <cuda_bf16.h>
#include <math.h>
#include <stdint.h>

#define H 512
#define F 1024
#define E 16
#define MAX_T 8192
#define EPS 1e-5f

// Per-compile-pass feature detection: tcgen05 only legal on sm_103a-style targets.
#if defined(__CUDA_ARCH__) && (defined(__CUDA_ARCH_FEAT_SM103_ALL) || \
    defined(__CUDA_ARCH_FEAT_SM100_ALL) || defined(__CUDA_ARCH_SPECIFIC__) || \
    defined(__CUDA_ARCH_FAMILY_SPECIFIC__))
#define USE_TC 1
#else
#define USE_TC 0
#endif

// ---------------------------------------------------------------------------
// Scratch (no allocation allowed -> device globals)
// ---------------------------------------------------------------------------
__device__ __align__(128) __nv_bfloat16 g_xhi[(size_t)MAX_T * H];
__device__ __align__(128) __nv_bfloat16 g_xlo[(size_t)MAX_T * H];
__device__ __align__(128) __nv_bfloat16 g_w1thi[(size_t)E * F * H];   // [e][f][h]
__device__ __align__(128) __nv_bfloat16 g_w1tlo[(size_t)E * F * H];
__device__ __align__(128) __nv_bfloat16 g_w2thi[(size_t)E * H * F];   // [e][h][f]
__device__ __align__(128) __nv_bfloat16 g_w2tlo[(size_t)E * H * F];
__device__ float g_b1p[E * F];
__device__ __align__(128) __nv_bfloat16 g_hhi[(size_t)E * MAX_T * F]; // [e][t][f]
__device__ __align__(128) __nv_bfloat16 g_hlo[(size_t)E * MAX_T * F];

// ---------------------------------------------------------------------------
// Common helpers
// ---------------------------------------------------------------------------
__device__ __forceinline__ uint32_t smem_to_u32(const void* p) {
    uint32_t a;
    asm("{ .reg .u64 t; cvta.to.shared.u64 t, %1; cvt.u32.u64 %0, t; }" : "=r"(a) : "l"(p));
    return a;
}
#define SMEM_SWIZZLE_128B(o) ((o) ^ (((o) >> 3) & 0x70))

__device__ __forceinline__ void cpa16(uint32_t dst, const void* src) {
    asm volatile("cp.async.cg.shared.global [%0], [%1], 16;" :: "r"(dst), "l"(src));
}
#define CP_COMMIT() asm volatile("cp.async.commit_group;" ::: "memory")
__device__ __forceinline__ void cp_wait1() { asm volatile("cp.async.wait_group 1;" ::: "memory"); }
__device__ __forceinline__ void cp_wait0() { asm volatile("cp.async.wait_group 0;" ::: "memory"); }

__device__ __forceinline__ float gelu_erf(float x) {
    return 0.5f * x * (1.0f + erff(x * 0.70710678118654752f));
}

// SMEM layout: 2 stages x 64KB; each stage: A_HI(16K) A_LO(16K) B_HI(16K) B_LO(16K)
#define STAGE_BYTES 65536
#define OFF_ALO 16384
#define OFF_BHI 32768
#define OFF_BLO 49152
#define S_CTRL 131072
#define S_MBAR 131088
#define SMEM_BYTES 131104

// Load one 128x64(bf16) tile quartet into a stage with SW128 swizzle via cp.async.
__device__ __forceinline__ void stage_load_async(uint32_t sbase,
    const __nv_bfloat16* __restrict__ Ah, const __nv_bfloat16* __restrict__ Al, size_t as,
    const __nv_bfloat16* __restrict__ Bh, const __nv_bfloat16* __restrict__ Bl, size_t bs,
    int k0, int tid)
{
    #pragma unroll
    for (int it = 0; it < 4; it++) {
        int v = tid + it * 256;
        int r = v >> 3, c = v & 7;                       // row, 16B chunk
        uint32_t off = SMEM_SWIZZLE_128B((uint32_t)(r * 128 + c * 16));
        size_t ga = (size_t)r * as + k0 + c * 8;
        size_t gb = (size_t)r * bs + k0 + c * 8;
        cpa16(sbase + off,           Ah + ga);
        cpa16(sbase + OFF_ALO + off, Al + ga);
        cpa16(sbase + OFF_BHI + off, Bh + gb);
        cpa16(sbase + OFF_BLO + off, Bl + gb);
    }
}

// ===========================================================================
#if USE_TC
// tcgen05 path
// ===========================================================================
__device__ __forceinline__ uint32_t elect_one_pred() {
    uint32_t pred;
    asm volatile("{\n\t.reg .pred p;\n\telect.sync _|p, 0xFFFFFFFF;\n\t"
                 "selp.b32 %0, 1, 0, p;\n\t}" : "=r"(pred));
    return pred;
}
static constexpr uint64_t SMEM_DESC_BASE_SW128 =
    (uint64_t(2) << 61) | (uint64_t(1) << 46) | (uint64_t(64) << 32) | (uint64_t(1) << 16);
#define MAKE_SMEM_DESC(a) (SMEM_DESC_BASE_SW128 | ((uint64_t)((a) >> 4) & 0x3FFF))

#define TCGEN05_ALLOC(sr, n) \
    asm volatile("tcgen05.alloc.cta_group::1.sync.aligned.shared::cta.b32 [%0], %1;" \
                 :: "r"((uint32_t)(sr)), "r"((uint32_t)(n)) : "memory")
#define TCGEN05_DEALLOC(t, n) \
    asm volatile("tcgen05.dealloc.cta_group::1.sync.aligned.b32 %0, %1;" :: "r"(t), "r"(n))
#define TCGEN05_RELINQUISH() \
    asm volatile("tcgen05.relinquish_alloc_permit.cta_group::1.sync.aligned;")
#define TCGEN05_COMMIT(m) \
    asm volatile("tcgen05.commit.cta_group::1.mbarrier::arrive::one.shared::cluster.b64 [%0];" \
                 :: "r"((uint32_t)(m)) : "memory")
#define TCGEN05_FENCE_AFTER() asm volatile("tcgen05.fence::after_thread_sync;" ::: "memory")
#define TCGEN05_WAIT_LD() asm volatile("tcgen05.wait::ld.sync.aligned;" ::: "memory")
#define MBARRIER_INIT(m, c) \
    asm volatile("mbarrier.init.shared.b64 [%0], %1;" :: "r"((uint32_t)(m)), "r"((uint32_t)(c)) : "memory")
#define MBARRIER_INVAL(m) \
    asm volatile("mbarrier.inval.shared.b64 [%0];" :: "r"((uint32_t)(m)) : "memory")

#define MBARRIER_WAIT_PARITY(mb, ph) do {                                         \
    uint32_t _m = (uint32_t)(mb), _p = (uint32_t)(ph), _d;                         \
    asm volatile("{\n\t.reg .pred p;\n\t"                                          \
        "mbarrier.try_wait.parity.acquire.cta.shared::cta.b64 p, [%1], %2;\n\t"    \
        "selp.b32 %0, 1, 0, p;\n\t}" : "=r"(_d) : "r"(_m), "r"(_p) : "memory");    \
    if (!_d) {                                                                     \
        asm volatile("{\n\t.reg .pred P1;\n\t"                                     \
            "WL_%=:\n\t"                                                           \
            "mbarrier.try_wait.parity.acquire.cta.shared::cta.b64 P1, [%0], %1, 0x989680;\n\t" \
            "@P1 bra.uni WD_%=;\n\t"                                               \
            "bra.uni WL_%=;\n\t"                                                   \
            "WD_%=:\n\t}" :: "r"(_m), "r"(_p) : "memory");                         \
    }                                                                              \
} while (0)

#define TCGEN05_LD_X32(r, a)                                                       \
    asm volatile("tcgen05.ld.sync.aligned.32x32b.x32.b32 "                         \
        "{%0, %1, %2, %3, %4, %5, %6, %7, %8, %9, %10, %11, %12, %13, %14, %15, "  \
        " %16, %17, %18, %19, %20, %21, %22, %23, %24, %25, %26, %27, %28, %29, %30, %31}, [%32];" \
        : "=r"((r)[0]), "=r"((r)[1]), "=r"((r)[2]), "=r"((r)[3]),                  \
          "=r"((r)[4]), "=r"((r)[5]), "=r"((r)[6]), "=r"((r)[7]),                  \
          "=r"((r)[8]), "=r"((r)[9]), "=r"((r)[10]), "=r"((r)[11]),                \
          "=r"((r)[12]), "=r"((r)[13]), "=r"((r)[14]), "=r"((r)[15]),              \
          "=r"((r)[16]), "=r"((r)[17]), "=r"((r)[18]), "=r"((r)[19]),              \
          "=r"((r)[20]), "=r"((r)[21]), "=r"((r)[22]), "=r"((r)[23]),              \
          "=r"((r)[24]), "=r"((r)[25]), "=r"((r)[26]), "=r"((r)[27]),              \
          "=r"((r)[28]), "=r"((r)[29]), "=r"((r)[30]), "=r"((r)[31])               \
        : "r"(a))

__device__ __forceinline__ void mma_bf16_ss(uint32_t d_tmem, uint64_t a_desc,
                                            uint64_t b_desc, uint32_t idesc, bool acc) {
    uint32_t en = acc ? 1u : 0u;
    asm volatile("{\n\t.reg .pred p;\n\tsetp.ne.u32 p, %4, 0;\n\t"
                 "tcgen05.mma.cta_group::1.kind::f16 [%0], %1, %2, %3, p;\n\t}"
                 :: "r"(d_tmem), "l"(a_desc), "l"(b_desc), "r"(idesc), "r"(en)
                 : "memory");
}
// dtype=F32, atype=btype=BF16, N=128, M=128, K-major
#define MMA_IDESC ((1u << 4) | (1u << 7) | (1u << 10) | ((128u / 8u) << 17) | ((128u / 16u) << 24))

__device__ __forceinline__ uint32_t tc_prologue(uint32_t su, int tid, int wid) {
    if (wid == 0) TCGEN05_ALLOC(su + S_CTRL, 128);
    if (tid == 128) MBARRIER_INIT(su + S_MBAR, 1);
    __syncthreads();
    uint32_t tmem;
    asm volatile("ld.shared.b32 %0, [%1];" : "=r"(tmem) : "r"(su + S_CTRL));
    if (wid == 0) TCGEN05_RELINQUISH();
    __syncthreads();
    return tmem;
}

__device__ __forceinline__ void tc_mainloop(uint32_t su, uint32_t tmem,
    const __nv_bfloat16* __restrict__ Ah, const __nv_bfloat16* __restrict__ Al, size_t as,
    const __nv_bfloat16* __restrict__ Bh, const __nv_bfloat16* __restrict__ Bl, size_t bs,
    int K, int tid, int wid)
{
    const int nk = K / 64;
    stage_load_async(su, Ah, Al, as, Bh, Bl, bs, 0, tid);
    CP_COMMIT();
    for (int ks = 0; ks < nk; ks++) {
        if (ks > 0) MBARRIER_WAIT_PARITY(su + S_MBAR, (ks - 1) & 1);
        if (ks + 1 < nk) {
            stage_load_async(su + ((ks + 1) & 1) * STAGE_BYTES,
                             Ah, Al, as, Bh, Bl, bs, (ks + 1) * 64, tid);
            CP_COMMIT();
            cp_wait1();
        } else {
            cp_wait0();
        }
        __syncthreads();
        if (wid == 0 && elect_one_pred()) {
            asm volatile("fence.proxy.async.shared::cta;" ::: "memory");
            uint32_t sb = su + (ks & 1) * STAGE_BYTES;
            uint64_t dAh = MAKE_SMEM_DESC(sb);
            uint64_t dAl = MAKE_SMEM_DESC(sb + OFF_ALO);
            uint64_t dBh = MAKE_SMEM_DESC(sb + OFF_BHI);
            uint64_t dBl = MAKE_SMEM_DESC(sb + OFF_BLO);
            #pragma unroll
            for (int kk = 0; kk < 4; kk++) {
                bool acc0 = (ks > 0) || (kk > 0);
                mma_bf16_ss(tmem, dAh + kk * 2, dBh + kk * 2, MMA_IDESC, acc0);
                mma_bf16_ss(tmem, dAh + kk * 2, dBl + kk * 2, MMA_IDESC, true);
                mma_bf16_ss(tmem, dAl + kk * 2, dBh + kk * 2, MMA_IDESC, true);
            }
            TCGEN05_COMMIT(su + S_MBAR);
        }
        __syncthreads();
    }
    MBARRIER_WAIT_PARITY(su + S_MBAR, (nk - 1) & 1);
    TCGEN05_FENCE_AFTER();
}

__device__ __forceinline__ void tc_release(uint32_t su, uint32_t tmem, int tid, int wid) {
    __syncthreads();
    if (tid == 128) MBARRIER_INVAL(su + S_MBAR);
    __syncthreads();
    if (wid == 0) TCGEN05_DEALLOC(tmem, 128);
}
#endif  // USE_TC

// ===========================================================================
#if !USE_TC
// mma.sync fallback path (legal on plain compute_103)
// ===========================================================================
__device__ __forceinline__ void ldsm_x4(uint32_t* r, uint32_t a) {
    asm volatile("ldmatrix.sync.aligned.m8n8.x4.shared.b16 {%0,%1,%2,%3}, [%4];"
                 : "=r"(r[0]), "=r"(r[1]), "=r"(r[2]), "=r"(r[3]) : "r"(a));
}
__device__ __forceinline__ void mma16816(float* d, const uint32_t* a, const uint32_t* b) {
    asm volatile("mma.sync.aligned.m16n8k16.row.col.f32.bf16.bf16.f32 "
                 "{%0,%1,%2,%3}, {%4,%5,%6,%7}, {%8,%9}, {%0,%1,%2,%3};"
                 : "+f"(d[0]), "+f"(d[1]), "+f"(d[2]), "+f"(d[3])
                 : "r"(a[0]), "r"(a[1]), "r"(a[2]), "r"(a[3]), "r"(b[0]), "r"(b[1]));
}

// acc[mtile][ntile][4]; warp tile 32x64 inside CTA tile 128x128
__device__ __forceinline__ void mmasync_mainloop(uint32_t su,
    const __nv_bfloat16* __restrict__ Ah, const __nv_bfloat16* __restrict__ Al, size_t as,
    const __nv_bfloat16* __restrict__ Bh, const __nv_bfloat16* __restrict__ Bl, size_t bs,
    int K, int tid, float acc[2][8][4])
{
    const int nk = K / 64;
    const int wid = tid >> 5, lane = tid & 31;
    const int wm = wid >> 1, wn = wid & 1;

    stage_load_async(su, Ah, Al, as, Bh, Bl, bs, 0, tid);
    CP_COMMIT();

    for (int ks = 0; ks < nk; ks++) {
        if (ks + 1 < nk) {
            stage_load_async(su + ((ks + 1) & 1) * STAGE_BYTES,
                             Ah, Al, as, Bh, Bl, bs, (ks + 1) * 64, tid);
            CP_COMMIT();
            cp_wait1();
        } else {
            cp_wait0();
        }
        __syncthreads();

        uint32_t sA = su + (ks & 1) * STAGE_BYTES;
        uint32_t sB = sA + OFF_BHI;

        #pragma unroll
        for (int k16 = 0; k16 < 64; k16 += 16) {
            uint32_t ah[2][4], al[2][4];
            #pragma unroll
            for (int i = 0; i < 2; i++) {
                int m = wm * 32 + i * 16 + (lane & 15);
                int k = k16 + (lane >> 4) * 8;
                uint32_t addr = sA + SMEM_SWIZZLE_128B((uint32_t)(m * 128 + k * 2));
                ldsm_x4(ah[i], addr);
                ldsm_x4(al[i], addr + OFF_ALO);
            }
            uint32_t bh[8][2], bl[8][2];
            #pragma unroll
            for (int jj = 0; jj < 4; jj++) {
                int n = wn * 64 + jj * 16 + (lane & 7) + ((lane >> 3) & 1) * 8;
                int k = k16 + (lane >> 4) * 8;
                uint32_t addr = sB + SMEM_SWIZZLE_128B((uint32_t)(n * 128 + k * 2));
                uint32_t t[4];
                ldsm_x4(t, addr);
                bh[2 * jj][0] = t[0]; bh[2 * jj + 1][0] = t[1];
                bh[2 * jj][1] = t[2]; bh[2 * jj + 1][1] = t[3];
                ldsm_x4(t, addr + 16384);   // B_LO - B_HI = 16384
                bl[2 * jj][0] = t[0]; bl[2 * jj + 1][0] = t[1];
                bl[2 * jj][1] = t[2]; bl[2 * jj + 1][1] = t[3];
            }
            #pragma unroll
            for (int i = 0; i < 2; i++)
                #pragma unroll
                for (int j = 0; j < 8; j++) {
                    mma16816(acc[i][j], ah[i], bh[j]);
                    mma16816(acc[i][j], ah[i], bl[j]);
                    mma16816(acc[i][j], al[i], bh[j]);
                }
        }
        __syncthreads();
    }
}
#endif  // !USE_TC

// ---------------------------------------------------------------------------
// Prep kernels
// ---------------------------------------------------------------------------
__device__ __forceinline__ float blk_sum256(float v) {
    __shared__ float red[8];
    #pragma unroll
    for (int o = 16; o > 0; o >>= 1) v += __shfl_xor_sync(0xffffffffu, v, o);
    int w = threadIdx.x >> 5, l = threadIdx.x & 31;
    if (l == 0) red[w] = v;
    __syncthreads();
    if (threadIdx.x < 32) {
        float r = (threadIdx.x < 8) ? red[threadIdx.x] : 0.0f;
        #pragma unroll
        for (int o = 4; o > 0; o >>= 1) r += __shfl_xor_sync(0xffffffffu, r, o);
        if (threadIdx.x == 0) red[0] = r;
    }
    __syncthreads();
    float out = red[0];
    __syncthreads();
    return out;
}

__global__ void ln_split_kernel(const float* __restrict__ tokens) {
    int row = blockIdx.x, tid = threadIdx.x;
    const float* x = tokens + (size_t)row * H;
    float v0 = x[tid], v1 = x[tid + 256];
    float mu = blk_sum256(v0 + v1) * (1.0f / H);
    float d0 = v0 - mu, d1 = v1 - mu;
    float rs = rsqrtf(blk_sum256(d0 * d0 + d1 * d1) * (1.0f / H) + EPS);
    float a0 = d0 * rs, a1 = d1 * rs;
    size_t base = (size_t)row * H;
    __nv_bfloat16 h0 = __float2bfloat16(a0);
    __nv_bfloat16 h1 = __float2bfloat16(a1);
    g_xhi[base + tid] = h0;
    g_xhi[base + tid + 256] = h1;
    g_xlo[base + tid] = __float2bfloat16(a0 - __bfloat162float(h0));
    g_xlo[base + tid + 256] = __float2bfloat16(a1 - __bfloat162float(h1));
}

__global__ void w1t_kernel(const float* __restrict__ W1, const float* __restrict__ ln_g) {
    __shared__ float ts[64][65];
    int e = blockIdx.z, f0 = blockIdx.x * 64, h0 = blockIdx.y * 64, tid = threadIdx.x;
    #pragma unroll
    for (int i = 0; i < 16; i++) {
        int idx = tid + i * 256, r = idx >> 6, c = idx & 63;
        ts[r][c] = W1[((size_t)e * H + h0 + r) * F + f0 + c];
    }
    __syncthreads();
    #pragma unroll
    for (int i = 0; i < 16; i++) {
        int idx = tid + i * 256, r = idx >> 6, c = idx & 63;
        float w = ts[c][r] * ln_g[e * H + h0 + c];
        __nv_bfloat16 hi = __float2bfloat16(w);
        size_t o = ((size_t)e * F + f0 + r) * H + h0 + c;
        g_w1thi[o] = hi;
        g_w1tlo[o] = __float2bfloat16(w - __bfloat162float(hi));
    }
}

__global__ void w2t_kernel(const float* __restrict__ W2) {
    __shared__ float ts[64][65];
    int e = blockIdx.z, h0 = blockIdx.x * 64, f0 = blockIdx.y * 64, tid = threadIdx.x;
    #pragma unroll
    for (int i = 0; i < 16; i++) {
        int idx = tid + i * 256, r = idx >> 6, c = idx & 63;
        ts[r][c] = W2[((size_t)e * F + f0 + r) * H + h0 + c];
    }
    __syncthreads();
    #pragma unroll
    for (int i = 0; i < 16; i++) {
        int idx = tid + i * 256, r = idx >> 6, c = idx & 63;
        float w = ts[c][r];
        __nv_bfloat16 hi = __float2bfloat16(w);
        size_t o = ((size_t)e * H + h0 + r) * F + f0 + c;
        g_w2thi[o] = hi;
        g_w2tlo[o] = __float2bfloat16(w - __bfloat162float(hi));
    }
}

__global__ void b1p_kernel(const float* __restrict__ W1, const float* __restrict__ ln_b,
                           const float* __restrict__ b1) {
    int e = blockIdx.y;
    int f = blockIdx.x * 256 + threadIdx.x;
    float acc = b1[e * F + f];
    const float* w = W1 + (size_t)e * H * F + f;
    const float* b = ln_b + e * H;
    #pragma unroll 4
    for (int h = 0; h < H; h++) acc += b[h] * w[(size_t)h * F];
    g_b1p[e * F + f] = acc;
}

// ---------------------------------------------------------------------------
// GEMM1: h = gelu(xhat @ (g*W1) + b1')    grid: (T/128, E, F/128)
// ---------------------------------------------------------------------------
__global__ void __launch_bounds__(256) gemm1_kernel() {
    extern __shared__ char smem[];
    uint32_t su = smem_to_u32(smem);
    const int tid = threadIdx.x, wid = tid >> 5, lane = tid & 31;
    const int e = blockIdx.y;
    const int tok0 = blockIdx.x * 128;
    const int fc = blockIdx.z * 128;

    const __nv_bfloat16* Ah = g_xhi + (size_t)tok0 * H;
    const __nv_bfloat16* Al = g_xlo + (size_t)tok0 * H;
    const __nv_bfloat16* Bh = g_w1thi + ((size_t)e * F + fc) * H;
    const __nv_bfloat16* Bl = g_w1tlo + ((size_t)e * F + fc) * H;

#if USE_TC
    uint32_t tmem = tc_prologue(su, tid, wid);
    tc_mainloop(su, tmem, Ah, Al, H, Bh, Bl, H, H, tid, wid);

    const int row = (wid & 3) * 32 + lane;
    const int ch = (wid >> 2) * 64;
    const size_t hrow = ((size_t)e * MAX_T + tok0 + row) * F;
    for (int cb = 0; cb < 64; cb += 32) {
        uint32_t r[32];
        TCGEN05_LD_X32(r, tmem + ch + cb);
        TCGEN05_WAIT_LD();
        int fglob = fc + ch + cb;
        __nv_bfloat16 hi8[8], lo8[8];
        #pragma unroll
        for (int j = 0; j < 32; j++) {
            float v = __uint_as_float(r[j]) + g_b1p[e * F + fglob + j];
            float gl = gelu_erf(v);
            __nv_bfloat16 hb = __float2bfloat16(gl);
            hi8[j & 7] = hb;
            lo8[j & 7] = __float2bfloat16(gl - __bfloat162float(hb));
            if ((j & 7) == 7) {
                size_t o = hrow + fglob + (j & ~7);
                *reinterpret_cast<uint4*>(&g_hhi[o]) = *reinterpret_cast<uint4*>(hi8);
                *reinterpret_cast<uint4*>(&g_hlo[o]) = *reinterpret_cast<uint4*>(lo8);
            }
        }
    }
    tc_release(su, tmem, tid, wid);
#else
    float acc[2][8][4];
    #pragma unroll
    for (int i = 0; i < 2; i++)
        #pragma unroll
        for (int j = 0; j < 8; j++)
            #pragma unroll
            for (int q = 0; q < 4; q++) acc[i][j][q] = 0.0f;

    mmasync_mainloop(su, Ah, Al, H, Bh, Bl, H, H, tid, acc);

    const int wm = wid >> 1, wn = wid & 1;
    const float* b1pp = g_b1p + e * F;
    #pragma unroll
    for (int i = 0; i < 2; i++) {
        #pragma unroll
        for (int j = 0; j < 8; j++) {
            int fj = fc + wn * 64 + j * 8 + (lane & 3) * 2;
            int r0 = tok0 + wm * 32 + i * 16 + (lane >> 2);
            #pragma unroll
            for (int half = 0; half < 2; half++) {
                int rr = r0 + half * 8;
                float v0 = acc[i][j][2 * half + 0] + b1pp[fj];
                float v1 = acc[i][j][2 * half + 1] + b1pp[fj + 1];
                float g0 = gelu_erf(v0), g1 = gelu_erf(v1);
                __nv_bfloat16 h0 = __float2bfloat16(g0);
                __nv_bfloat16 h1 = __float2bfloat16(g1);
                __nv_bfloat16 l0 = __float2bfloat16(g0 - __bfloat162float(h0));
                __nv_bfloat16 l1 = __float2bfloat16(g1 - __bfloat162float(h1));
                uint32_t ph = ((uint32_t)__bfloat16_as_ushort(h1) << 16) | __bfloat16_as_ushort(h0);
                uint32_t pl = ((uint32_t)__bfloat16_as_ushort(l1) << 16) | __bfloat16_as_ushort(l0);
                size_t o = ((size_t)e * MAX_T + rr) * F + fj;
                *reinterpret_cast<uint32_t*>(&g_hhi[o]) = ph;
                *reinterpret_cast<uint32_t*>(&g_hlo[o]) = pl;
            }
        }
    }
#endif
}

// ---------------------------------------------------------------------------
// GEMM2: out = h @ W2 + b2     grid: (T/128, E, H/128)
// ---------------------------------------------------------------------------
__global__ void __launch_bounds__(256) gemm2_kernel(const float* __restrict__ b2,
                                                    float* __restrict__ out) {
    extern __shared__ char smem[];
    uint32_t su = smem_to_u32(smem);
    const int tid = threadIdx.x, wid = tid >> 5, lane = tid & 31;
    const int e = blockIdx.y;
    const int tok0 = blockIdx.x * 128;
    const int hh0 = blockIdx.z * 128;

    const size_t hbase = ((size_t)e * MAX_T + tok0) * F;
    const __nv_bfloat16* Ah = g_hhi + hbase;
    const __nv_bfloat16* Al = g_hlo + hbase;
    const __nv_bfloat16* Bh = g_w2thi + ((size_t)e * H + hh0) * F;
    const __nv_bfloat16* Bl = g_w2tlo + ((size_t)e * H + hh0) * F;

#if USE_TC
    uint32_t tmem = tc_prologue(su, tid, wid);
    tc_mainloop(su, tmem, Ah, Al, F, Bh, Bl, F, F, tid, wid);

    const int row = (wid & 3) * 32 + lane;
    const int ch = (wid >> 2) * 64;
    float* orow = out + (((size_t)(tok0 + row)) * E + e) * H;
    for (int cb = 0; cb < 64; cb += 32) {
        uint32_t r[32];
        TCGEN05_LD_X32(r, tmem + ch + cb);
        TCGEN05_WAIT_LD();
        int hglob = hh0 + ch + cb;
        float v4[4];
        #pragma unroll
        for (int j = 0; j < 32; j++) {
            v4[j & 3] = __uint_as_float(r[j]) + b2[e * H + hglob + j];
            if ((j & 3) == 3)
                *reinterpret_cast<uint4*>(orow + hglob + (j & ~3)) =
                    *reinterpret_cast<uint4*>(v4);
        }
    }
    tc_release(su, tmem, tid, wid);
#else
    float acc[2][8][4];
    #pragma unroll
    for (int i = 0; i < 2; i++)
        #pragma unroll
        for (int j = 0; j < 8; j++)
            #pragma unroll
            for (int q = 0; q < 4; q++) acc[i][j][q] = 0.0f;

    mmasync_mainloop(su, Ah, Al, F, Bh, Bl, F, F, tid, acc);

    const int wm = wid >> 1, wn = wid & 1;
    const float* b2p = b2 + e * H;
    #pragma unroll
    for (int i = 0; i < 2; i++) {
        #pragma unroll
        for (int j = 0; j < 8; j++) {
            int hj = hh0 + wn * 64 + j * 8 + (lane & 3) * 2;
            int r0 = tok0 + wm * 32 + i * 16 + (lane >> 2);
            float bb0 = b2p[hj], bb1 = b2p[hj + 1];
            #pragma unroll
            for (int half = 0; half < 2; half++) {
                int rr = r0 + half * 8;
                float2 v = make_float2(acc[i][j][2 * half + 0] + bb0,
                                       acc[i][j][2 * half + 1] + bb1);
                *reinterpret_cast<float2*>(out + ((size_t)rr * E + e) * H + hj) = v;
            }
        }
    }
#endif
}

// ---------------------------------------------------------------------------
extern "C" void kernel_launch(void* const* d_in, const int* in_sizes, int n_in,
                              void* d_out, int out_size)
{
    const float* tokens = (const float*)d_in[0];
    const float* ln_g   = (const float*)d_in[1];
    const float* ln_b   = (const float*)d_in[2];
    const float* W1     = (const float*)d_in[3];
    const float* b1     = (const float*)d_in[4];
    const float* W2     = (const float*)d_in[5];
    const float* b2     = (const float*)d_in[6];
    float* out = (float*)d_out;

    int T = in_sizes[0] / H;      // 8192
    int tiles = T / 128;          // 64

    cudaFuncSetAttribute(gemm1_kernel, cudaFuncAttributeMaxDynamicSharedMemorySize, SMEM_BYTES);
    cudaFuncSetAttribute(gemm2_kernel, cudaFuncAttributeMaxDynamicSharedMemorySize, SMEM_BYTES);

    ln_split_kernel<<<T, 256>>>(tokens);
    { dim3 g(F / 64, H / 64, E); w1t_kernel<<<g, 256>>>(W1, ln_g); }
    { dim3 g(H / 64, F / 64, E); w2t_kernel<<<g, 256>>>(W2); }
    { dim3 g(F / 256, E); b1p_kernel<<<g, 256>>>(W1, ln_b, b1); }
    { dim3 g(tiles, E, F / 128); gemm1_kernel<<<g, 256, SMEM_BYTES>>>(); }
    { dim3 g(tiles, E, H / 128); gemm2_kernel<<<g, 256, SMEM_BYTES>>>(b2, out); }
}

// round 4
// speedup vs baseline: 12.8058x; 1.1696x over previous
#include <cuda_runtime.h>
#include <cuda_bf16.h>
#include <math.h>
#include <stdint.h>

#define H 512
#define F 1024
#define E 16
#define MAX_T 8192
#define EPS 1e-5f

// Per-compile-pass feature detection: tcgen05 only legal on sm_103a-style targets.
#if defined(__CUDA_ARCH__) && (defined(__CUDA_ARCH_FEAT_SM103_ALL) || \
    defined(__CUDA_ARCH_FEAT_SM100_ALL) || defined(__CUDA_ARCH_SPECIFIC__) || \
    defined(__CUDA_ARCH_FAMILY_SPECIFIC__))
#define USE_TC 1
#else
#define USE_TC 0
#endif

// ---------------------------------------------------------------------------
// Scratch (no allocation allowed -> device globals)
// ---------------------------------------------------------------------------
__device__ __align__(128) __nv_bfloat16 g_xhi[(size_t)MAX_T * H];
__device__ __align__(128) __nv_bfloat16 g_xlo[(size_t)MAX_T * H];
__device__ __align__(128) __nv_bfloat16 g_w1thi[(size_t)E * F * H];   // [e][f][h]
__device__ __align__(128) __nv_bfloat16 g_w1tlo[(size_t)E * F * H];
__device__ __align__(128) __nv_bfloat16 g_w2thi[(size_t)E * H * F];   // [e][h][f]
__device__ __align__(128) __nv_bfloat16 g_w2tlo[(size_t)E * H * F];
__device__ float g_b1part[8][E * F];
__device__ float g_b1p[E * F];
__device__ __align__(128) __nv_bfloat16 g_hhi[(size_t)E * MAX_T * F]; // [e][t][f]
__device__ __align__(128) __nv_bfloat16 g_hlo[(size_t)E * MAX_T * F];

// ---------------------------------------------------------------------------
// Common helpers
// ---------------------------------------------------------------------------
__device__ __forceinline__ uint32_t smem_to_u32(const void* p) {
    uint32_t a;
    asm("{ .reg .u64 t; cvta.to.shared.u64 t, %1; cvt.u32.u64 %0, t; }" : "=r"(a) : "l"(p));
    return a;
}
#define SMEM_SWIZZLE_128B(o) ((o) ^ (((o) >> 3) & 0x70))

__device__ __forceinline__ void cpa16(uint32_t dst, const void* src) {
    asm volatile("cp.async.cg.shared.global [%0], [%1], 16;" :: "r"(dst), "l"(src));
}
#define CP_COMMIT() asm volatile("cp.async.commit_group;" ::: "memory")
__device__ __forceinline__ void cp_wait1() { asm volatile("cp.async.wait_group 1;" ::: "memory"); }
__device__ __forceinline__ void cp_wait0() { asm volatile("cp.async.wait_group 0;" ::: "memory"); }

__device__ __forceinline__ float gelu_erf(float x) {
    return 0.5f * x * (1.0f + erff(x * 0.70710678118654752f));
}

// Tile geometry: M=256 tokens, N=128, K-step=64
// SMEM stage: A_HI(32K) A_LO(32K) B_HI(16K) B_LO(16K) = 96KB; 2 stages
#define OFF_ALO 32768
#define OFF_BHI 65536
#define OFF_BLO 81920
#define STAGE_BYTES 98304
#define S_CTRL 196608            // tmem ptr (tc path)
#define S_MBAR 196624
#define SMEM_BYTES 196640

// Load one stage (A: 256x64 bf16 hi/lo, B: 128x64 bf16 hi/lo) with SW128 swizzle
__device__ __forceinline__ void stage_load_async(uint32_t sbase,
    const __nv_bfloat16* __restrict__ Ah, const __nv_bfloat16* __restrict__ Al, size_t as,
    const __nv_bfloat16* __restrict__ Bh, const __nv_bfloat16* __restrict__ Bl, size_t bs,
    int k0, int tid)
{
    #pragma unroll
    for (int it = 0; it < 8; it++) {           // A: 256 rows x 8 chunks
        int v = tid + it * 256;
        int r = v >> 3, c = v & 7;
        uint32_t off = SMEM_SWIZZLE_128B((uint32_t)(r * 128 + c * 16));
        size_t ga = (size_t)r * as + k0 + c * 8;
        cpa16(sbase + off,           Ah + ga);
        cpa16(sbase + OFF_ALO + off, Al + ga);
    }
    #pragma unroll
    for (int it = 0; it < 4; it++) {           // B: 128 rows x 8 chunks
        int v = tid + it * 256;
        int r = v >> 3, c = v & 7;
        uint32_t off = SMEM_SWIZZLE_128B((uint32_t)(r * 128 + c * 16));
        size_t gb = (size_t)r * bs + k0 + c * 8;
        cpa16(sbase + OFF_BHI + off, Bh + gb);
        cpa16(sbase + OFF_BLO + off, Bl + gb);
    }
}

// ===========================================================================
#if USE_TC
// tcgen05 path: two M=128 MMAs (rows 0-127, 128-255) into 2x128 TMEM cols
// ===========================================================================
__device__ __forceinline__ uint32_t elect_one_pred() {
    uint32_t pred;
    asm volatile("{\n\t.reg .pred p;\n\telect.sync _|p, 0xFFFFFFFF;\n\t"
                 "selp.b32 %0, 1, 0, p;\n\t}" : "=r"(pred));
    return pred;
}
static constexpr uint64_t SMEM_DESC_BASE_SW128 =
    (uint64_t(2) << 61) | (uint64_t(1) << 46) | (uint64_t(64) << 32) | (uint64_t(1) << 16);
#define MAKE_SMEM_DESC(a) (SMEM_DESC_BASE_SW128 | ((uint64_t)((a) >> 4) & 0x3FFF))

#define TCGEN05_ALLOC(sr, n) \
    asm volatile("tcgen05.alloc.cta_group::1.sync.aligned.shared::cta.b32 [%0], %1;" \
                 :: "r"((uint32_t)(sr)), "r"((uint32_t)(n)) : "memory")
#define TCGEN05_DEALLOC(t, n) \
    asm volatile("tcgen05.dealloc.cta_group::1.sync.aligned.b32 %0, %1;" :: "r"(t), "r"(n))
#define TCGEN05_RELINQUISH() \
    asm volatile("tcgen05.relinquish_alloc_permit.cta_group::1.sync.aligned;")
#define TCGEN05_COMMIT(m) \
    asm volatile("tcgen05.commit.cta_group::1.mbarrier::arrive::one.shared::cluster.b64 [%0];" \
                 :: "r"((uint32_t)(m)) : "memory")
#define TCGEN05_FENCE_AFTER() asm volatile("tcgen05.fence::after_thread_sync;" ::: "memory")
#define TCGEN05_WAIT_LD() asm volatile("tcgen05.wait::ld.sync.aligned;" ::: "memory")
#define MBARRIER_INIT(m, c) \
    asm volatile("mbarrier.init.shared.b64 [%0], %1;" :: "r"((uint32_t)(m)), "r"((uint32_t)(c)) : "memory")
#define MBARRIER_INVAL(m) \
    asm volatile("mbarrier.inval.shared.b64 [%0];" :: "r"((uint32_t)(m)) : "memory")

#define MBARRIER_WAIT_PARITY(mb, ph) do {                                         \
    uint32_t _m = (uint32_t)(mb), _p = (uint32_t)(ph), _d;                         \
    asm volatile("{\n\t.reg .pred p;\n\t"                                          \
        "mbarrier.try_wait.parity.acquire.cta.shared::cta.b64 p, [%1], %2;\n\t"    \
        "selp.b32 %0, 1, 0, p;\n\t}" : "=r"(_d) : "r"(_m), "r"(_p) : "memory");    \
    if (!_d) {                                                                     \
        asm volatile("{\n\t.reg .pred P1;\n\t"                                     \
            "WL_%=:\n\t"                                                           \
            "mbarrier.try_wait.parity.acquire.cta.shared::cta.b64 P1, [%0], %1, 0x989680;\n\t" \
            "@P1 bra.uni WD_%=;\n\t"                                               \
            "bra.uni WL_%=;\n\t"                                                   \
            "WD_%=:\n\t}" :: "r"(_m), "r"(_p) : "memory");                         \
    }                                                                              \
} while (0)

#define TCGEN05_LD_X32(r, a)                                                       \
    asm volatile("tcgen05.ld.sync.aligned.32x32b.x32.b32 "                         \
        "{%0, %1, %2, %3, %4, %5, %6, %7, %8, %9, %10, %11, %12, %13, %14, %15, "  \
        " %16, %17, %18, %19, %20, %21, %22, %23, %24, %25, %26, %27, %28, %29, %30, %31}, [%32];" \
        : "=r"((r)[0]), "=r"((r)[1]), "=r"((r)[2]), "=r"((r)[3]),                  \
          "=r"((r)[4]), "=r"((r)[5]), "=r"((r)[6]), "=r"((r)[7]),                  \
          "=r"((r)[8]), "=r"((r)[9]), "=r"((r)[10]), "=r"((r)[11]),                \
          "=r"((r)[12]), "=r"((r)[13]), "=r"((r)[14]), "=r"((r)[15]),              \
          "=r"((r)[16]), "=r"((r)[17]), "=r"((r)[18]), "=r"((r)[19]),              \
          "=r"((r)[20]), "=r"((r)[21]), "=r"((r)[22]), "=r"((r)[23]),              \
          "=r"((r)[24]), "=r"((r)[25]), "=r"((r)[26]), "=r"((r)[27]),              \
          "=r"((r)[28]), "=r"((r)[29]), "=r"((r)[30]), "=r"((r)[31])               \
        : "r"(a))

__device__ __forceinline__ void mma_bf16_ss(uint32_t d_tmem, uint64_t a_desc,
                                            uint64_t b_desc, uint32_t idesc, bool acc) {
    uint32_t en = acc ? 1u : 0u;
    asm volatile("{\n\t.reg .pred p;\n\tsetp.ne.u32 p, %4, 0;\n\t"
                 "tcgen05.mma.cta_group::1.kind::f16 [%0], %1, %2, %3, p;\n\t}"
                 :: "r"(d_tmem), "l"(a_desc), "l"(b_desc), "r"(idesc), "r"(en)
                 : "memory");
}
// dtype=F32, atype=btype=BF16, N=128, M=128, K-major
#define MMA_IDESC ((1u << 4) | (1u << 7) | (1u << 10) | ((128u / 8u) << 17) | ((128u / 16u) << 24))

__device__ __forceinline__ uint32_t tc_prologue(uint32_t su, int tid, int wid) {
    if (wid == 0) TCGEN05_ALLOC(su + S_CTRL, 256);
    if (tid == 128) MBARRIER_INIT(su + S_MBAR, 1);
    __syncthreads();
    uint32_t tmem;
    asm volatile("ld.shared.b32 %0, [%1];" : "=r"(tmem) : "r"(su + S_CTRL));
    if (wid == 0) TCGEN05_RELINQUISH();
    __syncthreads();
    return tmem;
}

__device__ __forceinline__ void tc_mainloop(uint32_t su, uint32_t tmem,
    const __nv_bfloat16* __restrict__ Ah, const __nv_bfloat16* __restrict__ Al, size_t as,
    const __nv_bfloat16* __restrict__ Bh, const __nv_bfloat16* __restrict__ Bl, size_t bs,
    int K, int tid, int wid)
{
    const int nk = K / 64;
    stage_load_async(su, Ah, Al, as, Bh, Bl, bs, 0, tid);
    CP_COMMIT();
    for (int ks = 0; ks < nk; ks++) {
        if (ks > 0) MBARRIER_WAIT_PARITY(su + S_MBAR, (ks - 1) & 1);
        if (ks + 1 < nk) {
            stage_load_async(su + ((ks + 1) & 1) * STAGE_BYTES,
                             Ah, Al, as, Bh, Bl, bs, (ks + 1) * 64, tid);
            CP_COMMIT();
            cp_wait1();
        } else {
            cp_wait0();
        }
        __syncthreads();
        if (wid == 0 && elect_one_pred()) {
            asm volatile("fence.proxy.async.shared::cta;" ::: "memory");
            uint32_t sb = su + (ks & 1) * STAGE_BYTES;
            #pragma unroll
            for (int mh = 0; mh < 2; mh++) {       // M halves (rows 0-127 / 128-255)
                uint64_t dAh = MAKE_SMEM_DESC(sb + mh * 16384);
                uint64_t dAl = MAKE_SMEM_DESC(sb + OFF_ALO + mh * 16384);
                uint64_t dBh = MAKE_SMEM_DESC(sb + OFF_BHI);
                uint64_t dBl = MAKE_SMEM_DESC(sb + OFF_BLO);
                uint32_t dt = tmem + mh * 128;
                #pragma unroll
                for (int kk = 0; kk < 4; kk++) {
                    bool acc0 = (ks > 0) || (kk > 0);
                    mma_bf16_ss(dt, dAh + kk * 2, dBh + kk * 2, MMA_IDESC, acc0);
                    mma_bf16_ss(dt, dAh + kk * 2, dBl + kk * 2, MMA_IDESC, true);
                    mma_bf16_ss(dt, dAl + kk * 2, dBh + kk * 2, MMA_IDESC, true);
                }
            }
            TCGEN05_COMMIT(su + S_MBAR);
        }
        __syncthreads();
    }
    MBARRIER_WAIT_PARITY(su + S_MBAR, (nk - 1) & 1);
    TCGEN05_FENCE_AFTER();
}

__device__ __forceinline__ void tc_release(uint32_t su, uint32_t tmem, int tid, int wid) {
    __syncthreads();
    if (tid == 128) MBARRIER_INVAL(su + S_MBAR);
    __syncthreads();
    if (wid == 0) TCGEN05_DEALLOC(tmem, 256);
}
#endif  // USE_TC

// ===========================================================================
#if !USE_TC
// mma.sync fallback (legal on plain compute_103): 8 warps, warp tile 64x64
// ===========================================================================
__device__ __forceinline__ void ldsm_x4(uint32_t* r, uint32_t a) {
    asm volatile("ldmatrix.sync.aligned.m8n8.x4.shared.b16 {%0,%1,%2,%3}, [%4];"
                 : "=r"(r[0]), "=r"(r[1]), "=r"(r[2]), "=r"(r[3]) : "r"(a));
}
__device__ __forceinline__ void mma16816(float* d, const uint32_t* a, const uint32_t* b) {
    asm volatile("mma.sync.aligned.m16n8k16.row.col.f32.bf16.bf16.f32 "
                 "{%0,%1,%2,%3}, {%4,%5,%6,%7}, {%8,%9}, {%0,%1,%2,%3};"
                 : "+f"(d[0]), "+f"(d[1]), "+f"(d[2]), "+f"(d[3])
                 : "r"(a[0]), "r"(a[1]), "r"(a[2]), "r"(a[3]), "r"(b[0]), "r"(b[1]));
}

__device__ __forceinline__ void mmasync_mainloop(uint32_t su,
    const __nv_bfloat16* __restrict__ Ah, const __nv_bfloat16* __restrict__ Al, size_t as,
    const __nv_bfloat16* __restrict__ Bh, const __nv_bfloat16* __restrict__ Bl, size_t bs,
    int K, int tid, float acc[4][8][4])
{
    const int nk = K / 64;
    const int wid = tid >> 5, lane = tid & 31;
    const int wm = wid >> 1, wn = wid & 1;

    stage_load_async(su, Ah, Al, as, Bh, Bl, bs, 0, tid);
    CP_COMMIT();

    for (int ks = 0; ks < nk; ks++) {
        if (ks + 1 < nk) {
            stage_load_async(su + ((ks + 1) & 1) * STAGE_BYTES,
                             Ah, Al, as, Bh, Bl, bs, (ks + 1) * 64, tid);
            CP_COMMIT();
            cp_wait1();
        } else {
            cp_wait0();
        }
        __syncthreads();

        uint32_t sA = su + (ks & 1) * STAGE_BYTES;
        uint32_t sB = sA + OFF_BHI;

        #pragma unroll
        for (int k16 = 0; k16 < 64; k16 += 16) {
            // B fragments: warp covers n in [wn*64, wn*64+64)
            uint32_t bh[8][2], bl[8][2];
            #pragma unroll
            for (int jj = 0; jj < 4; jj++) {
                int n = wn * 64 + jj * 16 + (lane & 7) + ((lane >> 3) & 1) * 8;
                int k = k16 + (lane >> 4) * 8;
                uint32_t addr = sB + SMEM_SWIZZLE_128B((uint32_t)(n * 128 + k * 2));
                uint32_t t[4];
                ldsm_x4(t, addr);
                bh[2 * jj][0] = t[0]; bh[2 * jj + 1][0] = t[1];
                bh[2 * jj][1] = t[2]; bh[2 * jj + 1][1] = t[3];
                ldsm_x4(t, addr + 16384);   // B_LO - B_HI
                bl[2 * jj][0] = t[0]; bl[2 * jj + 1][0] = t[1];
                bl[2 * jj][1] = t[2]; bl[2 * jj + 1][1] = t[3];
            }
            // A fragments + MMA: warp covers m in [wm*64, wm*64+64)
            #pragma unroll
            for (int i = 0; i < 4; i++) {
                int m = wm * 64 + i * 16 + (lane & 15);
                int k = k16 + (lane >> 4) * 8;
                uint32_t addr = sA + SMEM_SWIZZLE_128B((uint32_t)(m * 128 + k * 2));
                uint32_t ah[4], al[4];
                ldsm_x4(ah, addr);
                ldsm_x4(al, addr + OFF_ALO);
                #pragma unroll
                for (int j = 0; j < 8; j++) {
                    mma16816(acc[i][j], ah, bh[j]);
                    mma16816(acc[i][j], ah, bl[j]);
                    mma16816(acc[i][j], al, bh[j]);
                }
            }
        }
        __syncthreads();
    }
}
#endif  // !USE_TC

// ---------------------------------------------------------------------------
// Prep kernels
// ---------------------------------------------------------------------------
__device__ __forceinline__ float blk_sum256(float v) {
    __shared__ float red[8];
    #pragma unroll
    for (int o = 16; o > 0; o >>= 1) v += __shfl_xor_sync(0xffffffffu, v, o);
    int w = threadIdx.x >> 5, l = threadIdx.x & 31;
    if (l == 0) red[w] = v;
    __syncthreads();
    if (threadIdx.x < 32) {
        float r = (threadIdx.x < 8) ? red[threadIdx.x] : 0.0f;
        #pragma unroll
        for (int o = 4; o > 0; o >>= 1) r += __shfl_xor_sync(0xffffffffu, r, o);
        if (threadIdx.x == 0) red[0] = r;
    }
    __syncthreads();
    float out = red[0];
    __syncthreads();
    return out;
}

__global__ void ln_split_kernel(const float* __restrict__ tokens) {
    int row = blockIdx.x, tid = threadIdx.x;
    const float* x = tokens + (size_t)row * H;
    float v0 = x[tid], v1 = x[tid + 256];
    float mu = blk_sum256(v0 + v1) * (1.0f / H);
    float d0 = v0 - mu, d1 = v1 - mu;
    float rs = rsqrtf(blk_sum256(d0 * d0 + d1 * d1) * (1.0f / H) + EPS);
    float a0 = d0 * rs, a1 = d1 * rs;
    size_t base = (size_t)row * H;
    __nv_bfloat16 h0 = __float2bfloat16(a0);
    __nv_bfloat16 h1 = __float2bfloat16(a1);
    g_xhi[base + tid] = h0;
    g_xhi[base + tid + 256] = h1;
    g_xlo[base + tid] = __float2bfloat16(a0 - __bfloat162float(h0));
    g_xlo[base + tid + 256] = __float2bfloat16(a1 - __bfloat162float(h1));
}

__global__ void w1t_kernel(const float* __restrict__ W1, const float* __restrict__ ln_g) {
    __shared__ float ts[64][65];
    int e = blockIdx.z, f0 = blockIdx.x * 64, h0 = blockIdx.y * 64, tid = threadIdx.x;
    #pragma unroll
    for (int i = 0; i < 16; i++) {
        int idx = tid + i * 256, r = idx >> 6, c = idx & 63;
        ts[r][c] = W1[((size_t)e * H + h0 + r) * F + f0 + c];
    }
    __syncthreads();
    #pragma unroll
    for (int i = 0; i < 16; i++) {
        int idx = tid + i * 256, r = idx >> 6, c = idx & 63;
        float w = ts[c][r] * ln_g[e * H + h0 + c];
        __nv_bfloat16 hi = __float2bfloat16(w);
        size_t o = ((size_t)e * F + f0 + r) * H + h0 + c;
        g_w1thi[o] = hi;
        g_w1tlo[o] = __float2bfloat16(w - __bfloat162float(hi));
    }
}

__global__ void w2t_kernel(const float* __restrict__ W2) {
    __shared__ float ts[64][65];
    int e = blockIdx.z, h0 = blockIdx.x * 64, f0 = blockIdx.y * 64, tid = threadIdx.x;
    #pragma unroll
    for (int i = 0; i < 16; i++) {
        int idx = tid + i * 256, r = idx >> 6, c = idx & 63;
        ts[r][c] = W2[((size_t)e * F + f0 + r) * H + h0 + c];
    }
    __syncthreads();
    #pragma unroll
    for (int i = 0; i < 16; i++) {
        int idx = tid + i * 256, r = idx >> 6, c = idx & 63;
        float w = ts[c][r];
        __nv_bfloat16 hi = __float2bfloat16(w);
        size_t o = ((size_t)e * H + h0 + r) * F + f0 + c;
        g_w2thi[o] = hi;
        g_w2tlo[o] = __float2bfloat16(w - __bfloat162float(hi));
    }
}

// b1' = ln_b @ W1 + b1, two-phase deterministic (h split into 8 slabs of 64)
__global__ void b1p_part_kernel(const float* __restrict__ W1, const float* __restrict__ ln_b) {
    int e = blockIdx.y, hs = blockIdx.z * 64;
    int f = blockIdx.x * 256 + threadIdx.x;
    const float* w = W1 + ((size_t)e * H + hs) * F + f;
    const float* b = ln_b + e * H + hs;
    float acc = 0.0f;
    #pragma unroll 8
    for (int h = 0; h < 64; h++) acc += b[h] * w[(size_t)h * F];
    g_b1part[blockIdx.z][e * F + f] = acc;
}
__global__ void b1p_reduce_kernel(const float* __restrict__ b1) {
    int i = blockIdx.x * 256 + threadIdx.x;
    float acc = b1[i];
    #pragma unroll
    for (int s = 0; s < 8; s++) acc += g_b1part[s][i];
    g_b1p[i] = acc;
}

// ---------------------------------------------------------------------------
// GEMM1: h = gelu(xhat @ (g*W1) + b1')    grid: (T/256, E, F/128)
// ---------------------------------------------------------------------------
__global__ void __launch_bounds__(256, 1) gemm1_kernel() {
    extern __shared__ char smem[];
    uint32_t su = smem_to_u32(smem);
    const int tid = threadIdx.x, wid = tid >> 5, lane = tid & 31;
    const int e = blockIdx.y;
    const int tok0 = blockIdx.x * 256;
    const int fc = blockIdx.z * 128;

    const __nv_bfloat16* Ah = g_xhi + (size_t)tok0 * H;
    const __nv_bfloat16* Al = g_xlo + (size_t)tok0 * H;
    const __nv_bfloat16* Bh = g_w1thi + ((size_t)e * F + fc) * H;
    const __nv_bfloat16* Bl = g_w1tlo + ((size_t)e * F + fc) * H;

#if USE_TC
    uint32_t tmem = tc_prologue(su, tid, wid);
    tc_mainloop(su, tmem, Ah, Al, H, Bh, Bl, H, H, tid, wid);

    const int row = (wid >= 4 ? 128 : 0) + (wid & 3) * 32 + lane;
    const uint32_t dbase = tmem + (wid >= 4 ? 128 : 0);
    const size_t hrow = ((size_t)e * MAX_T + tok0 + row) * F;
    for (int cb = 0; cb < 128; cb += 32) {
        uint32_t r[32];
        TCGEN05_LD_X32(r, dbase + cb);
        TCGEN05_WAIT_LD();
        int fglob = fc + cb;
        __nv_bfloat16 hi8[8], lo8[8];
        #pragma unroll
        for (int j = 0; j < 32; j++) {
            float v = __uint_as_float(r[j]) + g_b1p[e * F + fglob + j];
            float gl = gelu_erf(v);
            __nv_bfloat16 hb = __float2bfloat16(gl);
            hi8[j & 7] = hb;
            lo8[j & 7] = __float2bfloat16(gl - __bfloat162float(hb));
            if ((j & 7) == 7) {
                size_t o = hrow + fglob + (j & ~7);
                *reinterpret_cast<uint4*>(&g_hhi[o]) = *reinterpret_cast<uint4*>(hi8);
                *reinterpret_cast<uint4*>(&g_hlo[o]) = *reinterpret_cast<uint4*>(lo8);
            }
        }
    }
    tc_release(su, tmem, tid, wid);
#else
    float acc[4][8][4];
    #pragma unroll
    for (int i = 0; i < 4; i++)
        #pragma unroll
        for (int j = 0; j < 8; j++)
            #pragma unroll
            for (int q = 0; q < 4; q++) acc[i][j][q] = 0.0f;

    mmasync_mainloop(su, Ah, Al, H, Bh, Bl, H, H, tid, acc);

    const int wm = wid >> 1, wn = wid & 1;
    const float* b1pp = g_b1p + e * F;
    #pragma unroll
    for (int i = 0; i < 4; i++) {
        #pragma unroll
        for (int j = 0; j < 8; j++) {
            int fj = fc + wn * 64 + j * 8 + (lane & 3) * 2;
            int r0 = tok0 + wm * 64 + i * 16 + (lane >> 2);
            #pragma unroll
            for (int half = 0; half < 2; half++) {
                int rr = r0 + half * 8;
                float v0 = acc[i][j][2 * half + 0] + b1pp[fj];
                float v1 = acc[i][j][2 * half + 1] + b1pp[fj + 1];
                float g0 = gelu_erf(v0), g1 = gelu_erf(v1);
                __nv_bfloat16 h0 = __float2bfloat16(g0);
                __nv_bfloat16 h1 = __float2bfloat16(g1);
                __nv_bfloat16 l0 = __float2bfloat16(g0 - __bfloat162float(h0));
                __nv_bfloat16 l1 = __float2bfloat16(g1 - __bfloat162float(h1));
                uint32_t ph = ((uint32_t)__bfloat16_as_ushort(h1) << 16) | __bfloat16_as_ushort(h0);
                uint32_t pl = ((uint32_t)__bfloat16_as_ushort(l1) << 16) | __bfloat16_as_ushort(l0);
                size_t o = ((size_t)e * MAX_T + rr) * F + fj;
                *reinterpret_cast<uint32_t*>(&g_hhi[o]) = ph;
                *reinterpret_cast<uint32_t*>(&g_hlo[o]) = pl;
            }
        }
    }
#endif
}

// ---------------------------------------------------------------------------
// GEMM2: out = h @ W2 + b2     grid: (T/256, E, H/128)
// ---------------------------------------------------------------------------
__global__ void __launch_bounds__(256, 1) gemm2_kernel(const float* __restrict__ b2,
                                                       float* __restrict__ out) {
    extern __shared__ char smem[];
    uint32_t su = smem_to_u32(smem);
    const int tid = threadIdx.x, wid = tid >> 5, lane = tid & 31;
    const int e = blockIdx.y;
    const int tok0 = blockIdx.x * 256;
    const int hh0 = blockIdx.z * 128;

    const size_t hbase = ((size_t)e * MAX_T + tok0) * F;
    const __nv_bfloat16* Ah = g_hhi + hbase;
    const __nv_bfloat16* Al = g_hlo + hbase;
    const __nv_bfloat16* Bh = g_w2thi + ((size_t)e * H + hh0) * F;
    const __nv_bfloat16* Bl = g_w2tlo + ((size_t)e * H + hh0) * F;

#if USE_TC
    uint32_t tmem = tc_prologue(su, tid, wid);
    tc_mainloop(su, tmem, Ah, Al, F, Bh, Bl, F, F, tid, wid);

    const int row = (wid >= 4 ? 128 : 0) + (wid & 3) * 32 + lane;
    const uint32_t dbase = tmem + (wid >= 4 ? 128 : 0);
    float* orow = out + (((size_t)(tok0 + row)) * E + e) * H;
    for (int cb = 0; cb < 128; cb += 32) {
        uint32_t r[32];
        TCGEN05_LD_X32(r, dbase + cb);
        TCGEN05_WAIT_LD();
        int hglob = hh0 + cb;
        float v4[4];
        #pragma unroll
        for (int j = 0; j < 32; j++) {
            v4[j & 3] = __uint_as_float(r[j]) + b2[e * H + hglob + j];
            if ((j & 3) == 3)
                *reinterpret_cast<uint4*>(orow + hglob + (j & ~3)) =
                    *reinterpret_cast<uint4*>(v4);
        }
    }
    tc_release(su, tmem, tid, wid);
#else
    float acc[4][8][4];
    #pragma unroll
    for (int i = 0; i < 4; i++)
        #pragma unroll
        for (int j = 0; j < 8; j++)
            #pragma unroll
            for (int q = 0; q < 4; q++) acc[i][j][q] = 0.0f;

    mmasync_mainloop(su, Ah, Al, F, Bh, Bl, F, F, tid, acc);

    const int wm = wid >> 1, wn = wid & 1;
    const float* b2p = b2 + e * H;
    #pragma unroll
    for (int i = 0; i < 4; i++) {
        #pragma unroll
        for (int j = 0; j < 8; j++) {
            int hj = hh0 + wn * 64 + j * 8 + (lane & 3) * 2;
            int r0 = tok0 + wm * 64 + i * 16 + (lane >> 2);
            float bb0 = b2p[hj], bb1 = b2p[hj + 1];
            #pragma unroll
            for (int half = 0; half < 2; half++) {
                int rr = r0 + half * 8;
                float2 v = make_float2(acc[i][j][2 * half + 0] + bb0,
                                       acc[i][j][2 * half + 1] + bb1);
                *reinterpret_cast<float2*>(out + ((size_t)rr * E + e) * H + hj) = v;
            }
        }
    }
#endif
}

// ---------------------------------------------------------------------------
extern "C" void kernel_launch(void* const* d_in, const int* in_sizes, int n_in,
                              void* d_out, int out_size)
{
    const float* tokens = (const float*)d_in[0];
    const float* ln_g   = (const float*)d_in[1];
    const float* ln_b   = (const float*)d_in[2];
    const float* W1     = (const float*)d_in[3];
    const float* b1     = (const float*)d_in[4];
    const float* W2     = (const float*)d_in[5];
    const float* b2     = (const float*)d_in[6];
    float* out = (float*)d_out;

    int T = in_sizes[0] / H;      // 8192
    int tiles = T / 256;          // 32

    cudaFuncSetAttribute(gemm1_kernel, cudaFuncAttributeMaxDynamicSharedMemorySize, SMEM_BYTES);
    cudaFuncSetAttribute(gemm2_kernel, cudaFuncAttributeMaxDynamicSharedMemorySize, SMEM_BYTES);

    ln_split_kernel<<<T, 256>>>(tokens);
    { dim3 g(F / 64, H / 64, E); w1t_kernel<<<g, 256>>>(W1, ln_g); }
    { dim3 g(H / 64, F / 64, E); w2t_kernel<<<g, 256>>>(W2); }
    { dim3 g(F / 256, E, 8); b1p_part_kernel<<<g, 256>>>(W1, ln_b); }
    b1p_reduce_kernel<<<E * F / 256, 256>>>(b1);
    { dim3 g(tiles, E, F / 128); gemm1_kernel<<<g, 256, SMEM_BYTES>>>(); }
    { dim3 g(tiles, E, H / 128); gemm2_kernel<<<g, 256, SMEM_BYTES>>>(b2, out); }
}

// round 5
// speedup vs baseline: 17.2383x; 1.3461x over previous
#include <cuda_runtime.h>
#include <cuda_fp16.h>
#include <math.h>
#include <stdint.h>

#define H 512
#define F 1024
#define E 16
#define MAX_T 8192
#define EPS 1e-5f

// Per-compile-pass feature detection: tcgen05 only legal on sm_103a-style targets.
#if defined(__CUDA_ARCH__) && (defined(__CUDA_ARCH_FEAT_SM103_ALL) || \
    defined(__CUDA_ARCH_FEAT_SM100_ALL) || defined(__CUDA_ARCH_SPECIFIC__) || \
    defined(__CUDA_ARCH_FAMILY_SPECIFIC__))
#define USE_TC 1
#else
#define USE_TC 0
#endif

// ---------------------------------------------------------------------------
// Scratch (no allocation allowed -> device globals)
// Activations: single fp16. Weights: fp16 hi+lo split (exact to ~2^-22).
// ---------------------------------------------------------------------------
__device__ __align__(128) __half g_x[(size_t)MAX_T * H];
__device__ __align__(128) __half g_w1thi[(size_t)E * F * H];   // [e][f][h]
__device__ __align__(128) __half g_w1tlo[(size_t)E * F * H];
__device__ __align__(128) __half g_w2thi[(size_t)E * H * F];   // [e][h][f]
__device__ __align__(128) __half g_w2tlo[(size_t)E * H * F];
__device__ float g_b1part[8][E * F];
__device__ float g_b1p[E * F];
__device__ __align__(128) __half g_h[(size_t)E * MAX_T * F];   // [e][t][f]

// ---------------------------------------------------------------------------
// Common helpers
// ---------------------------------------------------------------------------
__device__ __forceinline__ uint32_t smem_to_u32(const void* p) {
    uint32_t a;
    asm("{ .reg .u64 t; cvta.to.shared.u64 t, %1; cvt.u32.u64 %0, t; }" : "=r"(a) : "l"(p));
    return a;
}
#define SMEM_SWIZZLE_128B(o) ((o) ^ (((o) >> 3) & 0x70))

__device__ __forceinline__ void cpa16(uint32_t dst, const void* src) {
    asm volatile("cp.async.cg.shared.global [%0], [%1], 16;" :: "r"(dst), "l"(src));
}
#define CP_COMMIT() asm volatile("cp.async.commit_group;" ::: "memory")
__device__ __forceinline__ void cp_wait2() { asm volatile("cp.async.wait_group 2;" ::: "memory"); }
__device__ __forceinline__ void cp_wait1() { asm volatile("cp.async.wait_group 1;" ::: "memory"); }
__device__ __forceinline__ void cp_wait0() { asm volatile("cp.async.wait_group 0;" ::: "memory"); }

__device__ __forceinline__ float gelu_erf(float x) {
    return 0.5f * x * (1.0f + erff(x * 0.70710678118654752f));
}

// Tile geometry: M=256 tokens, N=128, K-step=64
// SMEM stage: A(32K single) B_HI(16K) B_LO(16K) = 64KB; 3 stages
#define OFF_BHI 32768
#define OFF_BLO 49152
#define STAGE_BYTES 65536
#define S_CTRL 196608            // tmem ptr (tc path)
#define S_MBAR 196624
#define SMEM_BYTES 196640

// Load one stage (A: 256x64 fp16 single, B: 128x64 fp16 hi/lo) with SW128 swizzle
__device__ __forceinline__ void stage_load_async(uint32_t sbase,
    const __half* __restrict__ A, size_t as,
    const __half* __restrict__ Bh, const __half* __restrict__ Bl, size_t bs,
    int k0, int tid)
{
    #pragma unroll
    for (int it = 0; it < 8; it++) {           // A: 256 rows x 8 chunks
        int v = tid + it * 256;
        int r = v >> 3, c = v & 7;
        uint32_t off = SMEM_SWIZZLE_128B((uint32_t)(r * 128 + c * 16));
        cpa16(sbase + off, A + (size_t)r * as + k0 + c * 8);
    }
    #pragma unroll
    for (int it = 0; it < 4; it++) {           // B: 128 rows x 8 chunks
        int v = tid + it * 256;
        int r = v >> 3, c = v & 7;
        uint32_t off = SMEM_SWIZZLE_128B((uint32_t)(r * 128 + c * 16));
        size_t gb = (size_t)r * bs + k0 + c * 8;
        cpa16(sbase + OFF_BHI + off, Bh + gb);
        cpa16(sbase + OFF_BLO + off, Bl + gb);
    }
}

// ===========================================================================
#if USE_TC
// tcgen05 path: two M=128 MMAs per k-chunk into 2x128 TMEM cols
// ===========================================================================
__device__ __forceinline__ uint32_t elect_one_pred() {
    uint32_t pred;
    asm volatile("{\n\t.reg .pred p;\n\telect.sync _|p, 0xFFFFFFFF;\n\t"
                 "selp.b32 %0, 1, 0, p;\n\t}" : "=r"(pred));
    return pred;
}
static constexpr uint64_t SMEM_DESC_BASE_SW128 =
    (uint64_t(2) << 61) | (uint64_t(1) << 46) | (uint64_t(64) << 32) | (uint64_t(1) << 16);
#define MAKE_SMEM_DESC(a) (SMEM_DESC_BASE_SW128 | ((uint64_t)((a) >> 4) & 0x3FFF))

#define TCGEN05_ALLOC(sr, n) \
    asm volatile("tcgen05.alloc.cta_group::1.sync.aligned.shared::cta.b32 [%0], %1;" \
                 :: "r"((uint32_t)(sr)), "r"((uint32_t)(n)) : "memory")
#define TCGEN05_DEALLOC(t, n) \
    asm volatile("tcgen05.dealloc.cta_group::1.sync.aligned.b32 %0, %1;" :: "r"(t), "r"(n))
#define TCGEN05_RELINQUISH() \
    asm volatile("tcgen05.relinquish_alloc_permit.cta_group::1.sync.aligned;")
#define TCGEN05_COMMIT(m) \
    asm volatile("tcgen05.commit.cta_group::1.mbarrier::arrive::one.shared::cluster.b64 [%0];" \
                 :: "r"((uint32_t)(m)) : "memory")
#define TCGEN05_FENCE_AFTER() asm volatile("tcgen05.fence::after_thread_sync;" ::: "memory")
#define TCGEN05_WAIT_LD() asm volatile("tcgen05.wait::ld.sync.aligned;" ::: "memory")
#define MBARRIER_INIT(m, c) \
    asm volatile("mbarrier.init.shared.b64 [%0], %1;" :: "r"((uint32_t)(m)), "r"((uint32_t)(c)) : "memory")
#define MBARRIER_INVAL(m) \
    asm volatile("mbarrier.inval.shared.b64 [%0];" :: "r"((uint32_t)(m)) : "memory")

#define MBARRIER_WAIT_PARITY(mb, ph) do {                                         \
    uint32_t _m = (uint32_t)(mb), _p = (uint32_t)(ph), _d;                         \
    asm volatile("{\n\t.reg .pred p;\n\t"                                          \
        "mbarrier.try_wait.parity.acquire.cta.shared::cta.b64 p, [%1], %2;\n\t"    \
        "selp.b32 %0, 1, 0, p;\n\t}" : "=r"(_d) : "r"(_m), "r"(_p) : "memory");    \
    if (!_d) {                                                                     \
        asm volatile("{\n\t.reg .pred P1;\n\t"                                     \
            "WL_%=:\n\t"                                                           \
            "mbarrier.try_wait.parity.acquire.cta.shared::cta.b64 P1, [%0], %1, 0x989680;\n\t" \
            "@P1 bra.uni WD_%=;\n\t"                                               \
            "bra.uni WL_%=;\n\t"                                                   \
            "WD_%=:\n\t}" :: "r"(_m), "r"(_p) : "memory");                         \
    }                                                                              \
} while (0)

#define TCGEN05_LD_X32(r, a)                                                       \
    asm volatile("tcgen05.ld.sync.aligned.32x32b.x32.b32 "                         \
        "{%0, %1, %2, %3, %4, %5, %6, %7, %8, %9, %10, %11, %12, %13, %14, %15, "  \
        " %16, %17, %18, %19, %20, %21, %22, %23, %24, %25, %26, %27, %28, %29, %30, %31}, [%32];" \
        : "=r"((r)[0]), "=r"((r)[1]), "=r"((r)[2]), "=r"((r)[3]),                  \
          "=r"((r)[4]), "=r"((r)[5]), "=r"((r)[6]), "=r"((r)[7]),                  \
          "=r"((r)[8]), "=r"((r)[9]), "=r"((r)[10]), "=r"((r)[11]),                \
          "=r"((r)[12]), "=r"((r)[13]), "=r"((r)[14]), "=r"((r)[15]),              \
          "=r"((r)[16]), "=r"((r)[17]), "=r"((r)[18]), "=r"((r)[19]),              \
          "=r"((r)[20]), "=r"((r)[21]), "=r"((r)[22]), "=r"((r)[23]),              \
          "=r"((r)[24]), "=r"((r)[25]), "=r"((r)[26]), "=r"((r)[27]),              \
          "=r"((r)[28]), "=r"((r)[29]), "=r"((r)[30]), "=r"((r)[31])               \
        : "r"(a))

__device__ __forceinline__ void mma_f16_ss(uint32_t d_tmem, uint64_t a_desc,
                                           uint64_t b_desc, uint32_t idesc, bool acc) {
    uint32_t en = acc ? 1u : 0u;
    asm volatile("{\n\t.reg .pred p;\n\tsetp.ne.u32 p, %4, 0;\n\t"
                 "tcgen05.mma.cta_group::1.kind::f16 [%0], %1, %2, %3, p;\n\t}"
                 :: "r"(d_tmem), "l"(a_desc), "l"(b_desc), "r"(idesc), "r"(en)
                 : "memory");
}
// dtype=F32, atype=btype=F16(0), N=128, M=128, K-major
#define MMA_IDESC ((1u << 4) | ((128u / 8u) << 17) | ((128u / 16u) << 24))

__device__ __forceinline__ uint32_t tc_prologue(uint32_t su, int tid, int wid) {
    if (wid == 0) TCGEN05_ALLOC(su + S_CTRL, 256);
    if (tid == 128) MBARRIER_INIT(su + S_MBAR, 1);
    __syncthreads();
    uint32_t tmem;
    asm volatile("ld.shared.b32 %0, [%1];" : "=r"(tmem) : "r"(su + S_CTRL));
    if (wid == 0) TCGEN05_RELINQUISH();
    __syncthreads();
    return tmem;
}

__device__ __forceinline__ void tc_mainloop(uint32_t su, uint32_t tmem,
    const __half* __restrict__ A, size_t as,
    const __half* __restrict__ Bh, const __half* __restrict__ Bl, size_t bs,
    int K, int tid, int wid)
{
    const int nk = K / 64;
    stage_load_async(su, A, as, Bh, Bl, bs, 0, tid);
    CP_COMMIT();
    if (nk > 1) {
        stage_load_async(su + STAGE_BYTES, A, as, Bh, Bl, bs, 64, tid);
        CP_COMMIT();
    }
    for (int ks = 0; ks < nk; ks++) {
        if (ks > 0) MBARRIER_WAIT_PARITY(su + S_MBAR, (ks - 1) & 1);
        if (ks + 2 < nk) {
            stage_load_async(su + ((ks + 2) % 3) * STAGE_BYTES,
                             A, as, Bh, Bl, bs, (ks + 2) * 64, tid);
            CP_COMMIT();
            cp_wait2();
        } else if (ks + 1 < nk) {
            cp_wait1();
        } else {
            cp_wait0();
        }
        __syncthreads();
        if (wid == 0 && elect_one_pred()) {
            asm volatile("fence.proxy.async.shared::cta;" ::: "memory");
            uint32_t sb = su + (ks % 3) * STAGE_BYTES;
            #pragma unroll
            for (int mh = 0; mh < 2; mh++) {       // M halves (rows 0-127 / 128-255)
                uint64_t dA  = MAKE_SMEM_DESC(sb + mh * 16384);
                uint64_t dBh = MAKE_SMEM_DESC(sb + OFF_BHI);
                uint64_t dBl = MAKE_SMEM_DESC(sb + OFF_BLO);
                uint32_t dt = tmem + mh * 128;
                #pragma unroll
                for (int kk = 0; kk < 4; kk++) {
                    bool acc0 = (ks > 0) || (kk > 0);
                    mma_f16_ss(dt, dA + kk * 2, dBh + kk * 2, MMA_IDESC, acc0);
                    mma_f16_ss(dt, dA + kk * 2, dBl + kk * 2, MMA_IDESC, true);
                }
            }
            TCGEN05_COMMIT(su + S_MBAR);
        }
        __syncthreads();
    }
    MBARRIER_WAIT_PARITY(su + S_MBAR, (nk - 1) & 1);
    TCGEN05_FENCE_AFTER();
}

__device__ __forceinline__ void tc_release(uint32_t su, uint32_t tmem, int tid, int wid) {
    __syncthreads();
    if (tid == 128) MBARRIER_INVAL(su + S_MBAR);
    __syncthreads();
    if (wid == 0) TCGEN05_DEALLOC(tmem, 256);
}
#endif  // USE_TC

// ===========================================================================
#if !USE_TC
// mma.sync fallback (legal on plain compute_103): 8 warps, warp tile 64x64
// ===========================================================================
__device__ __forceinline__ void ldsm_x4(uint32_t* r, uint32_t a) {
    asm volatile("ldmatrix.sync.aligned.m8n8.x4.shared.b16 {%0,%1,%2,%3}, [%4];"
                 : "=r"(r[0]), "=r"(r[1]), "=r"(r[2]), "=r"(r[3]) : "r"(a));
}
__device__ __forceinline__ void mma16816(float* d, const uint32_t* a, const uint32_t* b) {
    asm volatile("mma.sync.aligned.m16n8k16.row.col.f32.f16.f16.f32 "
                 "{%0,%1,%2,%3}, {%4,%5,%6,%7}, {%8,%9}, {%0,%1,%2,%3};"
                 : "+f"(d[0]), "+f"(d[1]), "+f"(d[2]), "+f"(d[3])
                 : "r"(a[0]), "r"(a[1]), "r"(a[2]), "r"(a[3]), "r"(b[0]), "r"(b[1]));
}

__device__ __forceinline__ void mmasync_mainloop(uint32_t su,
    const __half* __restrict__ A, size_t as,
    const __half* __restrict__ Bh, const __half* __restrict__ Bl, size_t bs,
    int K, int tid, float acc[4][8][4])
{
    const int nk = K / 64;
    const int wid = tid >> 5, lane = tid & 31;
    const int wm = wid >> 1, wn = wid & 1;

    stage_load_async(su, A, as, Bh, Bl, bs, 0, tid);
    CP_COMMIT();
    if (nk > 1) {
        stage_load_async(su + STAGE_BYTES, A, as, Bh, Bl, bs, 64, tid);
        CP_COMMIT();
    }

    for (int ks = 0; ks < nk; ks++) {
        if (ks + 2 < nk) {
            stage_load_async(su + ((ks + 2) % 3) * STAGE_BYTES,
                             A, as, Bh, Bl, bs, (ks + 2) * 64, tid);
            CP_COMMIT();
            cp_wait2();
        } else if (ks + 1 < nk) {
            cp_wait1();
        } else {
            cp_wait0();
        }
        __syncthreads();

        uint32_t sA = su + (ks % 3) * STAGE_BYTES;
        uint32_t sB = sA + OFF_BHI;

        #pragma unroll
        for (int k16 = 0; k16 < 64; k16 += 16) {
            // B fragments: warp covers n in [wn*64, wn*64+64)
            uint32_t bh[8][2], bl[8][2];
            #pragma unroll
            for (int jj = 0; jj < 4; jj++) {
                int n = wn * 64 + jj * 16 + (lane & 7) + ((lane >> 3) & 1) * 8;
                int k = k16 + (lane >> 4) * 8;
                uint32_t addr = sB + SMEM_SWIZZLE_128B((uint32_t)(n * 128 + k * 2));
                uint32_t t[4];
                ldsm_x4(t, addr);
                bh[2 * jj][0] = t[0]; bh[2 * jj + 1][0] = t[1];
                bh[2 * jj][1] = t[2]; bh[2 * jj + 1][1] = t[3];
                ldsm_x4(t, addr + 16384);   // B_LO - B_HI
                bl[2 * jj][0] = t[0]; bl[2 * jj + 1][0] = t[1];
                bl[2 * jj][1] = t[2]; bl[2 * jj + 1][1] = t[3];
            }
            // A fragments + MMA: warp covers m in [wm*64, wm*64+64)
            #pragma unroll
            for (int i = 0; i < 4; i++) {
                int m = wm * 64 + i * 16 + (lane & 15);
                int k = k16 + (lane >> 4) * 8;
                uint32_t addr = sA + SMEM_SWIZZLE_128B((uint32_t)(m * 128 + k * 2));
                uint32_t ah[4];
                ldsm_x4(ah, addr);
                #pragma unroll
                for (int j = 0; j < 8; j++) {
                    mma16816(acc[i][j], ah, bh[j]);
                    mma16816(acc[i][j], ah, bl[j]);
                }
            }
        }
        __syncthreads();
    }
}
#endif  // !USE_TC

// ---------------------------------------------------------------------------
// Prep kernels
// ---------------------------------------------------------------------------
__device__ __forceinline__ float blk_sum256(float v) {
    __shared__ float red[8];
    #pragma unroll
    for (int o = 16; o > 0; o >>= 1) v += __shfl_xor_sync(0xffffffffu, v, o);
    int w = threadIdx.x >> 5, l = threadIdx.x & 31;
    if (l == 0) red[w] = v;
    __syncthreads();
    if (threadIdx.x < 32) {
        float r = (threadIdx.x < 8) ? red[threadIdx.x] : 0.0f;
        #pragma unroll
        for (int o = 4; o > 0; o >>= 1) r += __shfl_xor_sync(0xffffffffu, r, o);
        if (threadIdx.x == 0) red[0] = r;
    }
    __syncthreads();
    float out = red[0];
    __syncthreads();
    return out;
}

__global__ void ln_split_kernel(const float* __restrict__ tokens) {
    int row = blockIdx.x, tid = threadIdx.x;
    const float* x = tokens + (size_t)row * H;
    float v0 = x[tid], v1 = x[tid + 256];
    float mu = blk_sum256(v0 + v1) * (1.0f / H);
    float d0 = v0 - mu, d1 = v1 - mu;
    float rs = rsqrtf(blk_sum256(d0 * d0 + d1 * d1) * (1.0f / H) + EPS);
    size_t base = (size_t)row * H;
    g_x[base + tid]       = __float2half_rn(d0 * rs);
    g_x[base + tid + 256] = __float2half_rn(d1 * rs);
}

__global__ void w1t_kernel(const float* __restrict__ W1, const float* __restrict__ ln_g) {
    __shared__ float ts[64][65];
    int e = blockIdx.z, f0 = blockIdx.x * 64, h0 = blockIdx.y * 64, tid = threadIdx.x;
    #pragma unroll
    for (int i = 0; i < 16; i++) {
        int idx = tid + i * 256, r = idx >> 6, c = idx & 63;
        ts[r][c] = W1[((size_t)e * H + h0 + r) * F + f0 + c];
    }
    __syncthreads();
    #pragma unroll
    for (int i = 0; i < 16; i++) {
        int idx = tid + i * 256, r = idx >> 6, c = idx & 63;
        float w = ts[c][r] * ln_g[e * H + h0 + c];
        __half hi = __float2half_rn(w);
        size_t o = ((size_t)e * F + f0 + r) * H + h0 + c;
        g_w1thi[o] = hi;
        g_w1tlo[o] = __float2half_rn(w - __half2float(hi));
    }
}

__global__ void w2t_kernel(const float* __restrict__ W2) {
    __shared__ float ts[64][65];
    int e = blockIdx.z, h0 = blockIdx.x * 64, f0 = blockIdx.y * 64, tid = threadIdx.x;
    #pragma unroll
    for (int i = 0; i < 16; i++) {
        int idx = tid + i * 256, r = idx >> 6, c = idx & 63;
        ts[r][c] = W2[((size_t)e * F + f0 + r) * H + h0 + c];
    }
    __syncthreads();
    #pragma unroll
    for (int i = 0; i < 16; i++) {
        int idx = tid + i * 256, r = idx >> 6, c = idx & 63;
        float w = ts[c][r];
        __half hi = __float2half_rn(w);
        size_t o = ((size_t)e * H + h0 + r) * F + f0 + c;
        g_w2thi[o] = hi;
        g_w2tlo[o] = __float2half_rn(w - __half2float(hi));
    }
}

// b1' = ln_b @ W1 + b1, two-phase deterministic (h split into 8 slabs of 64)
__global__ void b1p_part_kernel(const float* __restrict__ W1, const float* __restrict__ ln_b) {
    int e = blockIdx.y, hs = blockIdx.z * 64;
    int f = blockIdx.x * 256 + threadIdx.x;
    const float* w = W1 + ((size_t)e * H + hs) * F + f;
    const float* b = ln_b + e * H + hs;
    float acc = 0.0f;
    #pragma unroll 8
    for (int h = 0; h < 64; h++) acc += b[h] * w[(size_t)h * F];
    g_b1part[blockIdx.z][e * F + f] = acc;
}
__global__ void b1p_reduce_kernel(const float* __restrict__ b1) {
    int i = blockIdx.x * 256 + threadIdx.x;
    float acc = b1[i];
    #pragma unroll
    for (int s = 0; s < 8; s++) acc += g_b1part[s][i];
    g_b1p[i] = acc;
}

// ---------------------------------------------------------------------------
// GEMM1: h = gelu(xhat @ (g*W1) + b1')    grid: (T/256, E, F/128)
// ---------------------------------------------------------------------------
__global__ void __launch_bounds__(256, 1) gemm1_kernel() {
    extern __shared__ char smem[];
    uint32_t su = smem_to_u32(smem);
    const int tid = threadIdx.x, wid = tid >> 5, lane = tid & 31;
    const int e = blockIdx.y;
    const int tok0 = blockIdx.x * 256;
    const int fc = blockIdx.z * 128;

    const __half* A  = g_x + (size_t)tok0 * H;
    const __half* Bh = g_w1thi + ((size_t)e * F + fc) * H;
    const __half* Bl = g_w1tlo + ((size_t)e * F + fc) * H;

#if USE_TC
    uint32_t tmem = tc_prologue(su, tid, wid);
    tc_mainloop(su, tmem, A, H, Bh, Bl, H, H, tid, wid);

    const int row = (wid >= 4 ? 128 : 0) + (wid & 3) * 32 + lane;
    const uint32_t dbase = tmem + (wid >= 4 ? 128 : 0);
    const size_t hrow = ((size_t)e * MAX_T + tok0 + row) * F;
    for (int cb = 0; cb < 128; cb += 32) {
        uint32_t r[32];
        TCGEN05_LD_X32(r, dbase + cb);
        TCGEN05_WAIT_LD();
        int fglob = fc + cb;
        __half h8[8];
        #pragma unroll
        for (int j = 0; j < 32; j++) {
            float v = __uint_as_float(r[j]) + g_b1p[e * F + fglob + j];
            h8[j & 7] = __float2half_rn(gelu_erf(v));
            if ((j & 7) == 7)
                *reinterpret_cast<uint4*>(&g_h[hrow + fglob + (j & ~7)]) =
                    *reinterpret_cast<uint4*>(h8);
        }
    }
    tc_release(su, tmem, tid, wid);
#else
    float acc[4][8][4];
    #pragma unroll
    for (int i = 0; i < 4; i++)
        #pragma unroll
        for (int j = 0; j < 8; j++)
            #pragma unroll
            for (int q = 0; q < 4; q++) acc[i][j][q] = 0.0f;

    mmasync_mainloop(su, A, H, Bh, Bl, H, H, tid, acc);

    const int wm = wid >> 1, wn = wid & 1;
    const float* b1pp = g_b1p + e * F;
    #pragma unroll
    for (int i = 0; i < 4; i++) {
        #pragma unroll
        for (int j = 0; j < 8; j++) {
            int fj = fc + wn * 64 + j * 8 + (lane & 3) * 2;
            int r0 = tok0 + wm * 64 + i * 16 + (lane >> 2);
            #pragma unroll
            for (int half = 0; half < 2; half++) {
                int rr = r0 + half * 8;
                float v0 = acc[i][j][2 * half + 0] + b1pp[fj];
                float v1 = acc[i][j][2 * half + 1] + b1pp[fj + 1];
                __half h0 = __float2half_rn(gelu_erf(v0));
                __half h1 = __float2half_rn(gelu_erf(v1));
                uint32_t ph = ((uint32_t)__half_as_ushort(h1) << 16) | __half_as_ushort(h0);
                *reinterpret_cast<uint32_t*>(&g_h[((size_t)e * MAX_T + rr) * F + fj]) = ph;
            }
        }
    }
#endif
}

// ---------------------------------------------------------------------------
// GEMM2: out = h @ W2 + b2     grid: (T/256, E, H/128)
// ---------------------------------------------------------------------------
__global__ void __launch_bounds__(256, 1) gemm2_kernel(const float* __restrict__ b2,
                                                       float* __restrict__ out) {
    extern __shared__ char smem[];
    uint32_t su = smem_to_u32(smem);
    const int tid = threadIdx.x, wid = tid >> 5, lane = tid & 31;
    const int e = blockIdx.y;
    const int tok0 = blockIdx.x * 256;
    const int hh0 = blockIdx.z * 128;

    const __half* A  = g_h + ((size_t)e * MAX_T + tok0) * F;
    const __half* Bh = g_w2thi + ((size_t)e * H + hh0) * F;
    const __half* Bl = g_w2tlo + ((size_t)e * H + hh0) * F;

#if USE_TC
    uint32_t tmem = tc_prologue(su, tid, wid);
    tc_mainloop(su, tmem, A, F, Bh, Bl, F, F, tid, wid);

    const int row = (wid >= 4 ? 128 : 0) + (wid & 3) * 32 + lane;
    const uint32_t dbase = tmem + (wid >= 4 ? 128 : 0);
    float* orow = out + (((size_t)(tok0 + row)) * E + e) * H;
    for (int cb = 0; cb < 128; cb += 32) {
        uint32_t r[32];
        TCGEN05_LD_X32(r, dbase + cb);
        TCGEN05_WAIT_LD();
        int hglob = hh0 + cb;
        float v4[4];
        #pragma unroll
        for (int j = 0; j < 32; j++) {
            v4[j & 3] = __uint_as_float(r[j]) + b2[e * H + hglob + j];
            if ((j & 3) == 3)
                *reinterpret_cast<uint4*>(orow + hglob + (j & ~3)) =
                    *reinterpret_cast<uint4*>(v4);
        }
    }
    tc_release(su, tmem, tid, wid);
#else
    float acc[4][8][4];
    #pragma unroll
    for (int i = 0; i < 4; i++)
        #pragma unroll
        for (int j = 0; j < 8; j++)
            #pragma unroll
            for (int q = 0; q < 4; q++) acc[i][j][q] = 0.0f;

    mmasync_mainloop(su, A, F, Bh, Bl, F, F, tid, acc);

    const int wm = wid >> 1, wn = wid & 1;
    const float* b2p = b2 + e * H;
    #pragma unroll
    for (int i = 0; i < 4; i++) {
        #pragma unroll
        for (int j = 0; j < 8; j++) {
            int hj = hh0 + wn * 64 + j * 8 + (lane & 3) * 2;
            int r0 = tok0 + wm * 64 + i * 16 + (lane >> 2);
            float bb0 = b2p[hj], bb1 = b2p[hj + 1];
            #pragma unroll
            for (int half = 0; half < 2; half++) {
                int rr = r0 + half * 8;
                float2 v = make_float2(acc[i][j][2 * half + 0] + bb0,
                                       acc[i][j][2 * half + 1] + bb1);
                *reinterpret_cast<float2*>(out + ((size_t)rr * E + e) * H + hj) = v;
            }
        }
    }
#endif
}

// ---------------------------------------------------------------------------
extern "C" void kernel_launch(void* const* d_in, const int* in_sizes, int n_in,
                              void* d_out, int out_size)
{
    const float* tokens = (const float*)d_in[0];
    const float* ln_g   = (const float*)d_in[1];
    const float* ln_b   = (const float*)d_in[2];
    const float* W1     = (const float*)d_in[3];
    const float* b1     = (const float*)d_in[4];
    const float* W2     = (const float*)d_in[5];
    const float* b2     = (const float*)d_in[6];
    float* out = (float*)d_out;

    int T = in_sizes[0] / H;      // 8192
    int tiles = T / 256;          // 32

    cudaFuncSetAttribute(gemm1_kernel, cudaFuncAttributeMaxDynamicSharedMemorySize, SMEM_BYTES);
    cudaFuncSetAttribute(gemm2_kernel, cudaFuncAttributeMaxDynamicSharedMemorySize, SMEM_BYTES);

    ln_split_kernel<<<T, 256>>>(tokens);
    { dim3 g(F / 64, H / 64, E); w1t_kernel<<<g, 256>>>(W1, ln_g); }
    { dim3 g(H / 64, F / 64, E); w2t_kernel<<<g, 256>>>(W2); }
    { dim3 g(F / 256, E, 8); b1p_part_kernel<<<g, 256>>>(W1, ln_b); }
    b1p_reduce_kernel<<<E * F / 256, 256>>>(b1);
    { dim3 g(tiles, E, F / 128); gemm1_kernel<<<g, 256, SMEM_BYTES>>>(); }
    { dim3 g(tiles, E, H / 128); gemm2_kernel<<<g, 256, SMEM_BYTES>>>(b2, out); }
}

// round 6
// speedup vs baseline: 20.0558x; 1.1634x over previous
#include <cuda_runtime.h>
#include <cuda_fp16.h>
#include <math.h>
#include <stdint.h>

#define H 512
#define F 1024
#define E 16
#define MAX_T 8192
#define EPS 1e-5f

// Per-compile-pass feature detection: tcgen05 only legal on sm_103a-style targets.
#if defined(__CUDA_ARCH__) && (defined(__CUDA_ARCH_FEAT_SM103_ALL) || \
    defined(__CUDA_ARCH_FEAT_SM100_ALL) || defined(__CUDA_ARCH_SPECIFIC__) || \
    defined(__CUDA_ARCH_FAMILY_SPECIFIC__))
#define USE_TC 1
#else
#define USE_TC 0
#endif

// ---------------------------------------------------------------------------
// Scratch (no allocation allowed -> device globals)
// Everything single fp16: activations AND weights (error budget ~5e-4 < 1e-3).
// ---------------------------------------------------------------------------
__device__ __align__(128) __half g_x[(size_t)MAX_T * H];
__device__ __align__(128) __half g_w1t[(size_t)E * F * H];   // [e][f][h]
__device__ __align__(128) __half g_w2t[(size_t)E * H * F];   // [e][h][f]
__device__ float g_b1part[8][E * F];
__device__ float g_b1p[E * F];
__device__ __align__(128) __half g_h[(size_t)E * MAX_T * F]; // [e][t][f]

// ---------------------------------------------------------------------------
// Common helpers
// ---------------------------------------------------------------------------
__device__ __forceinline__ uint32_t smem_to_u32(const void* p) {
    uint32_t a;
    asm("{ .reg .u64 t; cvta.to.shared.u64 t, %1; cvt.u32.u64 %0, t; }" : "=r"(a) : "l"(p));
    return a;
}
#define SMEM_SWIZZLE_128B(o) ((o) ^ (((o) >> 3) & 0x70))

__device__ __forceinline__ void cpa16(uint32_t dst, const void* src) {
    asm volatile("cp.async.cg.shared.global [%0], [%1], 16;" :: "r"(dst), "l"(src));
}
#define CP_COMMIT() asm volatile("cp.async.commit_group;" ::: "memory")
__device__ __forceinline__ void cp_wait2() { asm volatile("cp.async.wait_group 2;" ::: "memory"); }
__device__ __forceinline__ void cp_wait1() { asm volatile("cp.async.wait_group 1;" ::: "memory"); }
__device__ __forceinline__ void cp_wait0() { asm volatile("cp.async.wait_group 0;" ::: "memory"); }

__device__ __forceinline__ float gelu_erf(float x) {
    return 0.5f * x * (1.0f + erff(x * 0.70710678118654752f));
}

// Tile geometry: M=256 tokens, N=128, K-step=64
// SMEM stage: A(32K) B(16K) = 48KB; 3 stages = 144KB
#define OFF_B 32768
#define STAGE_BYTES 49152
#define S_CTRL 147456            // tmem ptr (tc path)
#define S_MBAR 147472
#define SMEM_BYTES 147488

// Load one stage (A: 256x64 fp16, B: 128x64 fp16) with SW128 swizzle
__device__ __forceinline__ void stage_load_async(uint32_t sbase,
    const __half* __restrict__ A, size_t as,
    const __half* __restrict__ B, size_t bs,
    int k0, int tid)
{
    #pragma unroll
    for (int it = 0; it < 8; it++) {           // A: 256 rows x 8 chunks
        int v = tid + it * 256;
        int r = v >> 3, c = v & 7;
        uint32_t off = SMEM_SWIZZLE_128B((uint32_t)(r * 128 + c * 16));
        cpa16(sbase + off, A + (size_t)r * as + k0 + c * 8);
    }
    #pragma unroll
    for (int it = 0; it < 4; it++) {           // B: 128 rows x 8 chunks
        int v = tid + it * 256;
        int r = v >> 3, c = v & 7;
        uint32_t off = SMEM_SWIZZLE_128B((uint32_t)(r * 128 + c * 16));
        cpa16(sbase + OFF_B + off, B + (size_t)r * bs + k0 + c * 8);
    }
}

// ===========================================================================
#if USE_TC
// tcgen05 path: two M=128 MMAs per k-chunk into 2x128 TMEM cols
// ===========================================================================
__device__ __forceinline__ uint32_t elect_one_pred() {
    uint32_t pred;
    asm volatile("{\n\t.reg .pred p;\n\telect.sync _|p, 0xFFFFFFFF;\n\t"
                 "selp.b32 %0, 1, 0, p;\n\t}" : "=r"(pred));
    return pred;
}
static constexpr uint64_t SMEM_DESC_BASE_SW128 =
    (uint64_t(2) << 61) | (uint64_t(1) << 46) | (uint64_t(64) << 32) | (uint64_t(1) << 16);
#define MAKE_SMEM_DESC(a) (SMEM_DESC_BASE_SW128 | ((uint64_t)((a) >> 4) & 0x3FFF))

#define TCGEN05_ALLOC(sr, n) \
    asm volatile("tcgen05.alloc.cta_group::1.sync.aligned.shared::cta.b32 [%0], %1;" \
                 :: "r"((uint32_t)(sr)), "r"((uint32_t)(n)) : "memory")
#define TCGEN05_DEALLOC(t, n) \
    asm volatile("tcgen05.dealloc.cta_group::1.sync.aligned.b32 %0, %1;" :: "r"(t), "r"(n))
#define TCGEN05_RELINQUISH() \
    asm volatile("tcgen05.relinquish_alloc_permit.cta_group::1.sync.aligned;")
#define TCGEN05_COMMIT(m) \
    asm volatile("tcgen05.commit.cta_group::1.mbarrier::arrive::one.shared::cluster.b64 [%0];" \
                 :: "r"((uint32_t)(m)) : "memory")
#define TCGEN05_FENCE_AFTER() asm volatile("tcgen05.fence::after_thread_sync;" ::: "memory")
#define TCGEN05_WAIT_LD() asm volatile("tcgen05.wait::ld.sync.aligned;" ::: "memory")
#define MBARRIER_INIT(m, c) \
    asm volatile("mbarrier.init.shared.b64 [%0], %1;" :: "r"((uint32_t)(m)), "r"((uint32_t)(c)) : "memory")
#define MBARRIER_INVAL(m) \
    asm volatile("mbarrier.inval.shared.b64 [%0];" :: "r"((uint32_t)(m)) : "memory")

#define MBARRIER_WAIT_PARITY(mb, ph) do {                                         \
    uint32_t _m = (uint32_t)(mb), _p = (uint32_t)(ph), _d;                         \
    asm volatile("{\n\t.reg .pred p;\n\t"                                          \
        "mbarrier.try_wait.parity.acquire.cta.shared::cta.b64 p, [%1], %2;\n\t"    \
        "selp.b32 %0, 1, 0, p;\n\t}" : "=r"(_d) : "r"(_m), "r"(_p) : "memory");    \
    if (!_d) {                                                                     \
        asm volatile("{\n\t.reg .pred P1;\n\t"                                     \
            "WL_%=:\n\t"                                                           \
            "mbarrier.try_wait.parity.acquire.cta.shared::cta.b64 P1, [%0], %1, 0x989680;\n\t" \
            "@P1 bra.uni WD_%=;\n\t"                                               \
            "bra.uni WL_%=;\n\t"                                                   \
            "WD_%=:\n\t}" :: "r"(_m), "r"(_p) : "memory");                         \
    }                                                                              \
} while (0)

#define TCGEN05_LD_X32(r, a)                                                       \
    asm volatile("tcgen05.ld.sync.aligned.32x32b.x32.b32 "                         \
        "{%0, %1, %2, %3, %4, %5, %6, %7, %8, %9, %10, %11, %12, %13, %14, %15, "  \
        " %16, %17, %18, %19, %20, %21, %22, %23, %24, %25, %26, %27, %28, %29, %30, %31}, [%32];" \
        : "=r"((r)[0]), "=r"((r)[1]), "=r"((r)[2]), "=r"((r)[3]),                  \
          "=r"((r)[4]), "=r"((r)[5]), "=r"((r)[6]), "=r"((r)[7]),                  \
          "=r"((r)[8]), "=r"((r)[9]), "=r"((r)[10]), "=r"((r)[11]),                \
          "=r"((r)[12]), "=r"((r)[13]), "=r"((r)[14]), "=r"((r)[15]),              \
          "=r"((r)[16]), "=r"((r)[17]), "=r"((r)[18]), "=r"((r)[19]),              \
          "=r"((r)[20]), "=r"((r)[21]), "=r"((r)[22]), "=r"((r)[23]),              \
          "=r"((r)[24]), "=r"((r)[25]), "=r"((r)[26]), "=r"((r)[27]),              \
          "=r"((r)[28]), "=r"((r)[29]), "=r"((r)[30]), "=r"((r)[31])               \
        : "r"(a))

__device__ __forceinline__ void mma_f16_ss(uint32_t d_tmem, uint64_t a_desc,
                                           uint64_t b_desc, uint32_t idesc, bool acc) {
    uint32_t en = acc ? 1u : 0u;
    asm volatile("{\n\t.reg .pred p;\n\tsetp.ne.u32 p, %4, 0;\n\t"
                 "tcgen05.mma.cta_group::1.kind::f16 [%0], %1, %2, %3, p;\n\t}"
                 :: "r"(d_tmem), "l"(a_desc), "l"(b_desc), "r"(idesc), "r"(en)
                 : "memory");
}
// dtype=F32, atype=btype=F16(0), N=128, M=128, K-major
#define MMA_IDESC ((1u << 4) | ((128u / 8u) << 17) | ((128u / 16u) << 24))

__device__ __forceinline__ uint32_t tc_prologue(uint32_t su, int tid, int wid) {
    if (wid == 0) TCGEN05_ALLOC(su + S_CTRL, 256);
    if (tid == 128) MBARRIER_INIT(su + S_MBAR, 1);
    __syncthreads();
    uint32_t tmem;
    asm volatile("ld.shared.b32 %0, [%1];" : "=r"(tmem) : "r"(su + S_CTRL));
    if (wid == 0) TCGEN05_RELINQUISH();
    __syncthreads();
    return tmem;
}

__device__ __forceinline__ void tc_mainloop(uint32_t su, uint32_t tmem,
    const __half* __restrict__ A, size_t as,
    const __half* __restrict__ B, size_t bs,
    int K, int tid, int wid)
{
    const int nk = K / 64;
    stage_load_async(su, A, as, B, bs, 0, tid);
    CP_COMMIT();
    if (nk > 1) {
        stage_load_async(su + STAGE_BYTES, A, as, B, bs, 64, tid);
        CP_COMMIT();
    }
    for (int ks = 0; ks < nk; ks++) {
        if (ks > 0) MBARRIER_WAIT_PARITY(su + S_MBAR, (ks - 1) & 1);
        if (ks + 2 < nk) {
            stage_load_async(su + ((ks + 2) % 3) * STAGE_BYTES,
                             A, as, B, bs, (ks + 2) * 64, tid);
            CP_COMMIT();
            cp_wait2();
        } else if (ks + 1 < nk) {
            cp_wait1();
        } else {
            cp_wait0();
        }
        __syncthreads();
        if (wid == 0 && elect_one_pred()) {
            asm volatile("fence.proxy.async.shared::cta;" ::: "memory");
            uint32_t sb = su + (ks % 3) * STAGE_BYTES;
            #pragma unroll
            for (int mh = 0; mh < 2; mh++) {       // M halves (rows 0-127 / 128-255)
                uint64_t dA = MAKE_SMEM_DESC(sb + mh * 16384);
                uint64_t dB = MAKE_SMEM_DESC(sb + OFF_B);
                uint32_t dt = tmem + mh * 128;
                #pragma unroll
                for (int kk = 0; kk < 4; kk++) {
                    bool acc0 = (ks > 0) || (kk > 0);
                    mma_f16_ss(dt, dA + kk * 2, dB + kk * 2, MMA_IDESC, acc0);
                }
            }
            TCGEN05_COMMIT(su + S_MBAR);
        }
        __syncthreads();
    }
    MBARRIER_WAIT_PARITY(su + S_MBAR, (nk - 1) & 1);
    TCGEN05_FENCE_AFTER();
}

__device__ __forceinline__ void tc_release(uint32_t su, uint32_t tmem, int tid, int wid) {
    __syncthreads();
    if (tid == 128) MBARRIER_INVAL(su + S_MBAR);
    __syncthreads();
    if (wid == 0) TCGEN05_DEALLOC(tmem, 256);
}
#endif  // USE_TC

// ===========================================================================
#if !USE_TC
// mma.sync fallback (legal on plain compute_103): 8 warps, warp tile 64x64
// ===========================================================================
__device__ __forceinline__ void ldsm_x4(uint32_t* r, uint32_t a) {
    asm volatile("ldmatrix.sync.aligned.m8n8.x4.shared.b16 {%0,%1,%2,%3}, [%4];"
                 : "=r"(r[0]), "=r"(r[1]), "=r"(r[2]), "=r"(r[3]) : "r"(a));
}
__device__ __forceinline__ void mma16816(float* d, const uint32_t* a, const uint32_t* b) {
    asm volatile("mma.sync.aligned.m16n8k16.row.col.f32.f16.f16.f32 "
                 "{%0,%1,%2,%3}, {%4,%5,%6,%7}, {%8,%9}, {%0,%1,%2,%3};"
                 : "+f"(d[0]), "+f"(d[1]), "+f"(d[2]), "+f"(d[3])
                 : "r"(a[0]), "r"(a[1]), "r"(a[2]), "r"(a[3]), "r"(b[0]), "r"(b[1]));
}

__device__ __forceinline__ void mmasync_mainloop(uint32_t su,
    const __half* __restrict__ A, size_t as,
    const __half* __restrict__ B, size_t bs,
    int K, int tid, float acc[4][8][4])
{
    const int nk = K / 64;
    const int wid = tid >> 5, lane = tid & 31;
    const int wm = wid >> 1, wn = wid & 1;

    stage_load_async(su, A, as, B, bs, 0, tid);
    CP_COMMIT();
    if (nk > 1) {
        stage_load_async(su + STAGE_BYTES, A, as, B, bs, 64, tid);
        CP_COMMIT();
    }

    for (int ks = 0; ks < nk; ks++) {
        if (ks + 2 < nk) {
            stage_load_async(su + ((ks + 2) % 3) * STAGE_BYTES,
                             A, as, B, bs, (ks + 2) * 64, tid);
            CP_COMMIT();
            cp_wait2();
        } else if (ks + 1 < nk) {
            cp_wait1();
        } else {
            cp_wait0();
        }
        __syncthreads();

        uint32_t sA = su + (ks % 3) * STAGE_BYTES;
        uint32_t sB = sA + OFF_B;

        #pragma unroll
        for (int k16 = 0; k16 < 64; k16 += 16) {
            // B fragments: warp covers n in [wn*64, wn*64+64)
            uint32_t bh[8][2];
            #pragma unroll
            for (int jj = 0; jj < 4; jj++) {
                int n = wn * 64 + jj * 16 + (lane & 7) + ((lane >> 3) & 1) * 8;
                int k = k16 + (lane >> 4) * 8;
                uint32_t addr = sB + SMEM_SWIZZLE_128B((uint32_t)(n * 128 + k * 2));
                uint32_t t[4];
                ldsm_x4(t, addr);
                bh[2 * jj][0] = t[0]; bh[2 * jj + 1][0] = t[1];
                bh[2 * jj][1] = t[2]; bh[2 * jj + 1][1] = t[3];
            }
            // A fragments + MMA: warp covers m in [wm*64, wm*64+64)
            #pragma unroll
            for (int i = 0; i < 4; i++) {
                int m = wm * 64 + i * 16 + (lane & 15);
                int k = k16 + (lane >> 4) * 8;
                uint32_t addr = sA + SMEM_SWIZZLE_128B((uint32_t)(m * 128 + k * 2));
                uint32_t ah[4];
                ldsm_x4(ah, addr);
                #pragma unroll
                for (int j = 0; j < 8; j++)
                    mma16816(acc[i][j], ah, bh[j]);
            }
        }
        __syncthreads();
    }
}
#endif  // !USE_TC

// ---------------------------------------------------------------------------
// Prep kernels
// ---------------------------------------------------------------------------
__device__ __forceinline__ float blk_sum256(float v) {
    __shared__ float red[8];
    #pragma unroll
    for (int o = 16; o > 0; o >>= 1) v += __shfl_xor_sync(0xffffffffu, v, o);
    int w = threadIdx.x >> 5, l = threadIdx.x & 31;
    if (l == 0) red[w] = v;
    __syncthreads();
    if (threadIdx.x < 32) {
        float r = (threadIdx.x < 8) ? red[threadIdx.x] : 0.0f;
        #pragma unroll
        for (int o = 4; o > 0; o >>= 1) r += __shfl_xor_sync(0xffffffffu, r, o);
        if (threadIdx.x == 0) red[0] = r;
    }
    __syncthreads();
    float out = red[0];
    __syncthreads();
    return out;
}

__global__ void ln_split_kernel(const float* __restrict__ tokens) {
    int row = blockIdx.x, tid = threadIdx.x;
    const float* x = tokens + (size_t)row * H;
    float v0 = x[tid], v1 = x[tid + 256];
    float mu = blk_sum256(v0 + v1) * (1.0f / H);
    float d0 = v0 - mu, d1 = v1 - mu;
    float rs = rsqrtf(blk_sum256(d0 * d0 + d1 * d1) * (1.0f / H) + EPS);
    size_t base = (size_t)row * H;
    g_x[base + tid]       = __float2half_rn(d0 * rs);
    g_x[base + tid + 256] = __float2half_rn(d1 * rs);
}

__global__ void w1t_kernel(const float* __restrict__ W1, const float* __restrict__ ln_g) {
    __shared__ float ts[64][65];
    int e = blockIdx.z, f0 = blockIdx.x * 64, h0 = blockIdx.y * 64, tid = threadIdx.x;
    #pragma unroll
    for (int i = 0; i < 16; i++) {
        int idx = tid + i * 256, r = idx >> 6, c = idx & 63;
        ts[r][c] = W1[((size_t)e * H + h0 + r) * F + f0 + c];
    }
    __syncthreads();
    #pragma unroll
    for (int i = 0; i < 16; i++) {
        int idx = tid + i * 256, r = idx >> 6, c = idx & 63;
        float w = ts[c][r] * ln_g[e * H + h0 + c];
        g_w1t[((size_t)e * F + f0 + r) * H + h0 + c] = __float2half_rn(w);
    }
}

__global__ void w2t_kernel(const float* __restrict__ W2) {
    __shared__ float ts[64][65];
    int e = blockIdx.z, h0 = blockIdx.x * 64, f0 = blockIdx.y * 64, tid = threadIdx.x;
    #pragma unroll
    for (int i = 0; i < 16; i++) {
        int idx = tid + i * 256, r = idx >> 6, c = idx & 63;
        ts[r][c] = W2[((size_t)e * F + f0 + r) * H + h0 + c];
    }
    __syncthreads();
    #pragma unroll
    for (int i = 0; i < 16; i++) {
        int idx = tid + i * 256, r = idx >> 6, c = idx & 63;
        g_w2t[((size_t)e * H + h0 + r) * F + f0 + c] = __float2half_rn(ts[c][r]);
    }
}

// b1' = ln_b @ W1 + b1, two-phase deterministic (h split into 8 slabs of 64)
__global__ void b1p_part_kernel(const float* __restrict__ W1, const float* __restrict__ ln_b) {
    int e = blockIdx.y, hs = blockIdx.z * 64;
    int f = blockIdx.x * 256 + threadIdx.x;
    const float* w = W1 + ((size_t)e * H + hs) * F + f;
    const float* b = ln_b + e * H + hs;
    float acc = 0.0f;
    #pragma unroll 8
    for (int h = 0; h < 64; h++) acc += b[h] * w[(size_t)h * F];
    g_b1part[blockIdx.z][e * F + f] = acc;
}
__global__ void b1p_reduce_kernel(const float* __restrict__ b1) {
    int i = blockIdx.x * 256 + threadIdx.x;
    float acc = b1[i];
    #pragma unroll
    for (int s = 0; s < 8; s++) acc += g_b1part[s][i];
    g_b1p[i] = acc;
}

// ---------------------------------------------------------------------------
// GEMM1: h = gelu(xhat @ (g*W1) + b1')    grid: (T/256, E, F/128)
// ---------------------------------------------------------------------------
__global__ void __launch_bounds__(256, 1) gemm1_kernel() {
    extern __shared__ char smem[];
    uint32_t su = smem_to_u32(smem);
    const int tid = threadIdx.x, wid = tid >> 5, lane = tid & 31;
    const int e = blockIdx.y;
    const int tok0 = blockIdx.x * 256;
    const int fc = blockIdx.z * 128;

    const __half* A = g_x + (size_t)tok0 * H;
    const __half* B = g_w1t + ((size_t)e * F + fc) * H;

#if USE_TC
    uint32_t tmem = tc_prologue(su, tid, wid);
    tc_mainloop(su, tmem, A, H, B, H, H, tid, wid);

    const int row = (wid >= 4 ? 128 : 0) + (wid & 3) * 32 + lane;
    const uint32_t dbase = tmem + (wid >= 4 ? 128 : 0);
    const size_t hrow = ((size_t)e * MAX_T + tok0 + row) * F;
    for (int cb = 0; cb < 128; cb += 32) {
        uint32_t r[32];
        TCGEN05_LD_X32(r, dbase + cb);
        TCGEN05_WAIT_LD();
        int fglob = fc + cb;
        __half h8[8];
        #pragma unroll
        for (int j = 0; j < 32; j++) {
            float v = __uint_as_float(r[j]) + g_b1p[e * F + fglob + j];
            h8[j & 7] = __float2half_rn(gelu_erf(v));
            if ((j & 7) == 7)
                *reinterpret_cast<uint4*>(&g_h[hrow + fglob + (j & ~7)]) =
                    *reinterpret_cast<uint4*>(h8);
        }
    }
    tc_release(su, tmem, tid, wid);
#else
    float acc[4][8][4];
    #pragma unroll
    for (int i = 0; i < 4; i++)
        #pragma unroll
        for (int j = 0; j < 8; j++)
            #pragma unroll
            for (int q = 0; q < 4; q++) acc[i][j][q] = 0.0f;

    mmasync_mainloop(su, A, H, B, H, H, tid, acc);

    const int wm = wid >> 1, wn = wid & 1;
    const float* b1pp = g_b1p + e * F;
    #pragma unroll
    for (int i = 0; i < 4; i++) {
        #pragma unroll
        for (int j = 0; j < 8; j++) {
            int fj = fc + wn * 64 + j * 8 + (lane & 3) * 2;
            int r0 = tok0 + wm * 64 + i * 16 + (lane >> 2);
            #pragma unroll
            for (int half = 0; half < 2; half++) {
                int rr = r0 + half * 8;
                float v0 = acc[i][j][2 * half + 0] + b1pp[fj];
                float v1 = acc[i][j][2 * half + 1] + b1pp[fj + 1];
                __half h0 = __float2half_rn(gelu_erf(v0));
                __half h1 = __float2half_rn(gelu_erf(v1));
                uint32_t ph = ((uint32_t)__half_as_ushort(h1) << 16) | __half_as_ushort(h0);
                *reinterpret_cast<uint32_t*>(&g_h[((size_t)e * MAX_T + rr) * F + fj]) = ph;
            }
        }
    }
#endif
}

// ---------------------------------------------------------------------------
// GEMM2: out = h @ W2 + b2     grid: (T/256, E, H/128)
// ---------------------------------------------------------------------------
__global__ void __launch_bounds__(256, 1) gemm2_kernel(const float* __restrict__ b2,
                                                       float* __restrict__ out) {
    extern __shared__ char smem[];
    uint32_t su = smem_to_u32(smem);
    const int tid = threadIdx.x, wid = tid >> 5, lane = tid & 31;
    const int e = blockIdx.y;
    const int tok0 = blockIdx.x * 256;
    const int hh0 = blockIdx.z * 128;

    const __half* A = g_h + ((size_t)e * MAX_T + tok0) * F;
    const __half* B = g_w2t + ((size_t)e * H + hh0) * F;

#if USE_TC
    uint32_t tmem = tc_prologue(su, tid, wid);
    tc_mainloop(su, tmem, A, F, B, F, F, tid, wid);

    const int row = (wid >= 4 ? 128 : 0) + (wid & 3) * 32 + lane;
    const uint32_t dbase = tmem + (wid >= 4 ? 128 : 0);
    float* orow = out + (((size_t)(tok0 + row)) * E + e) * H;
    for (int cb = 0; cb < 128; cb += 32) {
        uint32_t r[32];
        TCGEN05_LD_X32(r, dbase + cb);
        TCGEN05_WAIT_LD();
        int hglob = hh0 + cb;
        float v4[4];
        #pragma unroll
        for (int j = 0; j < 32; j++) {
            v4[j & 3] = __uint_as_float(r[j]) + b2[e * H + hglob + j];
            if ((j & 3) == 3)
                *reinterpret_cast<uint4*>(orow + hglob + (j & ~3)) =
                    *reinterpret_cast<uint4*>(v4);
        }
    }
    tc_release(su, tmem, tid, wid);
#else
    float acc[4][8][4];
    #pragma unroll
    for (int i = 0; i < 4; i++)
        #pragma unroll
        for (int j = 0; j < 8; j++)
            #pragma unroll
            for (int q = 0; q < 4; q++) acc[i][j][q] = 0.0f;

    mmasync_mainloop(su, A, F, B, F, F, tid, acc);

    const int wm = wid >> 1, wn = wid & 1;
    const float* b2p = b2 + e * H;
    #pragma unroll
    for (int i = 0; i < 4; i++) {
        #pragma unroll
        for (int j = 0; j < 8; j++) {
            int hj = hh0 + wn * 64 + j * 8 + (lane & 3) * 2;
            int r0 = tok0 + wm * 64 + i * 16 + (lane >> 2);
            float bb0 = b2p[hj], bb1 = b2p[hj + 1];
            #pragma unroll
            for (int half = 0; half < 2; half++) {
                int rr = r0 + half * 8;
                float2 v = make_float2(acc[i][j][2 * half + 0] + bb0,
                                       acc[i][j][2 * half + 1] + bb1);
                *reinterpret_cast<float2*>(out + ((size_t)rr * E + e) * H + hj) = v;
            }
        }
    }
#endif
}

// ---------------------------------------------------------------------------
extern "C" void kernel_launch(void* const* d_in, const int* in_sizes, int n_in,
                              void* d_out, int out_size)
{
    const float* tokens = (const float*)d_in[0];
    const float* ln_g   = (const float*)d_in[1];
    const float* ln_b   = (const float*)d_in[2];
    const float* W1     = (const float*)d_in[3];
    const float* b1     = (const float*)d_in[4];
    const float* W2     = (const float*)d_in[5];
    const float* b2     = (const float*)d_in[6];
    float* out = (float*)d_out;

    int T = in_sizes[0] / H;      // 8192
    int tiles = T / 256;          // 32

    cudaFuncSetAttribute(gemm1_kernel, cudaFuncAttributeMaxDynamicSharedMemorySize, SMEM_BYTES);
    cudaFuncSetAttribute(gemm2_kernel, cudaFuncAttributeMaxDynamicSharedMemorySize, SMEM_BYTES);

    ln_split_kernel<<<T, 256>>>(tokens);
    { dim3 g(F / 64, H / 64, E); w1t_kernel<<<g, 256>>>(W1, ln_g); }
    { dim3 g(H / 64, F / 64, E); w2t_kernel<<<g, 256>>>(W2); }
    { dim3 g(F / 256, E, 8); b1p_part_kernel<<<g, 256>>>(W1, ln_b); }
    b1p_reduce_kernel<<<E * F / 256, 256>>>(b1);
    { dim3 g(tiles, E, F / 128); gemm1_kernel<<<g, 256, SMEM_BYTES>>>(); }
    { dim3 g(tiles, E, H / 128); gemm2_kernel<<<g, 256, SMEM_BYTES>>>(b2, out); }
}

// round 7
// speedup vs baseline: 25.3594x; 1.2644x over previous
#include <cuda_runtime.h>
#include <cuda_fp16.h>
#include <math.h>
#include <stdint.h>

#define H 512
#define F 1024
#define E 16
#define MAX_T 8192
#define EPS 1e-5f

// Per-compile-pass feature detection: tcgen05 only legal on sm_103a-style targets.
#if defined(__CUDA_ARCH__) && (defined(__CUDA_ARCH_FEAT_SM103_ALL) || \
    defined(__CUDA_ARCH_FEAT_SM100_ALL) || defined(__CUDA_ARCH_SPECIFIC__) || \
    defined(__CUDA_ARCH_FAMILY_SPECIFIC__))
#define USE_TC 1
#else
#define USE_TC 0
#endif

// ---------------------------------------------------------------------------
// Scratch (no allocation allowed -> device globals)
// ---------------------------------------------------------------------------
__device__ __align__(128) __half g_x[(size_t)MAX_T * H];
__device__ __align__(128) __half g_w1t[(size_t)E * F * H];   // [e][f][h]
__device__ __align__(128) __half g_w2t[(size_t)E * H * F];   // [e][h][f]
__device__ float g_b1part[8][E * F];
__device__ float g_b1p[E * F];
__device__ __align__(128) __half g_h[(size_t)E * MAX_T * F]; // [e][t][f]

// ---------------------------------------------------------------------------
// Common helpers
// ---------------------------------------------------------------------------
__device__ __forceinline__ uint32_t smem_to_u32(const void* p) {
    uint32_t a;
    asm("{ .reg .u64 t; cvta.to.shared.u64 t, %1; cvt.u32.u64 %0, t; }" : "=r"(a) : "l"(p));
    return a;
}
#define SMEM_SWIZZLE_128B(o) ((o) ^ (((o) >> 3) & 0x70))

__device__ __forceinline__ void cpa16(uint32_t dst, const void* src) {
    asm volatile("cp.async.cg.shared.global [%0], [%1], 16;" :: "r"(dst), "l"(src));
}
#define CP_COMMIT() asm volatile("cp.async.commit_group;" ::: "memory")
__device__ __forceinline__ void cp_wait2() { asm volatile("cp.async.wait_group 2;" ::: "memory"); }
__device__ __forceinline__ void cp_wait1() { asm volatile("cp.async.wait_group 1;" ::: "memory"); }
__device__ __forceinline__ void cp_wait0() { asm volatile("cp.async.wait_group 0;" ::: "memory"); }

__device__ __forceinline__ float gelu_erf(float x) {
    return 0.5f * x * (1.0f + erff(x * 0.70710678118654752f));
}

// Tile geometry: M=128 tokens, N=128, K-step=64
// SMEM stage: A(16K) B(16K) = 32KB; 3 stages = 96KB; 2 CTAs/SM
#define OFF_B 16384
#define STAGE_BYTES 32768
#define S_CTRL 98304             // tmem ptr (tc path)
#define S_MBAR 98320
#define SMEM_BYTES 98336

// Load one stage (A: 128x64 fp16, B: 128x64 fp16) with SW128 swizzle
__device__ __forceinline__ void stage_load_async(uint32_t sbase,
    const __half* __restrict__ A, size_t as,
    const __half* __restrict__ B, size_t bs,
    int k0, int tid)
{
    #pragma unroll
    for (int it = 0; it < 4; it++) {
        int v = tid + it * 256;
        int r = v >> 3, c = v & 7;
        uint32_t off = SMEM_SWIZZLE_128B((uint32_t)(r * 128 + c * 16));
        cpa16(sbase + off,         A + (size_t)r * as + k0 + c * 8);
        cpa16(sbase + OFF_B + off, B + (size_t)r * bs + k0 + c * 8);
    }
}

// ===========================================================================
#if USE_TC
// tcgen05 path: one M=128 x N=128 MMA region
// ===========================================================================
__device__ __forceinline__ uint32_t elect_one_pred() {
    uint32_t pred;
    asm volatile("{\n\t.reg .pred p;\n\telect.sync _|p, 0xFFFFFFFF;\n\t"
                 "selp.b32 %0, 1, 0, p;\n\t}" : "=r"(pred));
    return pred;
}
static constexpr uint64_t SMEM_DESC_BASE_SW128 =
    (uint64_t(2) << 61) | (uint64_t(1) << 46) | (uint64_t(64) << 32) | (uint64_t(1) << 16);
#define MAKE_SMEM_DESC(a) (SMEM_DESC_BASE_SW128 | ((uint64_t)((a) >> 4) & 0x3FFF))

#define TCGEN05_ALLOC(sr, n) \
    asm volatile("tcgen05.alloc.cta_group::1.sync.aligned.shared::cta.b32 [%0], %1;" \
                 :: "r"((uint32_t)(sr)), "r"((uint32_t)(n)) : "memory")
#define TCGEN05_DEALLOC(t, n) \
    asm volatile("tcgen05.dealloc.cta_group::1.sync.aligned.b32 %0, %1;" :: "r"(t), "r"(n))
#define TCGEN05_RELINQUISH() \
    asm volatile("tcgen05.relinquish_alloc_permit.cta_group::1.sync.aligned;")
#define TCGEN05_COMMIT(m) \
    asm volatile("tcgen05.commit.cta_group::1.mbarrier::arrive::one.shared::cluster.b64 [%0];" \
                 :: "r"((uint32_t)(m)) : "memory")
#define TCGEN05_FENCE_AFTER() asm volatile("tcgen05.fence::after_thread_sync;" ::: "memory")
#define TCGEN05_WAIT_LD() asm volatile("tcgen05.wait::ld.sync.aligned;" ::: "memory")
#define MBARRIER_INIT(m, c) \
    asm volatile("mbarrier.init.shared.b64 [%0], %1;" :: "r"((uint32_t)(m)), "r"((uint32_t)(c)) : "memory")
#define MBARRIER_INVAL(m) \
    asm volatile("mbarrier.inval.shared.b64 [%0];" :: "r"((uint32_t)(m)) : "memory")

#define MBARRIER_WAIT_PARITY(mb, ph) do {                                         \
    uint32_t _m = (uint32_t)(mb), _p = (uint32_t)(ph), _d;                         \
    asm volatile("{\n\t.reg .pred p;\n\t"                                          \
        "mbarrier.try_wait.parity.acquire.cta.shared::cta.b64 p, [%1], %2;\n\t"    \
        "selp.b32 %0, 1, 0, p;\n\t}" : "=r"(_d) : "r"(_m), "r"(_p) : "memory");    \
    if (!_d) {                                                                     \
        asm volatile("{\n\t.reg .pred P1;\n\t"                                     \
            "WL_%=:\n\t"                                                           \
            "mbarrier.try_wait.parity.acquire.cta.shared::cta.b64 P1, [%0], %1, 0x989680;\n\t" \
            "@P1 bra.uni WD_%=;\n\t"                                               \
            "bra.uni WL_%=;\n\t"                                                   \
            "WD_%=:\n\t}" :: "r"(_m), "r"(_p) : "memory");                         \
    }                                                                              \
} while (0)

#define TCGEN05_LD_X32(r, a)                                                       \
    asm volatile("tcgen05.ld.sync.aligned.32x32b.x32.b32 "                         \
        "{%0, %1, %2, %3, %4, %5, %6, %7, %8, %9, %10, %11, %12, %13, %14, %15, "  \
        " %16, %17, %18, %19, %20, %21, %22, %23, %24, %25, %26, %27, %28, %29, %30, %31}, [%32];" \
        : "=r"((r)[0]), "=r"((r)[1]), "=r"((r)[2]), "=r"((r)[3]),                  \
          "=r"((r)[4]), "=r"((r)[5]), "=r"((r)[6]), "=r"((r)[7]),                  \
          "=r"((r)[8]), "=r"((r)[9]), "=r"((r)[10]), "=r"((r)[11]),                \
          "=r"((r)[12]), "=r"((r)[13]), "=r"((r)[14]), "=r"((r)[15]),              \
          "=r"((r)[16]), "=r"((r)[17]), "=r"((r)[18]), "=r"((r)[19]),              \
          "=r"((r)[20]), "=r"((r)[21]), "=r"((r)[22]), "=r"((r)[23]),              \
          "=r"((r)[24]), "=r"((r)[25]), "=r"((r)[26]), "=r"((r)[27]),              \
          "=r"((r)[28]), "=r"((r)[29]), "=r"((r)[30]), "=r"((r)[31])               \
        : "r"(a))

__device__ __forceinline__ void mma_f16_ss(uint32_t d_tmem, uint64_t a_desc,
                                           uint64_t b_desc, uint32_t idesc, bool acc) {
    uint32_t en = acc ? 1u : 0u;
    asm volatile("{\n\t.reg .pred p;\n\tsetp.ne.u32 p, %4, 0;\n\t"
                 "tcgen05.mma.cta_group::1.kind::f16 [%0], %1, %2, %3, p;\n\t}"
                 :: "r"(d_tmem), "l"(a_desc), "l"(b_desc), "r"(idesc), "r"(en)
                 : "memory");
}
// dtype=F32, atype=btype=F16(0), N=128, M=128, K-major
#define MMA_IDESC ((1u << 4) | ((128u / 8u) << 17) | ((128u / 16u) << 24))

__device__ __forceinline__ uint32_t tc_prologue(uint32_t su, int tid, int wid) {
    if (wid == 0) TCGEN05_ALLOC(su + S_CTRL, 128);
    if (tid == 128) MBARRIER_INIT(su + S_MBAR, 1);
    __syncthreads();
    uint32_t tmem;
    asm volatile("ld.shared.b32 %0, [%1];" : "=r"(tmem) : "r"(su + S_CTRL));
    if (wid == 0) TCGEN05_RELINQUISH();
    __syncthreads();
    return tmem;
}

__device__ __forceinline__ void tc_mainloop(uint32_t su, uint32_t tmem,
    const __half* __restrict__ A, size_t as,
    const __half* __restrict__ B, size_t bs,
    int K, int tid, int wid)
{
    const int nk = K / 64;
    stage_load_async(su, A, as, B, bs, 0, tid);
    CP_COMMIT();
    if (nk > 1) {
        stage_load_async(su + STAGE_BYTES, A, as, B, bs, 64, tid);
        CP_COMMIT();
    }
    for (int ks = 0; ks < nk; ks++) {
        if (ks > 0) MBARRIER_WAIT_PARITY(su + S_MBAR, (ks - 1) & 1);
        if (ks + 2 < nk) {
            stage_load_async(su + ((ks + 2) % 3) * STAGE_BYTES,
                             A, as, B, bs, (ks + 2) * 64, tid);
            CP_COMMIT();
            cp_wait2();
        } else if (ks + 1 < nk) {
            cp_wait1();
        } else {
            cp_wait0();
        }
        __syncthreads();
        if (wid == 0 && elect_one_pred()) {
            asm volatile("fence.proxy.async.shared::cta;" ::: "memory");
            uint32_t sb = su + (ks % 3) * STAGE_BYTES;
            uint64_t dA = MAKE_SMEM_DESC(sb);
            uint64_t dB = MAKE_SMEM_DESC(sb + OFF_B);
            #pragma unroll
            for (int kk = 0; kk < 4; kk++) {
                bool acc0 = (ks > 0) || (kk > 0);
                mma_f16_ss(tmem, dA + kk * 2, dB + kk * 2, MMA_IDESC, acc0);
            }
            TCGEN05_COMMIT(su + S_MBAR);
        }
        __syncthreads();
    }
    MBARRIER_WAIT_PARITY(su + S_MBAR, (nk - 1) & 1);
    TCGEN05_FENCE_AFTER();
}

__device__ __forceinline__ void tc_release(uint32_t su, uint32_t tmem, int tid, int wid) {
    __syncthreads();
    if (tid == 128) MBARRIER_INVAL(su + S_MBAR);
    __syncthreads();
    if (wid == 0) TCGEN05_DEALLOC(tmem, 128);
}
#endif  // USE_TC

// ===========================================================================
#if !USE_TC
// mma.sync fallback: 8 warps, warp tile 32x64 within 128x128 CTA tile
// ===========================================================================
__device__ __forceinline__ void ldsm_x4(uint32_t* r, uint32_t a) {
    asm volatile("ldmatrix.sync.aligned.m8n8.x4.shared.b16 {%0,%1,%2,%3}, [%4];"
                 : "=r"(r[0]), "=r"(r[1]), "=r"(r[2]), "=r"(r[3]) : "r"(a));
}
__device__ __forceinline__ void mma16816(float* d, const uint32_t* a, const uint32_t* b) {
    asm volatile("mma.sync.aligned.m16n8k16.row.col.f32.f16.f16.f32 "
                 "{%0,%1,%2,%3}, {%4,%5,%6,%7}, {%8,%9}, {%0,%1,%2,%3};"
                 : "+f"(d[0]), "+f"(d[1]), "+f"(d[2]), "+f"(d[3])
                 : "r"(a[0]), "r"(a[1]), "r"(a[2]), "r"(a[3]), "r"(b[0]), "r"(b[1]));
}

__device__ __forceinline__ void mmasync_mainloop(uint32_t su,
    const __half* __restrict__ A, size_t as,
    const __half* __restrict__ B, size_t bs,
    int K, int tid, float acc[2][8][4])
{
    const int nk = K / 64;
    const int wid = tid >> 5, lane = tid & 31;
    const int wm = wid >> 1, wn = wid & 1;

    stage_load_async(su, A, as, B, bs, 0, tid);
    CP_COMMIT();
    if (nk > 1) {
        stage_load_async(su + STAGE_BYTES, A, as, B, bs, 64, tid);
        CP_COMMIT();
    }

    for (int ks = 0; ks < nk; ks++) {
        if (ks + 2 < nk) {
            stage_load_async(su + ((ks + 2) % 3) * STAGE_BYTES,
                             A, as, B, bs, (ks + 2) * 64, tid);
            CP_COMMIT();
            cp_wait2();
        } else if (ks + 1 < nk) {
            cp_wait1();
        } else {
            cp_wait0();
        }
        __syncthreads();

        uint32_t sA = su + (ks % 3) * STAGE_BYTES;
        uint32_t sB = sA + OFF_B;

        #pragma unroll
        for (int k16 = 0; k16 < 64; k16 += 16) {
            // B fragments: warp covers n in [wn*64, wn*64+64)
            uint32_t bh[8][2];
            #pragma unroll
            for (int jj = 0; jj < 4; jj++) {
                int n = wn * 64 + jj * 16 + (lane & 7) + ((lane >> 3) & 1) * 8;
                int k = k16 + (lane >> 4) * 8;
                uint32_t addr = sB + SMEM_SWIZZLE_128B((uint32_t)(n * 128 + k * 2));
                uint32_t t[4];
                ldsm_x4(t, addr);
                bh[2 * jj][0] = t[0]; bh[2 * jj + 1][0] = t[1];
                bh[2 * jj][1] = t[2]; bh[2 * jj + 1][1] = t[3];
            }
            // A fragments + MMA: warp covers m in [wm*32, wm*32+32)
            #pragma unroll
            for (int i = 0; i < 2; i++) {
                int m = wm * 32 + i * 16 + (lane & 15);
                int k = k16 + (lane >> 4) * 8;
                uint32_t addr = sA + SMEM_SWIZZLE_128B((uint32_t)(m * 128 + k * 2));
                uint32_t ah[4];
                ldsm_x4(ah, addr);
                #pragma unroll
                for (int j = 0; j < 8; j++)
                    mma16816(acc[i][j], ah, bh[j]);
            }
        }
        __syncthreads();
    }
}
#endif  // !USE_TC

// ---------------------------------------------------------------------------
// Prep kernels
// ---------------------------------------------------------------------------
__device__ __forceinline__ float blk_sum256(float v) {
    __shared__ float red[8];
    #pragma unroll
    for (int o = 16; o > 0; o >>= 1) v += __shfl_xor_sync(0xffffffffu, v, o);
    int w = threadIdx.x >> 5, l = threadIdx.x & 31;
    if (l == 0) red[w] = v;
    __syncthreads();
    if (threadIdx.x < 32) {
        float r = (threadIdx.x < 8) ? red[threadIdx.x] : 0.0f;
        #pragma unroll
        for (int o = 4; o > 0; o >>= 1) r += __shfl_xor_sync(0xffffffffu, r, o);
        if (threadIdx.x == 0) red[0] = r;
    }
    __syncthreads();
    float out = red[0];
    __syncthreads();
    return out;
}

__global__ void ln_split_kernel(const float* __restrict__ tokens) {
    int row = blockIdx.x, tid = threadIdx.x;
    const float* x = tokens + (size_t)row * H;
    float v0 = x[tid], v1 = x[tid + 256];
    float mu = blk_sum256(v0 + v1) * (1.0f / H);
    float d0 = v0 - mu, d1 = v1 - mu;
    float rs = rsqrtf(blk_sum256(d0 * d0 + d1 * d1) * (1.0f / H) + EPS);
    size_t base = (size_t)row * H;
    g_x[base + tid]       = __float2half_rn(d0 * rs);
    g_x[base + tid + 256] = __float2half_rn(d1 * rs);
}

__global__ void w1t_kernel(const float* __restrict__ W1, const float* __restrict__ ln_g) {
    __shared__ float ts[64][65];
    int e = blockIdx.z, f0 = blockIdx.x * 64, h0 = blockIdx.y * 64, tid = threadIdx.x;
    #pragma unroll
    for (int i = 0; i < 16; i++) {
        int idx = tid + i * 256, r = idx >> 6, c = idx & 63;
        ts[r][c] = W1[((size_t)e * H + h0 + r) * F + f0 + c];
    }
    __syncthreads();
    #pragma unroll
    for (int i = 0; i < 16; i++) {
        int idx = tid + i * 256, r = idx >> 6, c = idx & 63;
        float w = ts[c][r] * ln_g[e * H + h0 + c];
        g_w1t[((size_t)e * F + f0 + r) * H + h0 + c] = __float2half_rn(w);
    }
}

__global__ void w2t_kernel(const float* __restrict__ W2) {
    __shared__ float ts[64][65];
    int e = blockIdx.z, h0 = blockIdx.x * 64, f0 = blockIdx.y * 64, tid = threadIdx.x;
    #pragma unroll
    for (int i = 0; i < 16; i++) {
        int idx = tid + i * 256, r = idx >> 6, c = idx & 63;
        ts[r][c] = W2[((size_t)e * F + f0 + r) * H + h0 + c];
    }
    __syncthreads();
    #pragma unroll
    for (int i = 0; i < 16; i++) {
        int idx = tid + i * 256, r = idx >> 6, c = idx & 63;
        g_w2t[((size_t)e * H + h0 + r) * F + f0 + c] = __float2half_rn(ts[c][r]);
    }
}

// b1' = ln_b @ W1 + b1, two-phase deterministic (h split into 8 slabs of 64)
__global__ void b1p_part_kernel(const float* __restrict__ W1, const float* __restrict__ ln_b) {
    int e = blockIdx.y, hs = blockIdx.z * 64;
    int f = blockIdx.x * 256 + threadIdx.x;
    const float* w = W1 + ((size_t)e * H + hs) * F + f;
    const float* b = ln_b + e * H + hs;
    float acc = 0.0f;
    #pragma unroll 8
    for (int h = 0; h < 64; h++) acc += b[h] * w[(size_t)h * F];
    g_b1part[blockIdx.z][e * F + f] = acc;
}
__global__ void b1p_reduce_kernel(const float* __restrict__ b1) {
    int i = blockIdx.x * 256 + threadIdx.x;
    float acc = b1[i];
    #pragma unroll
    for (int s = 0; s < 8; s++) acc += g_b1part[s][i];
    g_b1p[i] = acc;
}

// ---------------------------------------------------------------------------
// GEMM1: h = gelu(xhat @ (g*W1) + b1')    grid: (T/128, E, F/128)
// ---------------------------------------------------------------------------
__global__ void __launch_bounds__(256, 2) gemm1_kernel() {
    extern __shared__ char smem[];
    uint32_t su = smem_to_u32(smem);
    const int tid = threadIdx.x, wid = tid >> 5, lane = tid & 31;
    const int e = blockIdx.y;
    const int tok0 = blockIdx.x * 128;
    const int fc = blockIdx.z * 128;

    const __half* A = g_x + (size_t)tok0 * H;
    const __half* B = g_w1t + ((size_t)e * F + fc) * H;

#if USE_TC
    uint32_t tmem = tc_prologue(su, tid, wid);
    tc_mainloop(su, tmem, A, H, B, H, H, tid, wid);

    const int row = (wid & 3) * 32 + lane;
    const int ch = (wid >> 2) * 64;
    const size_t hrow = ((size_t)e * MAX_T + tok0 + row) * F;
    for (int cb = 0; cb < 64; cb += 32) {
        uint32_t r[32];
        TCGEN05_LD_X32(r, tmem + ch + cb);
        TCGEN05_WAIT_LD();
        int fglob = fc + ch + cb;
        __half h8[8];
        #pragma unroll
        for (int j = 0; j < 32; j++) {
            float v = __uint_as_float(r[j]) + g_b1p[e * F + fglob + j];
            h8[j & 7] = __float2half_rn(gelu_erf(v));
            if ((j & 7) == 7)
                *reinterpret_cast<uint4*>(&g_h[hrow + fglob + (j & ~7)]) =
                    *reinterpret_cast<uint4*>(h8);
        }
    }
    tc_release(su, tmem, tid, wid);
#else
    float acc[2][8][4];
    #pragma unroll
    for (int i = 0; i < 2; i++)
        #pragma unroll
        for (int j = 0; j < 8; j++)
            #pragma unroll
            for (int q = 0; q < 4; q++) acc[i][j][q] = 0.0f;

    mmasync_mainloop(su, A, H, B, H, H, tid, acc);

    const int wm = wid >> 1, wn = wid & 1;
    const float* b1pp = g_b1p + e * F;
    #pragma unroll
    for (int i = 0; i < 2; i++) {
        #pragma unroll
        for (int j = 0; j < 8; j++) {
            int fj = fc + wn * 64 + j * 8 + (lane & 3) * 2;
            int r0 = tok0 + wm * 32 + i * 16 + (lane >> 2);
            #pragma unroll
            for (int half = 0; half < 2; half++) {
                int rr = r0 + half * 8;
                float v0 = acc[i][j][2 * half + 0] + b1pp[fj];
                float v1 = acc[i][j][2 * half + 1] + b1pp[fj + 1];
                __half h0 = __float2half_rn(gelu_erf(v0));
                __half h1 = __float2half_rn(gelu_erf(v1));
                uint32_t ph = ((uint32_t)__half_as_ushort(h1) << 16) | __half_as_ushort(h0);
                *reinterpret_cast<uint32_t*>(&g_h[((size_t)e * MAX_T + rr) * F + fj]) = ph;
            }
        }
    }
#endif
}

// ---------------------------------------------------------------------------
// GEMM2: out = h @ W2 + b2     grid: (T/128, E, H/128)
// ---------------------------------------------------------------------------
__global__ void __launch_bounds__(256, 2) gemm2_kernel(const float* __restrict__ b2,
                                                       float* __restrict__ out) {
    extern __shared__ char smem[];
    uint32_t su = smem_to_u32(smem);
    const int tid = threadIdx.x, wid = tid >> 5, lane = tid & 31;
    const int e = blockIdx.y;
    const int tok0 = blockIdx.x * 128;
    const int hh0 = blockIdx.z * 128;

    const __half* A = g_h + ((size_t)e * MAX_T + tok0) * F;
    const __half* B = g_w2t + ((size_t)e * H + hh0) * F;

#if USE_TC
    uint32_t tmem = tc_prologue(su, tid, wid);
    tc_mainloop(su, tmem, A, F, B, F, F, tid, wid);

    const int row = (wid & 3) * 32 + lane;
    const int ch = (wid >> 2) * 64;
    float* orow = out + (((size_t)(tok0 + row)) * E + e) * H;
    for (int cb = 0; cb < 64; cb += 32) {
        uint32_t r[32];
        TCGEN05_LD_X32(r, tmem + ch + cb);
        TCGEN05_WAIT_LD();
        int hglob = hh0 + ch + cb;
        float v4[4];
        #pragma unroll
        for (int j = 0; j < 32; j++) {
            v4[j & 3] = __uint_as_float(r[j]) + b2[e * H + hglob + j];
            if ((j & 3) == 3)
                *reinterpret_cast<uint4*>(orow + hglob + (j & ~3)) =
                    *reinterpret_cast<uint4*>(v4);
        }
    }
    tc_release(su, tmem, tid, wid);
#else
    float acc[2][8][4];
    #pragma unroll
    for (int i = 0; i < 2; i++)
        #pragma unroll
        for (int j = 0; j < 8; j++)
            #pragma unroll
            for (int q = 0; q < 4; q++) acc[i][j][q] = 0.0f;

    mmasync_mainloop(su, A, F, B, F, F, tid, acc);

    const int wm = wid >> 1, wn = wid & 1;
    const float* b2p = b2 + e * H;
    #pragma unroll
    for (int i = 0; i < 2; i++) {
        #pragma unroll
        for (int j = 0; j < 8; j++) {
            int hj = hh0 + wn * 64 + j * 8 + (lane & 3) * 2;
            int r0 = tok0 + wm * 32 + i * 16 + (lane >> 2);
            float bb0 = b2p[hj], bb1 = b2p[hj + 1];
            #pragma unroll
            for (int half = 0; half < 2; half++) {
                int rr = r0 + half * 8;
                float2 v = make_float2(acc[i][j][2 * half + 0] + bb0,
                                       acc[i][j][2 * half + 1] + bb1);
                *reinterpret_cast<float2*>(out + ((size_t)rr * E + e) * H + hj) = v;
            }
        }
    }
#endif
}

// ---------------------------------------------------------------------------
extern "C" void kernel_launch(void* const* d_in, const int* in_sizes, int n_in,
                              void* d_out, int out_size)
{
    const float* tokens = (const float*)d_in[0];
    const float* ln_g   = (const float*)d_in[1];
    const float* ln_b   = (const float*)d_in[2];
    const float* W1     = (const float*)d_in[3];
    const float* b1     = (const float*)d_in[4];
    const float* W2     = (const float*)d_in[5];
    const float* b2     = (const float*)d_in[6];
    float* out = (float*)d_out;

    int T = in_sizes[0] / H;      // 8192
    int tiles = T / 128;          // 64

    cudaFuncSetAttribute(gemm1_kernel, cudaFuncAttributeMaxDynamicSharedMemorySize, SMEM_BYTES);
    cudaFuncSetAttribute(gemm2_kernel, cudaFuncAttributeMaxDynamicSharedMemorySize, SMEM_BYTES);

    ln_split_kernel<<<T, 256>>>(tokens);
    { dim3 g(F / 64, H / 64, E); w1t_kernel<<<g, 256>>>(W1, ln_g); }
    { dim3 g(H / 64, F / 64, E); w2t_kernel<<<g, 256>>>(W2); }
    { dim3 g(F / 256, E, 8); b1p_part_kernel<<<g, 256>>>(W1, ln_b); }
    b1p_reduce_kernel<<<E * F / 256, 256>>>(b1);
    { dim3 g(tiles, E, F / 128); gemm1_kernel<<<g, 256, SMEM_BYTES>>>(); }
    { dim3 g(tiles, E, H / 128); gemm2_kernel<<<g, 256, SMEM_BYTES>>>(b2, out); }
}

// round 8
// speedup vs baseline: 26.0891x; 1.0288x over previous
#include <cuda_runtime.h>
#include <cuda_fp16.h>
#include <math.h>
#include <stdint.h>

#define H 512
#define F 1024
#define E 16
#define MAX_T 8192
#define EPS 1e-5f

// Per-compile-pass feature detection: tcgen05 only legal on sm_103a-style targets.
#if defined(__CUDA_ARCH__) && (defined(__CUDA_ARCH_FEAT_SM103_ALL) || \
    defined(__CUDA_ARCH_FEAT_SM100_ALL) || defined(__CUDA_ARCH_SPECIFIC__) || \
    defined(__CUDA_ARCH_FAMILY_SPECIFIC__))
#define USE_TC 1
#else
#define USE_TC 0
#endif

// ---------------------------------------------------------------------------
// Scratch (no allocation allowed -> device globals)
// ---------------------------------------------------------------------------
__device__ __align__(128) __half g_x[(size_t)MAX_T * H];
__device__ __align__(128) __half g_w1t[(size_t)E * F * H];   // [e][f][h]
__device__ __align__(128) __half g_w2t[(size_t)E * H * F];   // [e][h][f]
__device__ float g_b1part[8][E * F];
__device__ __align__(128) __half g_h[(size_t)E * MAX_T * F]; // [e][t][f]

// ---------------------------------------------------------------------------
// Common helpers
// ---------------------------------------------------------------------------
__device__ __forceinline__ uint32_t smem_to_u32(const void* p) {
    uint32_t a;
    asm("{ .reg .u64 t; cvta.to.shared.u64 t, %1; cvt.u32.u64 %0, t; }" : "=r"(a) : "l"(p));
    return a;
}
#define SMEM_SWIZZLE_128B(o) ((o) ^ (((o) >> 3) & 0x70))

__device__ __forceinline__ void cpa16(uint32_t dst, const void* src) {
    asm volatile("cp.async.cg.shared.global [%0], [%1], 16;" :: "r"(dst), "l"(src));
}
#define CP_COMMIT() asm volatile("cp.async.commit_group;" ::: "memory")
__device__ __forceinline__ void cp_wait2() { asm volatile("cp.async.wait_group 2;" ::: "memory"); }
__device__ __forceinline__ void cp_wait1() { asm volatile("cp.async.wait_group 1;" ::: "memory"); }
__device__ __forceinline__ void cp_wait0() { asm volatile("cp.async.wait_group 0;" ::: "memory"); }

__device__ __forceinline__ float gelu_erf(float x) {
    return 0.5f * x * (1.0f + erff(x * 0.70710678118654752f));
}

// Tile geometry: M=128 tokens, N=128, K-step=64
// SMEM stage: A(16K) B(16K) = 32KB; 3 stages = 96KB; 2 CTAs/SM
#define OFF_B 16384
#define STAGE_BYTES 32768
#define S_CTRL 98304             // tmem ptr (tc path)
#define S_MBAR 98320
#define S_B1   98336             // 128 floats of b1' for this fc tile
#define SMEM_BYTES 98848

// Load one stage (A: 128x64 fp16, B: 128x64 fp16) with SW128 swizzle
__device__ __forceinline__ void stage_load_async(uint32_t sbase,
    const __half* __restrict__ A, size_t as,
    const __half* __restrict__ B, size_t bs,
    int k0, int tid)
{
    #pragma unroll
    for (int it = 0; it < 4; it++) {
        int v = tid + it * 256;
        int r = v >> 3, c = v & 7;
        uint32_t off = SMEM_SWIZZLE_128B((uint32_t)(r * 128 + c * 16));
        cpa16(sbase + off,         A + (size_t)r * as + k0 + c * 8);
        cpa16(sbase + OFF_B + off, B + (size_t)r * bs + k0 + c * 8);
    }
}

// ===========================================================================
#if USE_TC
// tcgen05 path: one M=128 x N=128 MMA region
// ===========================================================================
__device__ __forceinline__ uint32_t elect_one_pred() {
    uint32_t pred;
    asm volatile("{\n\t.reg .pred p;\n\telect.sync _|p, 0xFFFFFFFF;\n\t"
                 "selp.b32 %0, 1, 0, p;\n\t}" : "=r"(pred));
    return pred;
}
static constexpr uint64_t SMEM_DESC_BASE_SW128 =
    (uint64_t(2) << 61) | (uint64_t(1) << 46) | (uint64_t(64) << 32) | (uint64_t(1) << 16);
#define MAKE_SMEM_DESC(a) (SMEM_DESC_BASE_SW128 | ((uint64_t)((a) >> 4) & 0x3FFF))

#define TCGEN05_ALLOC(sr, n) \
    asm volatile("tcgen05.alloc.cta_group::1.sync.aligned.shared::cta.b32 [%0], %1;" \
                 :: "r"((uint32_t)(sr)), "r"((uint32_t)(n)) : "memory")
#define TCGEN05_DEALLOC(t, n) \
    asm volatile("tcgen05.dealloc.cta_group::1.sync.aligned.b32 %0, %1;" :: "r"(t), "r"(n))
#define TCGEN05_RELINQUISH() \
    asm volatile("tcgen05.relinquish_alloc_permit.cta_group::1.sync.aligned;")
#define TCGEN05_COMMIT(m) \
    asm volatile("tcgen05.commit.cta_group::1.mbarrier::arrive::one.shared::cluster.b64 [%0];" \
                 :: "r"((uint32_t)(m)) : "memory")
#define TCGEN05_FENCE_AFTER() asm volatile("tcgen05.fence::after_thread_sync;" ::: "memory")
#define TCGEN05_WAIT_LD() asm volatile("tcgen05.wait::ld.sync.aligned;" ::: "memory")
#define MBARRIER_INIT(m, c) \
    asm volatile("mbarrier.init.shared.b64 [%0], %1;" :: "r"((uint32_t)(m)), "r"((uint32_t)(c)) : "memory")
#define MBARRIER_INVAL(m) \
    asm volatile("mbarrier.inval.shared.b64 [%0];" :: "r"((uint32_t)(m)) : "memory")

#define MBARRIER_WAIT_PARITY(mb, ph) do {                                         \
    uint32_t _m = (uint32_t)(mb), _p = (uint32_t)(ph), _d;                         \
    asm volatile("{\n\t.reg .pred p;\n\t"                                          \
        "mbarrier.try_wait.parity.acquire.cta.shared::cta.b64 p, [%1], %2;\n\t"    \
        "selp.b32 %0, 1, 0, p;\n\t}" : "=r"(_d) : "r"(_m), "r"(_p) : "memory");    \
    if (!_d) {                                                                     \
        asm volatile("{\n\t.reg .pred P1;\n\t"                                     \
            "WL_%=:\n\t"                                                           \
            "mbarrier.try_wait.parity.acquire.cta.shared::cta.b64 P1, [%0], %1, 0x989680;\n\t" \
            "@P1 bra.uni WD_%=;\n\t"                                               \
            "bra.uni WL_%=;\n\t"                                                   \
            "WD_%=:\n\t}" :: "r"(_m), "r"(_p) : "memory");                         \
    }                                                                              \
} while (0)

#define TCGEN05_LD_X32(r, a)                                                       \
    asm volatile("tcgen05.ld.sync.aligned.32x32b.x32.b32 "                         \
        "{%0, %1, %2, %3, %4, %5, %6, %7, %8, %9, %10, %11, %12, %13, %14, %15, "  \
        " %16, %17, %18, %19, %20, %21, %22, %23, %24, %25, %26, %27, %28, %29, %30, %31}, [%32];" \
        : "=r"((r)[0]), "=r"((r)[1]), "=r"((r)[2]), "=r"((r)[3]),                  \
          "=r"((r)[4]), "=r"((r)[5]), "=r"((r)[6]), "=r"((r)[7]),                  \
          "=r"((r)[8]), "=r"((r)[9]), "=r"((r)[10]), "=r"((r)[11]),                \
          "=r"((r)[12]), "=r"((r)[13]), "=r"((r)[14]), "=r"((r)[15]),              \
          "=r"((r)[16]), "=r"((r)[17]), "=r"((r)[18]), "=r"((r)[19]),              \
          "=r"((r)[20]), "=r"((r)[21]), "=r"((r)[22]), "=r"((r)[23]),              \
          "=r"((r)[24]), "=r"((r)[25]), "=r"((r)[26]), "=r"((r)[27]),              \
          "=r"((r)[28]), "=r"((r)[29]), "=r"((r)[30]), "=r"((r)[31])               \
        : "r"(a))

__device__ __forceinline__ void mma_f16_ss(uint32_t d_tmem, uint64_t a_desc,
                                           uint64_t b_desc, uint32_t idesc, bool acc) {
    uint32_t en = acc ? 1u : 0u;
    asm volatile("{\n\t.reg .pred p;\n\tsetp.ne.u32 p, %4, 0;\n\t"
                 "tcgen05.mma.cta_group::1.kind::f16 [%0], %1, %2, %3, p;\n\t}"
                 :: "r"(d_tmem), "l"(a_desc), "l"(b_desc), "r"(idesc), "r"(en)
                 : "memory");
}
// dtype=F32, atype=btype=F16(0), N=128, M=128, K-major
#define MMA_IDESC ((1u << 4) | ((128u / 8u) << 17) | ((128u / 16u) << 24))

__device__ __forceinline__ uint32_t tc_prologue(uint32_t su, int tid, int wid) {
    if (wid == 0) TCGEN05_ALLOC(su + S_CTRL, 128);
    if (tid == 128) MBARRIER_INIT(su + S_MBAR, 1);
    __syncthreads();
    uint32_t tmem;
    asm volatile("ld.shared.b32 %0, [%1];" : "=r"(tmem) : "r"(su + S_CTRL));
    if (wid == 0) TCGEN05_RELINQUISH();
    __syncthreads();
    return tmem;
}

__device__ __forceinline__ void tc_mainloop(uint32_t su, uint32_t tmem,
    const __half* __restrict__ A, size_t as,
    const __half* __restrict__ B, size_t bs,
    int K, int tid, int wid)
{
    const int nk = K / 64;
    stage_load_async(su, A, as, B, bs, 0, tid);
    CP_COMMIT();
    if (nk > 1) {
        stage_load_async(su + STAGE_BYTES, A, as, B, bs, 64, tid);
        CP_COMMIT();
    }
    for (int ks = 0; ks < nk; ks++) {
        if (ks > 0) MBARRIER_WAIT_PARITY(su + S_MBAR, (ks - 1) & 1);
        if (ks + 2 < nk) {
            stage_load_async(su + ((ks + 2) % 3) * STAGE_BYTES,
                             A, as, B, bs, (ks + 2) * 64, tid);
            CP_COMMIT();
            cp_wait2();
        } else if (ks + 1 < nk) {
            cp_wait1();
        } else {
            cp_wait0();
        }
        __syncthreads();
        if (wid == 0 && elect_one_pred()) {
            asm volatile("fence.proxy.async.shared::cta;" ::: "memory");
            uint32_t sb = su + (ks % 3) * STAGE_BYTES;
            uint64_t dA = MAKE_SMEM_DESC(sb);
            uint64_t dB = MAKE_SMEM_DESC(sb + OFF_B);
            #pragma unroll
            for (int kk = 0; kk < 4; kk++) {
                bool acc0 = (ks > 0) || (kk > 0);
                mma_f16_ss(tmem, dA + kk * 2, dB + kk * 2, MMA_IDESC, acc0);
            }
            TCGEN05_COMMIT(su + S_MBAR);
        }
        __syncthreads();
    }
    MBARRIER_WAIT_PARITY(su + S_MBAR, (nk - 1) & 1);
    TCGEN05_FENCE_AFTER();
}

__device__ __forceinline__ void tc_release(uint32_t su, uint32_t tmem, int tid, int wid) {
    __syncthreads();
    if (tid == 128) MBARRIER_INVAL(su + S_MBAR);
    __syncthreads();
    if (wid == 0) TCGEN05_DEALLOC(tmem, 128);
}
#endif  // USE_TC

// ===========================================================================
#if !USE_TC
// mma.sync fallback: 8 warps, warp tile 32x64 within 128x128 CTA tile
// ===========================================================================
__device__ __forceinline__ void ldsm_x4(uint32_t* r, uint32_t a) {
    asm volatile("ldmatrix.sync.aligned.m8n8.x4.shared.b16 {%0,%1,%2,%3}, [%4];"
                 : "=r"(r[0]), "=r"(r[1]), "=r"(r[2]), "=r"(r[3]) : "r"(a));
}
__device__ __forceinline__ void mma16816(float* d, const uint32_t* a, const uint32_t* b) {
    asm volatile("mma.sync.aligned.m16n8k16.row.col.f32.f16.f16.f32 "
                 "{%0,%1,%2,%3}, {%4,%5,%6,%7}, {%8,%9}, {%0,%1,%2,%3};"
                 : "+f"(d[0]), "+f"(d[1]), "+f"(d[2]), "+f"(d[3])
                 : "r"(a[0]), "r"(a[1]), "r"(a[2]), "r"(a[3]), "r"(b[0]), "r"(b[1]));
}

__device__ __forceinline__ void mmasync_mainloop(uint32_t su,
    const __half* __restrict__ A, size_t as,
    const __half* __restrict__ B, size_t bs,
    int K, int tid, float acc[2][8][4])
{
    const int nk = K / 64;
    const int wid = tid >> 5, lane = tid & 31;
    const int wm = wid >> 1, wn = wid & 1;

    stage_load_async(su, A, as, B, bs, 0, tid);
    CP_COMMIT();
    if (nk > 1) {
        stage_load_async(su + STAGE_BYTES, A, as, B, bs, 64, tid);
        CP_COMMIT();
    }

    for (int ks = 0; ks < nk; ks++) {
        if (ks + 2 < nk) {
            stage_load_async(su + ((ks + 2) % 3) * STAGE_BYTES,
                             A, as, B, bs, (ks + 2) * 64, tid);
            CP_COMMIT();
            cp_wait2();
        } else if (ks + 1 < nk) {
            cp_wait1();
        } else {
            cp_wait0();
        }
        __syncthreads();

        uint32_t sA = su + (ks % 3) * STAGE_BYTES;
        uint32_t sB = sA + OFF_B;

        #pragma unroll
        for (int k16 = 0; k16 < 64; k16 += 16) {
            // B fragments: warp covers n in [wn*64, wn*64+64)
            uint32_t bh[8][2];
            #pragma unroll
            for (int jj = 0; jj < 4; jj++) {
                int n = wn * 64 + jj * 16 + (lane & 7) + ((lane >> 3) & 1) * 8;
                int k = k16 + (lane >> 4) * 8;
                uint32_t addr = sB + SMEM_SWIZZLE_128B((uint32_t)(n * 128 + k * 2));
                uint32_t t[4];
                ldsm_x4(t, addr);
                bh[2 * jj][0] = t[0]; bh[2 * jj + 1][0] = t[1];
                bh[2 * jj][1] = t[2]; bh[2 * jj + 1][1] = t[3];
            }
            // A fragments + MMA: warp covers m in [wm*32, wm*32+32)
            #pragma unroll
            for (int i = 0; i < 2; i++) {
                int m = wm * 32 + i * 16 + (lane & 15);
                int k = k16 + (lane >> 4) * 8;
                uint32_t addr = sA + SMEM_SWIZZLE_128B((uint32_t)(m * 128 + k * 2));
                uint32_t ah[4];
                ldsm_x4(ah, addr);
                #pragma unroll
                for (int j = 0; j < 8; j++)
                    mma16816(acc[i][j], ah, bh[j]);
            }
        }
        __syncthreads();
    }
}
#endif  // !USE_TC

// ---------------------------------------------------------------------------
// Fused prep kernel: all independent precomputation in ONE launch.
//   [0, nbLN)                     : LayerNorm -> g_x (warp per row)
//   [nbLN, nbLN+2048)             : W1^T * g -> g_w1t
//   [nbLN+2048, nbLN+4096)        : W2^T -> g_w2t
//   [nbLN+4096, nbLN+4608)        : b1 partials -> g_b1part
// ---------------------------------------------------------------------------
__global__ void __launch_bounds__(256) prep_kernel(
    const float* __restrict__ tokens, const float* __restrict__ ln_g,
    const float* __restrict__ ln_b,   const float* __restrict__ W1,
    const float* __restrict__ W2,     int nbLN)
{
    __shared__ float ts[64][65];
    const int tid = threadIdx.x;
    int b = blockIdx.x;

    if (b < nbLN) {
        // ---- LayerNorm: warp per row, 8 rows per block ----
        const int wid = tid >> 5, lane = tid & 31;
        const int row = b * 8 + wid;
        const float* x = tokens + (size_t)row * H;
        float v[16];
        float s = 0.0f;
        #pragma unroll
        for (int i = 0; i < 16; i++) { v[i] = x[lane + 32 * i]; s += v[i]; }
        #pragma unroll
        for (int o = 16; o > 0; o >>= 1) s += __shfl_xor_sync(0xffffffffu, s, o);
        float mu = s * (1.0f / H);
        float q = 0.0f;
        #pragma unroll
        for (int i = 0; i < 16; i++) { v[i] -= mu; q += v[i] * v[i]; }
        #pragma unroll
        for (int o = 16; o > 0; o >>= 1) q += __shfl_xor_sync(0xffffffffu, q, o);
        float rs = rsqrtf(q * (1.0f / H) + EPS);
        __half* ox = g_x + (size_t)row * H;
        #pragma unroll
        for (int i = 0; i < 16; i++)
            ox[lane + 32 * i] = __float2half_rn(v[i] * rs);
        return;
    }
    b -= nbLN;

    if (b < 2048) {
        // ---- W1^T * g: idx -> (f0, h0, e) ----
        int f0 = (b & 15) * 64, h0 = ((b >> 4) & 7) * 64, e = b >> 7;
        #pragma unroll
        for (int i = 0; i < 16; i++) {
            int idx = tid + i * 256, r = idx >> 6, c = idx & 63;
            ts[r][c] = W1[((size_t)e * H + h0 + r) * F + f0 + c];
        }
        __syncthreads();
        #pragma unroll
        for (int i = 0; i < 16; i++) {
            int idx = tid + i * 256, r = idx >> 6, c = idx & 63;
            float w = ts[c][r] * ln_g[e * H + h0 + c];
            g_w1t[((size_t)e * F + f0 + r) * H + h0 + c] = __float2half_rn(w);
        }
        return;
    }
    b -= 2048;

    if (b < 2048) {
        // ---- W2^T: idx -> (h0, f0, e) ----
        int h0 = (b & 7) * 64, f0 = ((b >> 3) & 15) * 64, e = b >> 7;
        #pragma unroll
        for (int i = 0; i < 16; i++) {
            int idx = tid + i * 256, r = idx >> 6, c = idx & 63;
            ts[r][c] = W2[((size_t)e * F + f0 + r) * H + h0 + c];
        }
        __syncthreads();
        #pragma unroll
        for (int i = 0; i < 16; i++) {
            int idx = tid + i * 256, r = idx >> 6, c = idx & 63;
            g_w2t[((size_t)e * H + h0 + r) * F + f0 + c] = __float2half_rn(ts[c][r]);
        }
        return;
    }
    b -= 2048;

    // ---- b1 partials: b in [0,512) -> (fblk, e, slab) ----
    {
        int fblk = b & 3, e = (b >> 2) & 15, slab = b >> 6;
        int hs = slab * 64;
        int f = fblk * 256 + tid;
        const float* w = W1 + ((size_t)e * H + hs) * F + f;
        const float* bb = ln_b + e * H + hs;
        float acc = 0.0f;
        #pragma unroll 8
        for (int h = 0; h < 64; h++) acc += bb[h] * w[(size_t)h * F];
        g_b1part[slab][e * F + f] = acc;
    }
}

// ---------------------------------------------------------------------------
// GEMM1: h = gelu(xhat @ (g*W1) + b1')    grid: (T/128, E, F/128)
// b1' reduced on the fly into smem (b1 + sum of 8 partials).
// ---------------------------------------------------------------------------
__global__ void __launch_bounds__(256, 2) gemm1_kernel(const float* __restrict__ b1) {
    extern __shared__ char smem[];
    uint32_t su = smem_to_u32(smem);
    float* sm_b1 = reinterpret_cast<float*>(smem + S_B1);
    const int tid = threadIdx.x, wid = tid >> 5, lane = tid & 31;
    const int e = blockIdx.y;
    const int tok0 = blockIdx.x * 128;
    const int fc = blockIdx.z * 128;

    // Reduce b1' tile into smem (consumed by epilogue; mainloop syncs cover it)
    if (tid < 128) {
        int fg = e * F + fc + tid;
        float a = b1[fg];
        #pragma unroll
        for (int s = 0; s < 8; s++) a += g_b1part[s][fg];
        sm_b1[tid] = a;
    }

    const __half* A = g_x + (size_t)tok0 * H;
    const __half* B = g_w1t + ((size_t)e * F + fc) * H;

#if USE_TC
    uint32_t tmem = tc_prologue(su, tid, wid);
    tc_mainloop(su, tmem, A, H, B, H, H, tid, wid);

    const int row = (wid & 3) * 32 + lane;
    const int ch = (wid >> 2) * 64;
    const size_t hrow = ((size_t)e * MAX_T + tok0 + row) * F;
    for (int cb = 0; cb < 64; cb += 32) {
        uint32_t r[32];
        TCGEN05_LD_X32(r, tmem + ch + cb);
        TCGEN05_WAIT_LD();
        int fglob = fc + ch + cb;
        __half h8[8];
        #pragma unroll
        for (int j = 0; j < 32; j++) {
            float v = __uint_as_float(r[j]) + sm_b1[ch + cb + j];
            h8[j & 7] = __float2half_rn(gelu_erf(v));
            if ((j & 7) == 7)
                *reinterpret_cast<uint4*>(&g_h[hrow + fglob + (j & ~7)]) =
                    *reinterpret_cast<uint4*>(h8);
        }
    }
    tc_release(su, tmem, tid, wid);
#else
    float acc[2][8][4];
    #pragma unroll
    for (int i = 0; i < 2; i++)
        #pragma unroll
        for (int j = 0; j < 8; j++)
            #pragma unroll
            for (int q = 0; q < 4; q++) acc[i][j][q] = 0.0f;

    mmasync_mainloop(su, A, H, B, H, H, tid, acc);

    const int wm = wid >> 1, wn = wid & 1;
    #pragma unroll
    for (int i = 0; i < 2; i++) {
        #pragma unroll
        for (int j = 0; j < 8; j++) {
            int fl = wn * 64 + j * 8 + (lane & 3) * 2;   // local f within tile
            int r0 = tok0 + wm * 32 + i * 16 + (lane >> 2);
            float bb0 = sm_b1[fl], bb1 = sm_b1[fl + 1];
            #pragma unroll
            for (int half = 0; half < 2; half++) {
                int rr = r0 + half * 8;
                float v0 = acc[i][j][2 * half + 0] + bb0;
                float v1 = acc[i][j][2 * half + 1] + bb1;
                __half h0 = __float2half_rn(gelu_erf(v0));
                __half h1 = __float2half_rn(gelu_erf(v1));
                uint32_t ph = ((uint32_t)__half_as_ushort(h1) << 16) | __half_as_ushort(h0);
                *reinterpret_cast<uint32_t*>(&g_h[((size_t)e * MAX_T + rr) * F + fc + fl]) = ph;
            }
        }
    }
#endif
}

// ---------------------------------------------------------------------------
// GEMM2: out = h @ W2 + b2     grid: (T/128, E, H/128)
// ---------------------------------------------------------------------------
__global__ void __launch_bounds__(256, 2) gemm2_kernel(const float* __restrict__ b2,
                                                       float* __restrict__ out) {
    extern __shared__ char smem[];
    uint32_t su = smem_to_u32(smem);
    const int tid = threadIdx.x, wid = tid >> 5, lane = tid & 31;
    const int e = blockIdx.y;
    const int tok0 = blockIdx.x * 128;
    const int hh0 = blockIdx.z * 128;

    const __half* A = g_h + ((size_t)e * MAX_T + tok0) * F;
    const __half* B = g_w2t + ((size_t)e * H + hh0) * F;

#if USE_TC
    uint32_t tmem = tc_prologue(su, tid, wid);
    tc_mainloop(su, tmem, A, F, B, F, F, tid, wid);

    const int row = (wid & 3) * 32 + lane;
    const int ch = (wid >> 2) * 64;
    float* orow = out + (((size_t)(tok0 + row)) * E + e) * H;
    for (int cb = 0; cb < 64; cb += 32) {
        uint32_t r[32];
        TCGEN05_LD_X32(r, tmem + ch + cb);
        TCGEN05_WAIT_LD();
        int hglob = hh0 + ch + cb;
        float v4[4];
        #pragma unroll
        for (int j = 0; j < 32; j++) {
            v4[j & 3] = __uint_as_float(r[j]) + b2[e * H + hglob + j];
            if ((j & 3) == 3)
                *reinterpret_cast<uint4*>(orow + hglob + (j & ~3)) =
                    *reinterpret_cast<uint4*>(v4);
        }
    }
    tc_release(su, tmem, tid, wid);
#else
    float acc[2][8][4];
    #pragma unroll
    for (int i = 0; i < 2; i++)
        #pragma unroll
        for (int j = 0; j < 8; j++)
            #pragma unroll
            for (int q = 0; q < 4; q++) acc[i][j][q] = 0.0f;

    mmasync_mainloop(su, A, F, B, F, F, tid, acc);

    const int wm = wid >> 1, wn = wid & 1;
    const float* b2p = b2 + e * H;
    #pragma unroll
    for (int i = 0; i < 2; i++) {
        #pragma unroll
        for (int j = 0; j < 8; j++) {
            int hj = hh0 + wn * 64 + j * 8 + (lane & 3) * 2;
            int r0 = tok0 + wm * 32 + i * 16 + (lane >> 2);
            float bb0 = b2p[hj], bb1 = b2p[hj + 1];
            #pragma unroll
            for (int half = 0; half < 2; half++) {
                int rr = r0 + half * 8;
                float2 v = make_float2(acc[i][j][2 * half + 0] + bb0,
                                       acc[i][j][2 * half + 1] + bb1);
                *reinterpret_cast<float2*>(out + ((size_t)rr * E + e) * H + hj) = v;
            }
        }
    }
#endif
}

// ---------------------------------------------------------------------------
extern "C" void kernel_launch(void* const* d_in, const int* in_sizes, int n_in,
                              void* d_out, int out_size)
{
    const float* tokens = (const float*)d_in[0];
    const float* ln_g   = (const float*)d_in[1];
    const float* ln_b   = (const float*)d_in[2];
    const float* W1     = (const float*)d_in[3];
    const float* b1     = (const float*)d_in[4];
    const float* W2     = (const float*)d_in[5];
    const float* b2     = (const float*)d_in[6];
    float* out = (float*)d_out;

    int T = in_sizes[0] / H;      // 8192
    int tiles = T / 128;          // 64
    int nbLN = T / 8;             // 1024

    cudaFuncSetAttribute(gemm1_kernel, cudaFuncAttributeMaxDynamicSharedMemorySize, SMEM_BYTES);
    cudaFuncSetAttribute(gemm2_kernel, cudaFuncAttributeMaxDynamicSharedMemorySize, SMEM_BYTES);

    int nb = nbLN + 2048 + 2048 + 512;
    prep_kernel<<<nb, 256>>>(tokens, ln_g, ln_b, W1, W2, nbLN);
    { dim3 g(tiles, E, F / 128); gemm1_kernel<<<g, 256, SMEM_BYTES>>>(b1); }
    { dim3 g(tiles, E, H / 128); gemm2_kernel<<<g, 256, SMEM_BYTES>>>(b2, out); }
}

// round 9
// speedup vs baseline: 28.0099x; 1.0736x over previous
#include <cuda_runtime.h>
#include <cuda_fp16.h>
#include <math.h>
#include <stdint.h>

#define H 512
#define F 1024
#define E 16
#define MAX_T 8192
#define EPS 1e-5f

// Per-compile-pass feature detection: tcgen05 only legal on sm_103a-style targets.
#if defined(__CUDA_ARCH__) && (defined(__CUDA_ARCH_FEAT_SM103_ALL) || \
    defined(__CUDA_ARCH_FEAT_SM100_ALL) || defined(__CUDA_ARCH_SPECIFIC__) || \
    defined(__CUDA_ARCH_FAMILY_SPECIFIC__))
#define USE_TC 1
#else
#define USE_TC 0
#endif

// ---------------------------------------------------------------------------
// Scratch (no allocation allowed -> device globals)
// ---------------------------------------------------------------------------
__device__ __align__(128) __half g_x[(size_t)MAX_T * H];
__device__ __align__(128) __half g_w1t[(size_t)E * F * H];   // [e][f][h]
__device__ __align__(128) __half g_w2t[(size_t)E * H * F];   // [e][h][f]
__device__ float g_b1part[8][E * F];
__device__ __align__(128) __half g_h[(size_t)E * MAX_T * F]; // [e][t][f]
__device__ unsigned g_cnt[(MAX_T / 128) * E];                // producer counters

// ---------------------------------------------------------------------------
// Common helpers
// ---------------------------------------------------------------------------
__device__ __forceinline__ uint32_t smem_to_u32(const void* p) {
    uint32_t a;
    asm("{ .reg .u64 t; cvta.to.shared.u64 t, %1; cvt.u32.u64 %0, t; }" : "=r"(a) : "l"(p));
    return a;
}
#define SMEM_SWIZZLE_128B(o) ((o) ^ (((o) >> 3) & 0x70))

__device__ __forceinline__ void cpa16(uint32_t dst, const void* src) {
    asm volatile("cp.async.cg.shared.global [%0], [%1], 16;" :: "r"(dst), "l"(src));
}
#define CP_COMMIT() asm volatile("cp.async.commit_group;" ::: "memory")
__device__ __forceinline__ void cp_wait2() { asm volatile("cp.async.wait_group 2;" ::: "memory"); }
__device__ __forceinline__ void cp_wait1() { asm volatile("cp.async.wait_group 1;" ::: "memory"); }
__device__ __forceinline__ void cp_wait0() { asm volatile("cp.async.wait_group 0;" ::: "memory"); }

__device__ __forceinline__ float gelu_erf(float x) {
    return 0.5f * x * (1.0f + erff(x * 0.70710678118654752f));
}

// Tile geometry: M=128 tokens, N=128, K-step=64
// SMEM stage: A(16K) B(16K) = 32KB; 3 stages = 96KB; 2 CTAs/SM
#define OFF_B 16384
#define STAGE_BYTES 32768
#define S_CTRL 98304             // tmem ptr (tc path)
#define S_MBAR 98320
#define S_B1   98336             // 128 floats of b1' for this fc tile
#define SMEM_BYTES 98848

// Load one stage (A: 128x64 fp16, B: 128x64 fp16) with SW128 swizzle
__device__ __forceinline__ void stage_load_async(uint32_t sbase,
    const __half* __restrict__ A, size_t as,
    const __half* __restrict__ B, size_t bs,
    int k0, int tid)
{
    #pragma unroll
    for (int it = 0; it < 4; it++) {
        int v = tid + it * 256;
        int r = v >> 3, c = v & 7;
        uint32_t off = SMEM_SWIZZLE_128B((uint32_t)(r * 128 + c * 16));
        cpa16(sbase + off,         A + (size_t)r * as + k0 + c * 8);
        cpa16(sbase + OFF_B + off, B + (size_t)r * bs + k0 + c * 8);
    }
}

// ===========================================================================
#if USE_TC
// tcgen05 path: one M=128 x N=128 MMA region
// ===========================================================================
__device__ __forceinline__ uint32_t elect_one_pred() {
    uint32_t pred;
    asm volatile("{\n\t.reg .pred p;\n\telect.sync _|p, 0xFFFFFFFF;\n\t"
                 "selp.b32 %0, 1, 0, p;\n\t}" : "=r"(pred));
    return pred;
}
static constexpr uint64_t SMEM_DESC_BASE_SW128 =
    (uint64_t(2) << 61) | (uint64_t(1) << 46) | (uint64_t(64) << 32) | (uint64_t(1) << 16);
#define MAKE_SMEM_DESC(a) (SMEM_DESC_BASE_SW128 | ((uint64_t)((a) >> 4) & 0x3FFF))

#define TCGEN05_ALLOC(sr, n) \
    asm volatile("tcgen05.alloc.cta_group::1.sync.aligned.shared::cta.b32 [%0], %1;" \
                 :: "r"((uint32_t)(sr)), "r"((uint32_t)(n)) : "memory")
#define TCGEN05_DEALLOC(t, n) \
    asm volatile("tcgen05.dealloc.cta_group::1.sync.aligned.b32 %0, %1;" :: "r"(t), "r"(n))
#define TCGEN05_RELINQUISH() \
    asm volatile("tcgen05.relinquish_alloc_permit.cta_group::1.sync.aligned;")
#define TCGEN05_COMMIT(m) \
    asm volatile("tcgen05.commit.cta_group::1.mbarrier::arrive::one.shared::cluster.b64 [%0];" \
                 :: "r"((uint32_t)(m)) : "memory")
#define TCGEN05_FENCE_AFTER() asm volatile("tcgen05.fence::after_thread_sync;" ::: "memory")
#define TCGEN05_WAIT_LD() asm volatile("tcgen05.wait::ld.sync.aligned;" ::: "memory")
#define MBARRIER_INIT(m, c) \
    asm volatile("mbarrier.init.shared.b64 [%0], %1;" :: "r"((uint32_t)(m)), "r"((uint32_t)(c)) : "memory")
#define MBARRIER_INVAL(m) \
    asm volatile("mbarrier.inval.shared.b64 [%0];" :: "r"((uint32_t)(m)) : "memory")

#define MBARRIER_WAIT_PARITY(mb, ph) do {                                         \
    uint32_t _m = (uint32_t)(mb), _p = (uint32_t)(ph), _d;                         \
    asm volatile("{\n\t.reg .pred p;\n\t"                                          \
        "mbarrier.try_wait.parity.acquire.cta.shared::cta.b64 p, [%1], %2;\n\t"    \
        "selp.b32 %0, 1, 0, p;\n\t}" : "=r"(_d) : "r"(_m), "r"(_p) : "memory");    \
    if (!_d) {                                                                     \
        asm volatile("{\n\t.reg .pred P1;\n\t"                                     \
            "WL_%=:\n\t"                                                           \
            "mbarrier.try_wait.parity.acquire.cta.shared::cta.b64 P1, [%0], %1, 0x989680;\n\t" \
            "@P1 bra.uni WD_%=;\n\t"                                               \
            "bra.uni WL_%=;\n\t"                                                   \
            "WD_%=:\n\t}" :: "r"(_m), "r"(_p) : "memory");                         \
    }                                                                              \
} while (0)

#define TCGEN05_LD_X32(r, a)                                                       \
    asm volatile("tcgen05.ld.sync.aligned.32x32b.x32.b32 "                         \
        "{%0, %1, %2, %3, %4, %5, %6, %7, %8, %9, %10, %11, %12, %13, %14, %15, "  \
        " %16, %17, %18, %19, %20, %21, %22, %23, %24, %25, %26, %27, %28, %29, %30, %31}, [%32];" \
        : "=r"((r)[0]), "=r"((r)[1]), "=r"((r)[2]), "=r"((r)[3]),                  \
          "=r"((r)[4]), "=r"((r)[5]), "=r"((r)[6]), "=r"((r)[7]),                  \
          "=r"((r)[8]), "=r"((r)[9]), "=r"((r)[10]), "=r"((r)[11]),                \
          "=r"((r)[12]), "=r"((r)[13]), "=r"((r)[14]), "=r"((r)[15]),              \
          "=r"((r)[16]), "=r"((r)[17]), "=r"((r)[18]), "=r"((r)[19]),              \
          "=r"((r)[20]), "=r"((r)[21]), "=r"((r)[22]), "=r"((r)[23]),              \
          "=r"((r)[24]), "=r"((r)[25]), "=r"((r)[26]), "=r"((r)[27]),              \
          "=r"((r)[28]), "=r"((r)[29]), "=r"((r)[30]), "=r"((r)[31])               \
        : "r"(a))

__device__ __forceinline__ void mma_f16_ss(uint32_t d_tmem, uint64_t a_desc,
                                           uint64_t b_desc, uint32_t idesc, bool acc) {
    uint32_t en = acc ? 1u : 0u;
    asm volatile("{\n\t.reg .pred p;\n\tsetp.ne.u32 p, %4, 0;\n\t"
                 "tcgen05.mma.cta_group::1.kind::f16 [%0], %1, %2, %3, p;\n\t}"
                 :: "r"(d_tmem), "l"(a_desc), "l"(b_desc), "r"(idesc), "r"(en)
                 : "memory");
}
// dtype=F32, atype=btype=F16(0), N=128, M=128, K-major
#define MMA_IDESC ((1u << 4) | ((128u / 8u) << 17) | ((128u / 16u) << 24))

__device__ __forceinline__ uint32_t tc_prologue(uint32_t su, int tid, int wid) {
    if (wid == 0) TCGEN05_ALLOC(su + S_CTRL, 128);
    if (tid == 128) MBARRIER_INIT(su + S_MBAR, 1);
    __syncthreads();
    uint32_t tmem;
    asm volatile("ld.shared.b32 %0, [%1];" : "=r"(tmem) : "r"(su + S_CTRL));
    if (wid == 0) TCGEN05_RELINQUISH();
    __syncthreads();
    return tmem;
}

__device__ __forceinline__ void tc_mainloop(uint32_t su, uint32_t tmem,
    const __half* __restrict__ A, size_t as,
    const __half* __restrict__ B, size_t bs,
    int K, int tid, int wid)
{
    const int nk = K / 64;
    stage_load_async(su, A, as, B, bs, 0, tid);
    CP_COMMIT();
    if (nk > 1) {
        stage_load_async(su + STAGE_BYTES, A, as, B, bs, 64, tid);
        CP_COMMIT();
    }
    for (int ks = 0; ks < nk; ks++) {
        if (ks > 0) MBARRIER_WAIT_PARITY(su + S_MBAR, (ks - 1) & 1);
        if (ks + 2 < nk) {
            stage_load_async(su + ((ks + 2) % 3) * STAGE_BYTES,
                             A, as, B, bs, (ks + 2) * 64, tid);
            CP_COMMIT();
            cp_wait2();
        } else if (ks + 1 < nk) {
            cp_wait1();
        } else {
            cp_wait0();
        }
        __syncthreads();
        if (wid == 0 && elect_one_pred()) {
            asm volatile("fence.proxy.async.shared::cta;" ::: "memory");
            uint32_t sb = su + (ks % 3) * STAGE_BYTES;
            uint64_t dA = MAKE_SMEM_DESC(sb);
            uint64_t dB = MAKE_SMEM_DESC(sb + OFF_B);
            #pragma unroll
            for (int kk = 0; kk < 4; kk++) {
                bool acc0 = (ks > 0) || (kk > 0);
                mma_f16_ss(tmem, dA + kk * 2, dB + kk * 2, MMA_IDESC, acc0);
            }
            TCGEN05_COMMIT(su + S_MBAR);
        }
        __syncthreads();
    }
    MBARRIER_WAIT_PARITY(su + S_MBAR, (nk - 1) & 1);
    TCGEN05_FENCE_AFTER();
}

__device__ __forceinline__ void tc_release(uint32_t su, uint32_t tmem, int tid, int wid) {
    __syncthreads();
    if (tid == 128) MBARRIER_INVAL(su + S_MBAR);
    __syncthreads();
    if (wid == 0) TCGEN05_DEALLOC(tmem, 128);
}
#endif  // USE_TC

// ===========================================================================
#if !USE_TC
// mma.sync fallback: 8 warps, warp tile 32x64 within 128x128 CTA tile
// ===========================================================================
__device__ __forceinline__ void ldsm_x4(uint32_t* r, uint32_t a) {
    asm volatile("ldmatrix.sync.aligned.m8n8.x4.shared.b16 {%0,%1,%2,%3}, [%4];"
                 : "=r"(r[0]), "=r"(r[1]), "=r"(r[2]), "=r"(r[3]) : "r"(a));
}
__device__ __forceinline__ void mma16816(float* d, const uint32_t* a, const uint32_t* b) {
    asm volatile("mma.sync.aligned.m16n8k16.row.col.f32.f16.f16.f32 "
                 "{%0,%1,%2,%3}, {%4,%5,%6,%7}, {%8,%9}, {%0,%1,%2,%3};"
                 : "+f"(d[0]), "+f"(d[1]), "+f"(d[2]), "+f"(d[3])
                 : "r"(a[0]), "r"(a[1]), "r"(a[2]), "r"(a[3]), "r"(b[0]), "r"(b[1]));
}

__device__ __forceinline__ void mmasync_mainloop(uint32_t su,
    const __half* __restrict__ A, size_t as,
    const __half* __restrict__ B, size_t bs,
    int K, int tid, float acc[2][8][4])
{
    const int nk = K / 64;
    const int wid = tid >> 5, lane = tid & 31;
    const int wm = wid >> 1, wn = wid & 1;

    stage_load_async(su, A, as, B, bs, 0, tid);
    CP_COMMIT();
    if (nk > 1) {
        stage_load_async(su + STAGE_BYTES, A, as, B, bs, 64, tid);
        CP_COMMIT();
    }

    for (int ks = 0; ks < nk; ks++) {
        if (ks + 2 < nk) {
            stage_load_async(su + ((ks + 2) % 3) * STAGE_BYTES,
                             A, as, B, bs, (ks + 2) * 64, tid);
            CP_COMMIT();
            cp_wait2();
        } else if (ks + 1 < nk) {
            cp_wait1();
        } else {
            cp_wait0();
        }
        __syncthreads();

        uint32_t sA = su + (ks % 3) * STAGE_BYTES;
        uint32_t sB = sA + OFF_B;

        #pragma unroll
        for (int k16 = 0; k16 < 64; k16 += 16) {
            uint32_t bh[8][2];
            #pragma unroll
            for (int jj = 0; jj < 4; jj++) {
                int n = wn * 64 + jj * 16 + (lane & 7) + ((lane >> 3) & 1) * 8;
                int k = k16 + (lane >> 4) * 8;
                uint32_t addr = sB + SMEM_SWIZZLE_128B((uint32_t)(n * 128 + k * 2));
                uint32_t t[4];
                ldsm_x4(t, addr);
                bh[2 * jj][0] = t[0]; bh[2 * jj + 1][0] = t[1];
                bh[2 * jj][1] = t[2]; bh[2 * jj + 1][1] = t[3];
            }
            #pragma unroll
            for (int i = 0; i < 2; i++) {
                int m = wm * 32 + i * 16 + (lane & 15);
                int k = k16 + (lane >> 4) * 8;
                uint32_t addr = sA + SMEM_SWIZZLE_128B((uint32_t)(m * 128 + k * 2));
                uint32_t ah[4];
                ldsm_x4(ah, addr);
                #pragma unroll
                for (int j = 0; j < 8; j++)
                    mma16816(acc[i][j], ah, bh[j]);
            }
        }
        __syncthreads();
    }
}
#endif  // !USE_TC

// ---------------------------------------------------------------------------
// Fused prep kernel: all independent precomputation in ONE launch.
//   [0, nbLN)             : LayerNorm -> g_x (warp per row)
//   [nbLN, +2048)         : W1^T * g -> g_w1t  AND b1 partial sums -> g_b1part
//   [nbLN+2048, +2048)    : W2^T -> g_w2t
//   [nbLN+4096]           : zero g_cnt
// ---------------------------------------------------------------------------
__global__ void __launch_bounds__(256) prep_kernel(
    const float* __restrict__ tokens, const float* __restrict__ ln_g,
    const float* __restrict__ ln_b,   const float* __restrict__ W1,
    const float* __restrict__ W2,     int nbLN)
{
    __shared__ float ts[64][65];
    __shared__ float ps[4][64];
    const int tid = threadIdx.x;
    int b = blockIdx.x;

    if (b < nbLN) {
        const int wid = tid >> 5, lane = tid & 31;
        const int row = b * 8 + wid;
        const float* x = tokens + (size_t)row * H;
        float v[16];
        float s = 0.0f;
        #pragma unroll
        for (int i = 0; i < 16; i++) { v[i] = x[lane + 32 * i]; s += v[i]; }
        #pragma unroll
        for (int o = 16; o > 0; o >>= 1) s += __shfl_xor_sync(0xffffffffu, s, o);
        float mu = s * (1.0f / H);
        float q = 0.0f;
        #pragma unroll
        for (int i = 0; i < 16; i++) { v[i] -= mu; q += v[i] * v[i]; }
        #pragma unroll
        for (int o = 16; o > 0; o >>= 1) q += __shfl_xor_sync(0xffffffffu, q, o);
        float rs = rsqrtf(q * (1.0f / H) + EPS);
        __half* ox = g_x + (size_t)row * H;
        #pragma unroll
        for (int i = 0; i < 16; i++)
            ox[lane + 32 * i] = __float2half_rn(v[i] * rs);
        return;
    }
    b -= nbLN;

    if (b < 2048) {
        // ---- W1^T * g + b1 partials: idx -> (f0, h0, e) ----
        int f0 = (b & 15) * 64, h0 = ((b >> 4) & 7) * 64, e = b >> 7;
        #pragma unroll
        for (int i = 0; i < 16; i++) {
            int idx = tid + i * 256, r = idx >> 6, c = idx & 63;
            ts[r][c] = W1[((size_t)e * H + h0 + r) * F + f0 + c];
        }
        __syncthreads();
        #pragma unroll
        for (int i = 0; i < 16; i++) {
            int idx = tid + i * 256, r = idx >> 6, c = idx & 63;
            float w = ts[c][r] * ln_g[e * H + h0 + c];
            g_w1t[((size_t)e * F + f0 + r) * H + h0 + c] = __float2half_rn(w);
        }
        // b1 partials from the already-staged tile: Σ_r ln_b[h0+r]*ts[r][f]
        {
            int f = tid & 63, q = tid >> 6;
            const float* lb = ln_b + e * H + h0 + q * 16;
            float s = 0.0f;
            #pragma unroll
            for (int r = 0; r < 16; r++) s += lb[r] * ts[q * 16 + r][f];
            ps[q][f] = s;
        }
        __syncthreads();
        if (tid < 64) {
            float a = ps[0][tid] + ps[1][tid] + ps[2][tid] + ps[3][tid];
            g_b1part[h0 >> 6][e * F + f0 + tid] = a;
        }
        return;
    }
    b -= 2048;

    if (b < 2048) {
        int h0 = (b & 7) * 64, f0 = ((b >> 3) & 15) * 64, e = b >> 7;
        #pragma unroll
        for (int i = 0; i < 16; i++) {
            int idx = tid + i * 256, r = idx >> 6, c = idx & 63;
            ts[r][c] = W2[((size_t)e * F + f0 + r) * H + h0 + c];
        }
        __syncthreads();
        #pragma unroll
        for (int i = 0; i < 16; i++) {
            int idx = tid + i * 256, r = idx >> 6, c = idx & 63;
            g_w2t[((size_t)e * H + h0 + r) * F + f0 + c] = __float2half_rn(ts[c][r]);
        }
        return;
    }

    // ---- zero producer counters ----
    #pragma unroll
    for (int i = 0; i < 4; i++) g_cnt[tid + i * 256] = 0u;
}

// ---------------------------------------------------------------------------
// Fused GEMM kernel: GEMM1 CTAs (bid < nb1) then GEMM2 CTAs, with device-side
// release/acquire counters per (token-tile, expert).
//   GEMM1: h = gelu(xhat @ (g*W1) + b1')   decode (t, e, fc)
//   GEMM2: out = h @ W2 + b2               decode (t, e, hh)
// ---------------------------------------------------------------------------
__global__ void __launch_bounds__(256, 2) gemm_fused_kernel(
    const float* __restrict__ b1, const float* __restrict__ b2,
    float* __restrict__ out, int tiles)
{
    extern __shared__ char smem[];
    uint32_t su = smem_to_u32(smem);
    const int tid = threadIdx.x, wid = tid >> 5, lane = tid & 31;
    const int nb1 = tiles * E * 8;
    int b = blockIdx.x;

    if (b < nb1) {
        // ================= GEMM1 producer =================
        const int t = b >> 7;                 // /(E*8)
        const int e = (b >> 3) & 15;
        const int fc = (b & 7) * 128;
        const int tok0 = t * 128;
        float* sm_b1 = reinterpret_cast<float*>(smem + S_B1);

        if (tid < 128) {
            int fg = e * F + fc + tid;
            float a = b1[fg];
            #pragma unroll
            for (int s = 0; s < 8; s++) a += g_b1part[s][fg];
            sm_b1[tid] = a;
        }

        const __half* A = g_x + (size_t)tok0 * H;
        const __half* B = g_w1t + ((size_t)e * F + fc) * H;

#if USE_TC
        uint32_t tmem = tc_prologue(su, tid, wid);
        tc_mainloop(su, tmem, A, H, B, H, H, tid, wid);
        const int row = (wid & 3) * 32 + lane;
        const int ch = (wid >> 2) * 64;
        const size_t hrow = ((size_t)e * MAX_T + tok0 + row) * F;
        for (int cb = 0; cb < 64; cb += 32) {
            uint32_t r[32];
            TCGEN05_LD_X32(r, tmem + ch + cb);
            TCGEN05_WAIT_LD();
            int fglob = fc + ch + cb;
            __half h8[8];
            #pragma unroll
            for (int j = 0; j < 32; j++) {
                float v = __uint_as_float(r[j]) + sm_b1[ch + cb + j];
                h8[j & 7] = __float2half_rn(gelu_erf(v));
                if ((j & 7) == 7)
                    *reinterpret_cast<uint4*>(&g_h[hrow + fglob + (j & ~7)]) =
                        *reinterpret_cast<uint4*>(h8);
            }
        }
        tc_release(su, tmem, tid, wid);
#else
        float acc[2][8][4];
        #pragma unroll
        for (int i = 0; i < 2; i++)
            #pragma unroll
            for (int j = 0; j < 8; j++)
                #pragma unroll
                for (int q = 0; q < 4; q++) acc[i][j][q] = 0.0f;

        mmasync_mainloop(su, A, H, B, H, H, tid, acc);

        const int wm = wid >> 1, wn = wid & 1;
        #pragma unroll
        for (int i = 0; i < 2; i++) {
            #pragma unroll
            for (int j = 0; j < 8; j++) {
                int fl = wn * 64 + j * 8 + (lane & 3) * 2;
                int r0 = tok0 + wm * 32 + i * 16 + (lane >> 2);
                float bb0 = sm_b1[fl], bb1 = sm_b1[fl + 1];
                #pragma unroll
                for (int half = 0; half < 2; half++) {
                    int rr = r0 + half * 8;
                    float v0 = acc[i][j][2 * half + 0] + bb0;
                    float v1 = acc[i][j][2 * half + 1] + bb1;
                    __half h0 = __float2half_rn(gelu_erf(v0));
                    __half h1 = __float2half_rn(gelu_erf(v1));
                    uint32_t ph = ((uint32_t)__half_as_ushort(h1) << 16) | __half_as_ushort(h0);
                    *reinterpret_cast<uint32_t*>(&g_h[((size_t)e * MAX_T + rr) * F + fc + fl]) = ph;
                }
            }
        }
#endif
        // Release: all h writes visible, then bump counter.
        __threadfence();
        __syncthreads();
        if (tid == 0) {
            unsigned* cp = &g_cnt[t * E + e];
            asm volatile("red.release.gpu.global.add.u32 [%0], 1;" :: "l"(cp) : "memory");
        }
    } else {
        // ================= GEMM2 consumer =================
        const int bb = b - nb1;
        const int t = bb >> 6;                // /(E*4)
        const int e = (bb >> 2) & 15;
        const int hh0 = (bb & 3) * 128;
        const int tok0 = t * 128;

        // Acquire: wait for all 8 producers of (t, e).
        if (tid == 0) {
            const unsigned* cp = &g_cnt[t * E + e];
            unsigned v;
            do {
                asm volatile("ld.acquire.gpu.global.u32 %0, [%1];" : "=r"(v) : "l"(cp) : "memory");
                if (v >= 8u) break;
                __nanosleep(256);
            } while (true);
        }
        __syncthreads();
        __threadfence();

        const __half* A = g_h + ((size_t)e * MAX_T + tok0) * F;
        const __half* B = g_w2t + ((size_t)e * H + hh0) * F;

#if USE_TC
        uint32_t tmem = tc_prologue(su, tid, wid);
        tc_mainloop(su, tmem, A, F, B, F, F, tid, wid);
        const int row = (wid & 3) * 32 + lane;
        const int ch = (wid >> 2) * 64;
        float* orow = out + (((size_t)(tok0 + row)) * E + e) * H;
        for (int cb = 0; cb < 64; cb += 32) {
            uint32_t r[32];
            TCGEN05_LD_X32(r, tmem + ch + cb);
            TCGEN05_WAIT_LD();
            int hglob = hh0 + ch + cb;
            float v4[4];
            #pragma unroll
            for (int j = 0; j < 32; j++) {
                v4[j & 3] = __uint_as_float(r[j]) + b2[e * H + hglob + j];
                if ((j & 3) == 3)
                    *reinterpret_cast<uint4*>(orow + hglob + (j & ~3)) =
                        *reinterpret_cast<uint4*>(v4);
            }
        }
        tc_release(su, tmem, tid, wid);
#else
        float acc[2][8][4];
        #pragma unroll
        for (int i = 0; i < 2; i++)
            #pragma unroll
            for (int j = 0; j < 8; j++)
                #pragma unroll
                for (int q = 0; q < 4; q++) acc[i][j][q] = 0.0f;

        mmasync_mainloop(su, A, F, B, F, F, tid, acc);

        const int wm = wid >> 1, wn = wid & 1;
        const float* b2p = b2 + e * H;
        #pragma unroll
        for (int i = 0; i < 2; i++) {
            #pragma unroll
            for (int j = 0; j < 8; j++) {
                int hj = hh0 + wn * 64 + j * 8 + (lane & 3) * 2;
                int r0 = tok0 + wm * 32 + i * 16 + (lane >> 2);
                float bb0 = b2p[hj], bb1 = b2p[hj + 1];
                #pragma unroll
                for (int half = 0; half < 2; half++) {
                    int rr = r0 + half * 8;
                    float2 v = make_float2(acc[i][j][2 * half + 0] + bb0,
                                           acc[i][j][2 * half + 1] + bb1);
                    *reinterpret_cast<float2*>(out + ((size_t)rr * E + e) * H + hj) = v;
                }
            }
        }
#endif
    }
}

// ---------------------------------------------------------------------------
extern "C" void kernel_launch(void* const* d_in, const int* in_sizes, int n_in,
                              void* d_out, int out_size)
{
    const float* tokens = (const float*)d_in[0];
    const float* ln_g   = (const float*)d_in[1];
    const float* ln_b   = (const float*)d_in[2];
    const float* W1     = (const float*)d_in[3];
    const float* b1     = (const float*)d_in[4];
    const float* W2     = (const float*)d_in[5];
    const float* b2     = (const float*)d_in[6];
    float* out = (float*)d_out;

    int T = in_sizes[0] / H;      // 8192
    int tiles = T / 128;          // 64
    int nbLN = T / 8;             // 1024

    cudaFuncSetAttribute(gemm_fused_kernel, cudaFuncAttributeMaxDynamicSharedMemorySize, SMEM_BYTES);

    int nb = nbLN + 2048 + 2048 + 1;
    prep_kernel<<<nb, 256>>>(tokens, ln_g, ln_b, W1, W2, nbLN);

    int ng = tiles * E * 8 + tiles * E * 4;   // 12288
    gemm_fused_kernel<<<ng, 256, SMEM_BYTES>>>(b1, b2, out, tiles);
}